// round 6
// baseline (speedup 1.0000x reference)
#include <cuda_runtime.h>
#include <math.h>

// ---------------------------------------------------------------------------
// Problem constants
// ---------------------------------------------------------------------------
namespace {
constexpr int kB   = 32;
constexpr int kN   = 256;
constexpr int kNF  = 3;
constexpr int kNEF = 3;
constexpr int kD   = 768;
constexpr int kFF  = 3072;
constexpr int kH   = 12;
constexpr int kL   = 6;
constexpr int kNA  = 512;
constexpr int kND  = 512;
constexpr int kNE  = 512;
constexpr int kNS  = 512;
constexpr int kS   = 257;          // N + 1
constexpr int kHD  = 64;           // D / H
constexpr int kBS  = kB * kS;      // 8224 tokens
constexpr float kSCALE = 0.125f;   // HD^-0.5
constexpr float kEPS   = 1e-5f;

constexpr size_t SZ_TOK = (size_t)kBS * kD;            // 6,316,032
constexpr size_t SZ_ATT = (size_t)kB * kH * kS * kS;   // 25,365,504
constexpr size_t SZ_FF  = (size_t)kBS * kFF;           // 25,264,128
constexpr size_t OFF_H  = 0;
constexpr size_t OFF_Z  = OFF_H  + SZ_TOK;
constexpr size_t OFF_Q  = OFF_Z  + SZ_TOK;
constexpr size_t OFF_K  = OFF_Q  + SZ_TOK;
constexpr size_t OFF_V  = OFF_K  + SZ_TOK;
constexpr size_t OFF_O  = OFF_V  + SZ_TOK;
constexpr size_t OFF_GB = OFF_O  + SZ_TOK;
constexpr size_t OFF_SC = OFF_GB + SZ_ATT;
constexpr size_t OFF_F  = OFF_SC + SZ_ATT;
constexpr size_t SCRATCH_ELEMS = OFF_F + SZ_FF;        // ~113.9M floats (~456 MB)
}  // namespace

__device__ float g_scratch[SCRATCH_ELEMS];

__device__ __forceinline__ int iclamp(int v, int lo, int hi) {
    return min(max(v, lo), hi);
}

// ---------------------------------------------------------------------------
// Embedding: h[b,0,:]=graph_token; h[b,1+n,:]=sum_f atom_emb[x] + deg embeds
// grid = kBS blocks, 256 threads
// ---------------------------------------------------------------------------
__global__ void embed_kernel(const int* __restrict__ x,
                             const int* __restrict__ in_deg,
                             const int* __restrict__ out_deg,
                             const float* __restrict__ atom_emb,
                             const float* __restrict__ in_deg_emb,
                             const float* __restrict__ out_deg_emb,
                             const float* __restrict__ graph_token,
                             float* __restrict__ h) {
    int tok = blockIdx.x;
    int b = tok / kS, s = tok % kS;
    float* out = h + (size_t)tok * kD;
    if (s == 0) {
        for (int d = threadIdx.x; d < kD; d += 256) out[d] = graph_token[d];
        return;
    }
    int n = s - 1;
    const int* xr = x + (b * kN + n) * kNF;
    int a0 = iclamp(xr[0], 0, kNA);
    int a1 = iclamp(xr[1], 0, kNA);
    int a2 = iclamp(xr[2], 0, kNA);
    int di = iclamp(in_deg[b * kN + n], 0, kND - 1);
    int dq = iclamp(out_deg[b * kN + n], 0, kND - 1);
    const float* e0 = atom_emb + (size_t)a0 * kD;
    const float* e1 = atom_emb + (size_t)a1 * kD;
    const float* e2 = atom_emb + (size_t)a2 * kD;
    const float* ei = in_deg_emb + (size_t)di * kD;
    const float* eo = out_deg_emb + (size_t)dq * kD;
    for (int d = threadIdx.x; d < kD; d += 256)
        out[d] = e0[d] + e1[d] + e2[d] + ei[d] + eo[d];
}

// ---------------------------------------------------------------------------
// Graph bias gb[b,h,q,k] (includes mask baked in as -1e30) — computed once
// grid = ((S*S+255)/256, B), 256 threads; each thread does one (q,k), all H
// ---------------------------------------------------------------------------
__global__ void bias_kernel(const float* __restrict__ attn_bias,
                            const int* __restrict__ spatial_pos,
                            const int* __restrict__ edge_type,
                            const int* __restrict__ x,
                            const float* __restrict__ spatial_emb,
                            const float* __restrict__ edge_emb,
                            const float* __restrict__ virt_dist,
                            float* __restrict__ gb) {
    int idx = blockIdx.x * 256 + threadIdx.x;
    if (idx >= kS * kS) return;
    int b = blockIdx.y;
    int q = idx / kS, k = idx % kS;

    size_t obase = ((size_t)b * kH) * kS * kS + (size_t)q * kS + k;

    // padding mask on key (pad[b,0] is always false)
    if (k >= 1 && x[(b * kN + (k - 1)) * kNF] == 0) {
#pragma unroll
        for (int hh = 0; hh < kH; hh++)
            gb[obase + (size_t)hh * kS * kS] = -1e30f;
        return;
    }

    float base = attn_bias[(size_t)b * kS * kS + idx];
    float vals[kH];
#pragma unroll
    for (int hh = 0; hh < kH; hh++) vals[hh] = base;

    if (q >= 1 && k >= 1) {
        size_t e = (size_t)b * kN * kN + (size_t)(q - 1) * kN + (k - 1);
        int sp = iclamp(spatial_pos[e], 0, kNS - 1);
        const int* et = edge_type + e * kNEF;
        int t0 = iclamp(et[0], 0, kNE);
        int t1 = iclamp(et[1], 0, kNE);
        int t2 = iclamp(et[2], 0, kNE);
        const float* sr = spatial_emb + (size_t)sp * kH;
        const float* r0 = edge_emb + (size_t)t0 * kH;
        const float* r1 = edge_emb + (size_t)t1 * kH;
        const float* r2 = edge_emb + (size_t)t2 * kH;
#pragma unroll
        for (int hh = 0; hh < kH; hh++)
            vals[hh] += sr[hh] + (r0[hh] + r1[hh] + r2[hh]) * (1.0f / 3.0f);
    }
    if (q == 0 || k == 0) {
#pragma unroll
        for (int hh = 0; hh < kH; hh++) vals[hh] += virt_dist[hh];
    }
#pragma unroll
    for (int hh = 0; hh < kH; hh++)
        gb[obase + (size_t)hh * kS * kS] = vals[hh];
}

// ---------------------------------------------------------------------------
// LayerNorm: one block per token, 256 threads (D = 768 = 3*256 exactly)
// ---------------------------------------------------------------------------
__global__ void ln_kernel(const float* __restrict__ in,
                          const float* __restrict__ g,
                          const float* __restrict__ bt,
                          float* __restrict__ out) {
    int tok = blockIdx.x;
    int tid = threadIdx.x;
    const float* xr = in + (size_t)tok * kD;
    __shared__ float red[256];
    float x0 = xr[tid], x1 = xr[tid + 256], x2 = xr[tid + 512];
    red[tid] = x0 + x1 + x2;
    __syncthreads();
    for (int off = 128; off; off >>= 1) {
        if (tid < off) red[tid] += red[tid + off];
        __syncthreads();
    }
    float mean = red[0] * (1.0f / kD);
    __syncthreads();
    float d0 = x0 - mean, d1 = x1 - mean, d2 = x2 - mean;
    red[tid] = d0 * d0 + d1 * d1 + d2 * d2;
    __syncthreads();
    for (int off = 128; off; off >>= 1) {
        if (tid < off) red[tid] += red[tid + off];
        __syncthreads();
    }
    float inv = rsqrtf(red[0] * (1.0f / kD) + kEPS);
    float* orow = out + (size_t)tok * kD;
    orow[tid]       = d0 * inv * g[tid]       + bt[tid];
    orow[tid + 256] = d1 * inv * g[tid + 256] + bt[tid + 256];
    orow[tid + 512] = d2 * inv * g[tid + 512] + bt[tid + 512];
}

// Final LN: writes node_rep (B,N,D) then graph_rep (B,D) into d_out
__global__ void final_ln_kernel(const float* __restrict__ in,
                                const float* __restrict__ g,
                                const float* __restrict__ bt,
                                float* __restrict__ out) {
    int tok = blockIdx.x;
    int b = tok / kS, s = tok % kS;
    int tid = threadIdx.x;
    const float* xr = in + (size_t)tok * kD;
    __shared__ float red[256];
    float x0 = xr[tid], x1 = xr[tid + 256], x2 = xr[tid + 512];
    red[tid] = x0 + x1 + x2;
    __syncthreads();
    for (int off = 128; off; off >>= 1) {
        if (tid < off) red[tid] += red[tid + off];
        __syncthreads();
    }
    float mean = red[0] * (1.0f / kD);
    __syncthreads();
    float d0 = x0 - mean, d1 = x1 - mean, d2 = x2 - mean;
    red[tid] = d0 * d0 + d1 * d1 + d2 * d2;
    __syncthreads();
    for (int off = 128; off; off >>= 1) {
        if (tid < off) red[tid] += red[tid + off];
        __syncthreads();
    }
    float inv = rsqrtf(red[0] * (1.0f / kD) + kEPS);
    float* orow = (s == 0)
        ? out + (size_t)kB * kN * kD + (size_t)b * kD          // graph_rep
        : out + ((size_t)b * kN + (s - 1)) * kD;               // node_rep
    orow[tid]       = d0 * inv * g[tid]       + bt[tid];
    orow[tid + 256] = d1 * inv * g[tid + 256] + bt[tid + 256];
    orow[tid + 512] = d2 * inv * g[tid + 512] + bt[tid + 512];
}

// ---------------------------------------------------------------------------
// SGEMM NT: C[M,N] = epi(A[M,K] @ W[N,K]^T + bias[N])
// 128x128 block tile, BK=8, 256 threads, 8x8 per thread, float4 everywhere.
// N must be a multiple of 128, K a multiple of 8; M is guarded.
// ---------------------------------------------------------------------------
enum { EPI_NONE = 0, EPI_SCALE = 1, EPI_GELU = 2, EPI_RES = 3 };

__global__ __launch_bounds__(256)
void sgemm_nt(const float* __restrict__ A, const float* __restrict__ W,
              const float* __restrict__ bias, float* __restrict__ C,
              int M, int N, int K, int epi) {
    constexpr int BM = 128, BN = 128, BK = 8;
    __shared__ float As[BK][BM];
    __shared__ float Ws[BK][BN];
    int tid = threadIdx.x;
    int bm = blockIdx.y * BM;
    int bn = blockIdx.x * BN;
    int lrow = tid >> 1;            // 0..127
    int lcol = (tid & 1) << 2;      // 0 or 4
    int tx = tid & 15;              // n micro-tile
    int ty = tid >> 4;              // m micro-tile

    const float* Aptr = A + (size_t)(bm + lrow) * K + lcol;
    const float* Wptr = W + (size_t)(bn + lrow) * K + lcol;
    bool avalid = (bm + lrow) < M;

    float acc[8][8];
#pragma unroll
    for (int i = 0; i < 8; i++)
#pragma unroll
        for (int j = 0; j < 8; j++) acc[i][j] = 0.0f;

    for (int k0 = 0; k0 < K; k0 += BK) {
        float4 a4 = avalid ? *(const float4*)(Aptr + k0)
                           : make_float4(0.f, 0.f, 0.f, 0.f);
        float4 w4 = *(const float4*)(Wptr + k0);
        As[lcol + 0][lrow] = a4.x; As[lcol + 1][lrow] = a4.y;
        As[lcol + 2][lrow] = a4.z; As[lcol + 3][lrow] = a4.w;
        Ws[lcol + 0][lrow] = w4.x; Ws[lcol + 1][lrow] = w4.y;
        Ws[lcol + 2][lrow] = w4.z; Ws[lcol + 3][lrow] = w4.w;
        __syncthreads();
#pragma unroll
        for (int kk = 0; kk < BK; kk++) {
            float4 a0 = *(const float4*)&As[kk][ty * 8];
            float4 a1 = *(const float4*)&As[kk][ty * 8 + 4];
            float4 w0 = *(const float4*)&Ws[kk][tx * 8];
            float4 w1 = *(const float4*)&Ws[kk][tx * 8 + 4];
            float af[8] = {a0.x, a0.y, a0.z, a0.w, a1.x, a1.y, a1.z, a1.w};
            float wf[8] = {w0.x, w0.y, w0.z, w0.w, w1.x, w1.y, w1.z, w1.w};
#pragma unroll
            for (int i = 0; i < 8; i++)
#pragma unroll
                for (int j = 0; j < 8; j++) acc[i][j] += af[i] * wf[j];
        }
        __syncthreads();
    }

#pragma unroll
    for (int i = 0; i < 8; i++) {
        int r = bm + ty * 8 + i;
        if (r >= M) continue;
        float* crow = C + (size_t)r * N + bn + tx * 8;
        const float* brow = bias + bn + tx * 8;
#pragma unroll
        for (int j = 0; j < 8; j++) {
            float v = acc[i][j] + brow[j];
            if (epi == EPI_SCALE) {
                v *= kSCALE;
            } else if (epi == EPI_GELU) {
                v = 0.5f * v * (1.0f + erff(v * 0.70710678118654752f));
            } else if (epi == EPI_RES) {
                v += crow[j];
            }
            crow[j] = v;
        }
    }
}

// ---------------------------------------------------------------------------
// scores[b,h,q,k] = sum_d q[b,q,h,d]*k[b,k,h,d] + gb[b,h,q,k]
// grid (17,17,B*H), 256 threads; 16x16 output tile, K=64 in shared.
// ---------------------------------------------------------------------------
__global__ void scores_kernel(const float* __restrict__ qm,
                              const float* __restrict__ km,
                              const float* __restrict__ gb,
                              float* __restrict__ sc) {
    int bh = blockIdx.z;
    int b = bh / kH, h = bh % kH;
    int q0 = blockIdx.y * 16, k0 = blockIdx.x * 16;
    __shared__ float qs[16][68];
    __shared__ float ks[16][68];
    int tid = threadIdx.x;
    int lr = tid >> 4;
    int lc = (tid & 15) * 4;

    int gq = q0 + lr;
    float4 v4 = make_float4(0.f, 0.f, 0.f, 0.f);
    if (gq < kS)
        v4 = *(const float4*)(qm + ((size_t)(b * kS + gq)) * kD + h * kHD + lc);
    qs[lr][lc] = v4.x; qs[lr][lc + 1] = v4.y; qs[lr][lc + 2] = v4.z; qs[lr][lc + 3] = v4.w;

    int gk = k0 + lr;
    v4 = make_float4(0.f, 0.f, 0.f, 0.f);
    if (gk < kS)
        v4 = *(const float4*)(km + ((size_t)(b * kS + gk)) * kD + h * kHD + lc);
    ks[lr][lc] = v4.x; ks[lr][lc + 1] = v4.y; ks[lr][lc + 2] = v4.z; ks[lr][lc + 3] = v4.w;
    __syncthreads();

    int qi = tid >> 4, ki = tid & 15;
    float acc = 0.0f;
#pragma unroll
    for (int d = 0; d < kHD; d++) acc += qs[qi][d] * ks[ki][d];

    int oq = q0 + qi, ok = k0 + ki;
    if (oq < kS && ok < kS) {
        size_t o = (((size_t)bh) * kS + oq) * kS + ok;
        sc[o] = acc + gb[o];
    }
}

// ---------------------------------------------------------------------------
// In-place softmax over the last dim (257) — one block per row.
// ---------------------------------------------------------------------------
__global__ void softmax_kernel(float* __restrict__ sc) {
    float* p = sc + (size_t)blockIdx.x * kS;
    int tid = threadIdx.x;
    __shared__ float red[256];
    float a = (tid < kS) ? p[tid] : -3.4e38f;
    float c = (tid == 0) ? p[256] : -3.4e38f;
    red[tid] = fmaxf(a, c);
    __syncthreads();
    for (int off = 128; off; off >>= 1) {
        if (tid < off) red[tid] = fmaxf(red[tid], red[tid + off]);
        __syncthreads();
    }
    float m = red[0];
    __syncthreads();
    float ea = (tid < kS) ? expf(a - m) : 0.0f;
    float ec = (tid == 0) ? expf(c - m) : 0.0f;
    red[tid] = ea + ec;
    __syncthreads();
    for (int off = 128; off; off >>= 1) {
        if (tid < off) red[tid] += red[tid + off];
        __syncthreads();
    }
    float inv = 1.0f / red[0];
    if (tid < kS) p[tid] = ea * inv;
    if (tid == 0) p[256] = ec * inv;
}

// ---------------------------------------------------------------------------
// o[b,q,h,d] = sum_k a[b,h,q,k] * v[b,k,h,d]
// grid (1, ceil(S/4), B*H); 256 threads = 4 q-rows x 64 d-lanes.
// ---------------------------------------------------------------------------
__global__ void attnv_kernel(const float* __restrict__ sc,
                             const float* __restrict__ vm,
                             float* __restrict__ om) {
    int bh = blockIdx.z;
    int b = bh / kH, h = bh % kH;
    int q0 = blockIdx.y * 4;
    int r = threadIdx.x >> 6;    // 0..3
    int d = threadIdx.x & 63;    // 0..63
    __shared__ float as_[4][kS];
    for (int idx = threadIdx.x; idx < 4 * kS; idx += 256) {
        int rr = idx / kS, kk = idx % kS;
        int gq = q0 + rr;
        as_[rr][kk] = (gq < kS) ? sc[(((size_t)bh) * kS + gq) * kS + kk] : 0.0f;
    }
    __syncthreads();
    const float* vb = vm + (size_t)b * kS * kD + h * kHD + d;
    float acc = 0.0f;
#pragma unroll 4
    for (int kk = 0; kk < kS; kk++) acc += as_[r][kk] * vb[(size_t)kk * kD];
    int gq = q0 + r;
    if (gq < kS)
        om[((size_t)(b * kS + gq)) * kD + h * kHD + d] = acc;
}

// ---------------------------------------------------------------------------
// Host launcher
// ---------------------------------------------------------------------------
extern "C" void kernel_launch(void* const* d_in, const int* in_sizes, int n_in,
                              void* d_out, int out_size) {
    (void)in_sizes; (void)n_in; (void)out_size;

    const int*   x              = (const int*)  d_in[0];
    const float* attn_bias      = (const float*)d_in[1];
    const int*   spatial_pos    = (const int*)  d_in[2];
    const int*   attn_edge_type = (const int*)  d_in[3];
    const int*   in_degree      = (const int*)  d_in[4];
    const int*   out_degree     = (const int*)  d_in[5];
    const float* atom_emb       = (const float*)d_in[6];
    const float* in_deg_emb     = (const float*)d_in[7];
    const float* out_deg_emb    = (const float*)d_in[8];
    const float* graph_token    = (const float*)d_in[9];
    const float* spatial_emb    = (const float*)d_in[10];
    const float* edge_emb       = (const float*)d_in[11];
    const float* virt_dist      = (const float*)d_in[12];
    const float* Wq             = (const float*)d_in[13];
    const float* Wk             = (const float*)d_in[14];
    const float* Wv             = (const float*)d_in[15];
    const float* Wo             = (const float*)d_in[16];
    const float* bq             = (const float*)d_in[17];
    const float* bk             = (const float*)d_in[18];
    const float* bv             = (const float*)d_in[19];
    const float* bo             = (const float*)d_in[20];
    const float* ln1_g          = (const float*)d_in[21];
    const float* ln1_b          = (const float*)d_in[22];
    const float* ln2_g          = (const float*)d_in[23];
    const float* ln2_b          = (const float*)d_in[24];
    const float* W1             = (const float*)d_in[25];
    const float* b1             = (const float*)d_in[26];
    const float* W2             = (const float*)d_in[27];
    const float* b2             = (const float*)d_in[28];
    const float* fin_g          = (const float*)d_in[29];
    const float* fin_b          = (const float*)d_in[30];
    float* out = (float*)d_out;

    float* base = nullptr;
    cudaGetSymbolAddress((void**)&base, g_scratch);
    float* h  = base + OFF_H;
    float* z  = base + OFF_Z;
    float* q  = base + OFF_Q;
    float* k  = base + OFF_K;
    float* v  = base + OFF_V;
    float* o  = base + OFF_O;
    float* gb = base + OFF_GB;
    float* sc = base + OFF_SC;
    float* f  = base + OFF_F;

    embed_kernel<<<kBS, 256>>>(x, in_degree, out_degree, atom_emb, in_deg_emb,
                               out_deg_emb, graph_token, h);
    bias_kernel<<<dim3((kS * kS + 255) / 256, kB), 256>>>(
        attn_bias, spatial_pos, attn_edge_type, x, spatial_emb, edge_emb,
        virt_dist, gb);

    dim3 gemmD(kD / 128, (kBS + 127) / 128);   // (6, 65)
    dim3 gemmF(kFF / 128, (kBS + 127) / 128);  // (24, 65)
    dim3 scoreG((kS + 15) / 16, (kS + 15) / 16, kB * kH);
    dim3 avG(1, (kS + 3) / 4, kB * kH);

    for (int l = 0; l < kL; l++) {
        const size_t wdd = (size_t)l * kD * kD;
        const size_t wfd = (size_t)l * kFF * kD;

        ln_kernel<<<kBS, 256>>>(h, ln1_g + l * kD, ln1_b + l * kD, z);

        sgemm_nt<<<gemmD, 256>>>(z, Wq + wdd, bq + l * kD, q, kBS, kD, kD, EPI_SCALE);
        sgemm_nt<<<gemmD, 256>>>(z, Wk + wdd, bk + l * kD, k, kBS, kD, kD, EPI_NONE);
        sgemm_nt<<<gemmD, 256>>>(z, Wv + wdd, bv + l * kD, v, kBS, kD, kD, EPI_NONE);

        scores_kernel<<<scoreG, 256>>>(q, k, gb, sc);
        softmax_kernel<<<kB * kH * kS, 256>>>(sc);
        attnv_kernel<<<avG, 256>>>(sc, v, o);

        sgemm_nt<<<gemmD, 256>>>(o, Wo + wdd, bo + l * kD, h, kBS, kD, kD, EPI_RES);

        ln_kernel<<<kBS, 256>>>(h, ln2_g + l * kD, ln2_b + l * kD, z);
        sgemm_nt<<<gemmF, 256>>>(z, W1 + wfd, b1 + l * kFF, f, kBS, kFF, kD, EPI_GELU);
        sgemm_nt<<<gemmD, 256>>>(f, W2 + wfd, b2 + l * kD, h, kBS, kD, kFF, EPI_RES);
    }

    final_ln_kernel<<<kBS, 256>>>(h, fin_g, fin_b, out);
}

// round 12
// speedup vs baseline: 1.9495x; 1.9495x over previous
#include <cuda_runtime.h>
#include <math.h>
#include <stdint.h>

// ---------------------------------------------------------------------------
// Problem constants
// ---------------------------------------------------------------------------
namespace {
constexpr int kB   = 32;
constexpr int kN   = 256;
constexpr int kNF  = 3;
constexpr int kNEF = 3;
constexpr int kD   = 768;
constexpr int kFF  = 3072;
constexpr int kH   = 12;
constexpr int kL   = 6;
constexpr int kNA  = 512;
constexpr int kND  = 512;
constexpr int kNE  = 512;
constexpr int kNS  = 512;
constexpr int kS   = 257;          // N + 1
constexpr int kHD  = 64;           // D / H
constexpr int kBS  = kB * kS;      // 8224 tokens
constexpr float kSCALE = 0.125f;   // HD^-0.5
constexpr float kEPS   = 1e-5f;

constexpr size_t SZ_TOK = (size_t)kBS * kD;
constexpr size_t SZ_ATT = (size_t)kB * kH * kS * kS;
constexpr size_t SZ_FF  = (size_t)kBS * kFF;
constexpr size_t OFF_H  = 0;
constexpr size_t OFF_Z  = OFF_H  + SZ_TOK;
constexpr size_t OFF_Q  = OFF_Z  + SZ_TOK;
constexpr size_t OFF_K  = OFF_Q  + SZ_TOK;
constexpr size_t OFF_V  = OFF_K  + SZ_TOK;
constexpr size_t OFF_O  = OFF_V  + SZ_TOK;
constexpr size_t OFF_GB = OFF_O  + SZ_TOK;
constexpr size_t OFF_SC = OFF_GB + SZ_ATT;
constexpr size_t OFF_F  = OFF_SC + SZ_ATT;
// pad so M-edge tile reads can never go OOB
constexpr size_t SCRATCH_ELEMS = OFF_F + SZ_FF + (size_t)128 * kFF;
}  // namespace

__device__ float g_scratch[SCRATCH_ELEMS];

__device__ __forceinline__ int iclamp(int v, int lo, int hi) {
    return min(max(v, lo), hi);
}

__device__ __forceinline__ uint32_t smem_u32(const void* p) {
    uint32_t a;
    asm("{ .reg .u64 t; cvta.to.shared.u64 t, %1; cvt.u32.u64 %0, t; }"
        : "=r"(a) : "l"(p));
    return a;
}

// ---------------------------------------------------------------------------
// bf16 split helpers: x = hi + lo, each bf16; packed as bf16x2
// ---------------------------------------------------------------------------
__device__ __forceinline__ uint32_t pk_bf2(float lo_f, float hi_f) {
    uint32_t r;
    asm("cvt.rn.bf16x2.f32 %0, %1, %2;" : "=r"(r) : "f"(hi_f), "f"(lo_f));
    return r;
}

// split two floats -> {hi pair, lo pair}
__device__ __forceinline__ uint2 sp2(float a, float b) {
    uint32_t h = pk_bf2(a, b);
    float ha = __uint_as_float(h << 16);
    float hb = __uint_as_float(h & 0xffff0000u);
    uint32_t l = pk_bf2(a - ha, b - hb);
    return make_uint2(h, l);
}

__device__ __forceinline__ void split8(float4 f0, float4 f1, uint4& hi, uint4& lo) {
    uint2 s;
    s = sp2(f0.x, f0.y); hi.x = s.x; lo.x = s.y;
    s = sp2(f0.z, f0.w); hi.y = s.x; lo.y = s.y;
    s = sp2(f1.x, f1.y); hi.z = s.x; lo.z = s.y;
    s = sp2(f1.z, f1.w); hi.w = s.x; lo.w = s.y;
}

#define LDM4(r0, r1, r2, r3, ad)                                              \
    asm volatile(                                                             \
        "ldmatrix.sync.aligned.m8n8.x4.shared.b16 {%0,%1,%2,%3}, [%4];"       \
        : "=r"(r0), "=r"(r1), "=r"(r2), "=r"(r3) : "r"(ad))

#define MMA_BF16(c, a, b0r, b1r)                                              \
    asm volatile(                                                             \
        "mma.sync.aligned.m16n8k16.row.col.f32.bf16.bf16.f32 "                \
        "{%0,%1,%2,%3}, {%4,%5,%6,%7}, {%8,%9}, {%0,%1,%2,%3};"               \
        : "+f"((c)[0]), "+f"((c)[1]), "+f"((c)[2]), "+f"((c)[3])              \
        : "r"((a)[0]), "r"((a)[1]), "r"((a)[2]), "r"((a)[3]),                 \
          "r"(b0r), "r"(b1r))

// ---------------------------------------------------------------------------
// Tensor-core GEMM, bf16 2-term split (3 passes), fp32 accumulate.
// C[M,N] = epi(A[M,K] @ W[N,K]^T + bias[N])
// BM=BN=128, BK=32, 256 threads, warp tile 64x32.
// SMEM stage (32KB): Ahi[8K] Alo[8K] Bhi[8K] Blo[8K], double buffered (64KB).
// Tile layout: [128 rows][32 cols] bf16, 64B/row, 16B chunk swizzle:
//   u' = u ^ ((row>>1)&3)   (conflict-free for STS.128 and ldmatrix)
// ---------------------------------------------------------------------------
enum { EPI_NONE = 0, EPI_SCALE = 1, EPI_GELU = 2, EPI_RES = 3 };

namespace {
constexpr uint32_t STAGE = 32768;
constexpr uint32_t GT_SMEM = 2 * STAGE;  // 64KB
}

__device__ __forceinline__ void ldg_chunk(float4* pa, float4* pb,
                                          const float* __restrict__ A,
                                          const float* __restrict__ W,
                                          int M, int K, int bm, int bn,
                                          int kc, int tid) {
#pragma unroll
    for (int it = 0; it < 2; it++) {
        int p = tid + it * 256;     // 0..511
        int row = p >> 2;           // 0..127
        int u = p & 3;              // 8-float chunk
        const float* ap = A + (size_t)(bm + row) * K + kc + u * 8;
        if (bm + row < M) {
            pa[it * 2]     = *(const float4*)ap;
            pa[it * 2 + 1] = *(const float4*)(ap + 4);
        } else {
            pa[it * 2] = pa[it * 2 + 1] = make_float4(0.f, 0.f, 0.f, 0.f);
        }
        const float* wp = W + (size_t)(bn + row) * K + kc + u * 8;
        pb[it * 2]     = *(const float4*)wp;
        pb[it * 2 + 1] = *(const float4*)(wp + 4);
    }
}

__device__ __forceinline__ void cvt_sts(char* sm, uint32_t stOff,
                                        const float4* pa, const float4* pb,
                                        int tid) {
#pragma unroll
    for (int it = 0; it < 2; it++) {
        int p = tid + it * 256;
        int row = p >> 2;
        uint32_t u = (uint32_t)(p & 3);
        uint32_t off = (uint32_t)row * 64 +
                       ((u ^ (((uint32_t)row >> 1) & 3)) << 4);
        uint4 hi, lo;
        split8(pa[it * 2], pa[it * 2 + 1], hi, lo);
        *(uint4*)(sm + stOff + off)         = hi;
        *(uint4*)(sm + stOff + 8192 + off)  = lo;
        split8(pb[it * 2], pb[it * 2 + 1], hi, lo);
        *(uint4*)(sm + stOff + 16384 + off) = hi;
        *(uint4*)(sm + stOff + 24576 + off) = lo;
    }
}

__global__ __launch_bounds__(256, 1)
void gemm_tc(const float* __restrict__ A, const float* __restrict__ W,
             const float* __restrict__ bias, float* __restrict__ C,
             int M, int N, int K, int epi) {
    extern __shared__ char sm[];
    const int tid = threadIdx.x;
    const int lane = tid & 31;
    const int wid = tid >> 5;
    const int bm = blockIdx.y * 128;
    const int bn = blockIdx.x * 128;
    const int wm = (wid & 1) * 64;
    const int wn = (wid >> 1) * 32;
    const uint32_t sbase = smem_u32(sm);
    const int nchunk = K >> 5;

    // lane decomposition for ldmatrix addressing
    const int g = lane >> 3;
    const int r8 = lane & 7;
    // A: g0 -> (m0..7, k0..7)=a0, g1 -> (m8..15,k0..7)=a1, g2 -> k+8 = a2, g3 = a3
    const int aRow = wm + ((g & 1) << 3) + r8;        // + mf*16
    const uint32_t aK1 = (uint32_t)(g >> 1);          // chunk bit (k +8)
    // B: g0 -> (n0..7, k0..7)=b0(nf even), g1 -> k+8 = b1, g2/g3 -> next nfrag
    const int bRow = wn + ((g >> 1) << 3) + r8;       // + p*16
    const uint32_t bK1 = (uint32_t)(g & 1);
    const uint32_t swA = ((uint32_t)(aRow >> 1)) & 3; // invariant to +16 rows
    const uint32_t swB = ((uint32_t)(bRow >> 1)) & 3;

    float acc[4][4][4];
#pragma unroll
    for (int i = 0; i < 4; i++)
#pragma unroll
        for (int j = 0; j < 4; j++)
#pragma unroll
            for (int t = 0; t < 4; t++) acc[i][j][t] = 0.0f;

    float4 pa[4], pb[4];
    ldg_chunk(pa, pb, A, W, M, K, bm, bn, 0, tid);
    cvt_sts(sm, 0, pa, pb, tid);
    __syncthreads();

    for (int c = 0; c < nchunk; c++) {
        if (c + 1 < nchunk)
            ldg_chunk(pa, pb, A, W, M, K, bm, bn, (c + 1) << 5, tid);

        const uint32_t st = sbase + (uint32_t)(c & 1) * STAGE;
#pragma unroll
        for (int ks = 0; ks < 2; ks++) {
            const uint32_t kx = ks ? 2u : 0u;
            uint32_t a[4][4], bh[4][2], bl[4][2];
            // --- A hi frags ---
#pragma unroll
            for (int mf = 0; mf < 4; mf++) {
                uint32_t ad = st + (uint32_t)(aRow + mf * 16) * 64 +
                              (((kx | aK1) ^ swA) << 4);
                LDM4(a[mf][0], a[mf][1], a[mf][2], a[mf][3], ad);
            }
            // --- B hi frags (2 x4 loads cover 4 nfrags) ---
#pragma unroll
            for (int p = 0; p < 2; p++) {
                uint32_t ad = st + 16384u + (uint32_t)(bRow + p * 16) * 64 +
                              (((kx | bK1) ^ swB) << 4);
                uint32_t r0, r1, r2, r3;
                LDM4(r0, r1, r2, r3, ad);
                bh[p * 2][0] = r0; bh[p * 2][1] = r1;
                bh[p * 2 + 1][0] = r2; bh[p * 2 + 1][1] = r3;
            }
            // hi * hi
#pragma unroll
            for (int mf = 0; mf < 4; mf++)
#pragma unroll
                for (int nf = 0; nf < 4; nf++)
                    MMA_BF16(acc[mf][nf], a[mf], bh[nf][0], bh[nf][1]);
            // --- B lo frags ---
#pragma unroll
            for (int p = 0; p < 2; p++) {
                uint32_t ad = st + 24576u + (uint32_t)(bRow + p * 16) * 64 +
                              (((kx | bK1) ^ swB) << 4);
                uint32_t r0, r1, r2, r3;
                LDM4(r0, r1, r2, r3, ad);
                bl[p * 2][0] = r0; bl[p * 2][1] = r1;
                bl[p * 2 + 1][0] = r2; bl[p * 2 + 1][1] = r3;
            }
            // hi * lo
#pragma unroll
            for (int mf = 0; mf < 4; mf++)
#pragma unroll
                for (int nf = 0; nf < 4; nf++)
                    MMA_BF16(acc[mf][nf], a[mf], bl[nf][0], bl[nf][1]);
            // --- A lo frags (overwrite A regs) ---
#pragma unroll
            for (int mf = 0; mf < 4; mf++) {
                uint32_t ad = st + 8192u + (uint32_t)(aRow + mf * 16) * 64 +
                              (((kx | aK1) ^ swA) << 4);
                LDM4(a[mf][0], a[mf][1], a[mf][2], a[mf][3], ad);
            }
            // lo * hi
#pragma unroll
            for (int mf = 0; mf < 4; mf++)
#pragma unroll
                for (int nf = 0; nf < 4; nf++)
                    MMA_BF16(acc[mf][nf], a[mf], bh[nf][0], bh[nf][1]);
        }

        if (c + 1 < nchunk)
            cvt_sts(sm, (uint32_t)((c + 1) & 1) * STAGE, pa, pb, tid);
        __syncthreads();
    }

    // epilogue: direct register -> GMEM, bias + epi
#pragma unroll
    for (int mf = 0; mf < 4; mf++) {
        const int r0 = bm + wm + mf * 16 + (lane >> 2);
#pragma unroll
        for (int nf = 0; nf < 4; nf++) {
            const int cc = bn + wn + nf * 8 + ((lane & 3) << 1);
            const float b0v = bias[cc];
            const float b1v = bias[cc + 1];
            float v0 = acc[mf][nf][0] + b0v;
            float v1 = acc[mf][nf][1] + b1v;
            float v2 = acc[mf][nf][2] + b0v;
            float v3 = acc[mf][nf][3] + b1v;
            if (epi == EPI_SCALE) {
                v0 *= kSCALE; v1 *= kSCALE; v2 *= kSCALE; v3 *= kSCALE;
            } else if (epi == EPI_GELU) {
                v0 = 0.5f * v0 * (1.0f + erff(v0 * 0.70710678118654752f));
                v1 = 0.5f * v1 * (1.0f + erff(v1 * 0.70710678118654752f));
                v2 = 0.5f * v2 * (1.0f + erff(v2 * 0.70710678118654752f));
                v3 = 0.5f * v3 * (1.0f + erff(v3 * 0.70710678118654752f));
            }
            if (r0 < M) {
                float* cp = C + (size_t)r0 * N + cc;
                if (epi == EPI_RES) {
                    float2 old = *(float2*)cp;
                    v0 += old.x; v1 += old.y;
                }
                *(float2*)cp = make_float2(v0, v1);
            }
            if (r0 + 8 < M) {
                float* cp = C + (size_t)(r0 + 8) * N + cc;
                if (epi == EPI_RES) {
                    float2 old = *(float2*)cp;
                    v2 += old.x; v3 += old.y;
                }
                *(float2*)cp = make_float2(v2, v3);
            }
        }
    }
}

// ---------------------------------------------------------------------------
// Embedding
// ---------------------------------------------------------------------------
__global__ void embed_kernel(const int* __restrict__ x,
                             const int* __restrict__ in_deg,
                             const int* __restrict__ out_deg,
                             const float* __restrict__ atom_emb,
                             const float* __restrict__ in_deg_emb,
                             const float* __restrict__ out_deg_emb,
                             const float* __restrict__ graph_token,
                             float* __restrict__ h) {
    int tok = blockIdx.x;
    int b = tok / kS, s = tok % kS;
    float* out = h + (size_t)tok * kD;
    if (s == 0) {
        for (int d = threadIdx.x; d < kD; d += 256) out[d] = graph_token[d];
        return;
    }
    int n = s - 1;
    const int* xr = x + (b * kN + n) * kNF;
    int a0 = iclamp(xr[0], 0, kNA);
    int a1 = iclamp(xr[1], 0, kNA);
    int a2 = iclamp(xr[2], 0, kNA);
    int di = iclamp(in_deg[b * kN + n], 0, kND - 1);
    int dq = iclamp(out_deg[b * kN + n], 0, kND - 1);
    const float* e0 = atom_emb + (size_t)a0 * kD;
    const float* e1 = atom_emb + (size_t)a1 * kD;
    const float* e2 = atom_emb + (size_t)a2 * kD;
    const float* ei = in_deg_emb + (size_t)di * kD;
    const float* eo = out_deg_emb + (size_t)dq * kD;
    for (int d = threadIdx.x; d < kD; d += 256)
        out[d] = e0[d] + e1[d] + e2[d] + ei[d] + eo[d];
}

// ---------------------------------------------------------------------------
// Graph bias gb[b,h,q,k] (mask baked in)
// ---------------------------------------------------------------------------
__global__ void bias_kernel(const float* __restrict__ attn_bias,
                            const int* __restrict__ spatial_pos,
                            const int* __restrict__ edge_type,
                            const int* __restrict__ x,
                            const float* __restrict__ spatial_emb,
                            const float* __restrict__ edge_emb,
                            const float* __restrict__ virt_dist,
                            float* __restrict__ gb) {
    int idx = blockIdx.x * 256 + threadIdx.x;
    if (idx >= kS * kS) return;
    int b = blockIdx.y;
    int q = idx / kS, k = idx % kS;

    size_t obase = ((size_t)b * kH) * kS * kS + (size_t)q * kS + k;

    if (k >= 1 && x[(b * kN + (k - 1)) * kNF] == 0) {
#pragma unroll
        for (int hh = 0; hh < kH; hh++)
            gb[obase + (size_t)hh * kS * kS] = -1e30f;
        return;
    }

    float base = attn_bias[(size_t)b * kS * kS + idx];
    float vals[kH];
#pragma unroll
    for (int hh = 0; hh < kH; hh++) vals[hh] = base;

    if (q >= 1 && k >= 1) {
        size_t e = (size_t)b * kN * kN + (size_t)(q - 1) * kN + (k - 1);
        int sp = iclamp(spatial_pos[e], 0, kNS - 1);
        const int* et = edge_type + e * kNEF;
        int t0 = iclamp(et[0], 0, kNE);
        int t1 = iclamp(et[1], 0, kNE);
        int t2 = iclamp(et[2], 0, kNE);
        const float* sr = spatial_emb + (size_t)sp * kH;
        const float* r0 = edge_emb + (size_t)t0 * kH;
        const float* r1 = edge_emb + (size_t)t1 * kH;
        const float* r2 = edge_emb + (size_t)t2 * kH;
#pragma unroll
        for (int hh = 0; hh < kH; hh++)
            vals[hh] += sr[hh] + (r0[hh] + r1[hh] + r2[hh]) * (1.0f / 3.0f);
    }
    if (q == 0 || k == 0) {
#pragma unroll
        for (int hh = 0; hh < kH; hh++) vals[hh] += virt_dist[hh];
    }
#pragma unroll
    for (int hh = 0; hh < kH; hh++)
        gb[obase + (size_t)hh * kS * kS] = vals[hh];
}

// ---------------------------------------------------------------------------
// LayerNorm
// ---------------------------------------------------------------------------
__global__ void ln_kernel(const float* __restrict__ in,
                          const float* __restrict__ g,
                          const float* __restrict__ bt,
                          float* __restrict__ out) {
    int tok = blockIdx.x;
    int tid = threadIdx.x;
    const float* xr = in + (size_t)tok * kD;
    __shared__ float red[256];
    float x0 = xr[tid], x1 = xr[tid + 256], x2 = xr[tid + 512];
    red[tid] = x0 + x1 + x2;
    __syncthreads();
    for (int off = 128; off; off >>= 1) {
        if (tid < off) red[tid] += red[tid + off];
        __syncthreads();
    }
    float mean = red[0] * (1.0f / kD);
    __syncthreads();
    float d0 = x0 - mean, d1 = x1 - mean, d2 = x2 - mean;
    red[tid] = d0 * d0 + d1 * d1 + d2 * d2;
    __syncthreads();
    for (int off = 128; off; off >>= 1) {
        if (tid < off) red[tid] += red[tid + off];
        __syncthreads();
    }
    float inv = rsqrtf(red[0] * (1.0f / kD) + kEPS);
    float* orow = out + (size_t)tok * kD;
    orow[tid]       = d0 * inv * g[tid]       + bt[tid];
    orow[tid + 256] = d1 * inv * g[tid + 256] + bt[tid + 256];
    orow[tid + 512] = d2 * inv * g[tid + 512] + bt[tid + 512];
}

__global__ void final_ln_kernel(const float* __restrict__ in,
                                const float* __restrict__ g,
                                const float* __restrict__ bt,
                                float* __restrict__ out) {
    int tok = blockIdx.x;
    int b = tok / kS, s = tok % kS;
    int tid = threadIdx.x;
    const float* xr = in + (size_t)tok * kD;
    __shared__ float red[256];
    float x0 = xr[tid], x1 = xr[tid + 256], x2 = xr[tid + 512];
    red[tid] = x0 + x1 + x2;
    __syncthreads();
    for (int off = 128; off; off >>= 1) {
        if (tid < off) red[tid] += red[tid + off];
        __syncthreads();
    }
    float mean = red[0] * (1.0f / kD);
    __syncthreads();
    float d0 = x0 - mean, d1 = x1 - mean, d2 = x2 - mean;
    red[tid] = d0 * d0 + d1 * d1 + d2 * d2;
    __syncthreads();
    for (int off = 128; off; off >>= 1) {
        if (tid < off) red[tid] += red[tid + off];
        __syncthreads();
    }
    float inv = rsqrtf(red[0] * (1.0f / kD) + kEPS);
    float* orow = (s == 0)
        ? out + (size_t)kB * kN * kD + (size_t)b * kD
        : out + ((size_t)b * kN + (s - 1)) * kD;
    orow[tid]       = d0 * inv * g[tid]       + bt[tid];
    orow[tid + 256] = d1 * inv * g[tid + 256] + bt[tid + 256];
    orow[tid + 512] = d2 * inv * g[tid + 512] + bt[tid + 512];
}

// ---------------------------------------------------------------------------
// scores / softmax / attn*V (fp32, unchanged from passing R5)
// ---------------------------------------------------------------------------
__global__ void scores_kernel(const float* __restrict__ qm,
                              const float* __restrict__ km,
                              const float* __restrict__ gb,
                              float* __restrict__ sc) {
    int bh = blockIdx.z;
    int b = bh / kH, h = bh % kH;
    int q0 = blockIdx.y * 16, k0 = blockIdx.x * 16;
    __shared__ float qs[16][68];
    __shared__ float ks[16][68];
    int tid = threadIdx.x;
    int lr = tid >> 4;
    int lc = (tid & 15) * 4;

    int gq = q0 + lr;
    float4 v4 = make_float4(0.f, 0.f, 0.f, 0.f);
    if (gq < kS)
        v4 = *(const float4*)(qm + ((size_t)(b * kS + gq)) * kD + h * kHD + lc);
    qs[lr][lc] = v4.x; qs[lr][lc + 1] = v4.y; qs[lr][lc + 2] = v4.z; qs[lr][lc + 3] = v4.w;

    int gk = k0 + lr;
    v4 = make_float4(0.f, 0.f, 0.f, 0.f);
    if (gk < kS)
        v4 = *(const float4*)(km + ((size_t)(b * kS + gk)) * kD + h * kHD + lc);
    ks[lr][lc] = v4.x; ks[lr][lc + 1] = v4.y; ks[lr][lc + 2] = v4.z; ks[lr][lc + 3] = v4.w;
    __syncthreads();

    int qi = tid >> 4, ki = tid & 15;
    float acc = 0.0f;
#pragma unroll
    for (int d = 0; d < kHD; d++) acc += qs[qi][d] * ks[ki][d];

    int oq = q0 + qi, ok = k0 + ki;
    if (oq < kS && ok < kS) {
        size_t o = (((size_t)bh) * kS + oq) * kS + ok;
        sc[o] = acc + gb[o];
    }
}

__global__ void softmax_kernel(float* __restrict__ sc) {
    float* p = sc + (size_t)blockIdx.x * kS;
    int tid = threadIdx.x;
    __shared__ float red[256];
    float a = (tid < kS) ? p[tid] : -3.4e38f;
    float c = (tid == 0) ? p[256] : -3.4e38f;
    red[tid] = fmaxf(a, c);
    __syncthreads();
    for (int off = 128; off; off >>= 1) {
        if (tid < off) red[tid] = fmaxf(red[tid], red[tid + off]);
        __syncthreads();
    }
    float m = red[0];
    __syncthreads();
    float ea = (tid < kS) ? expf(a - m) : 0.0f;
    float ec = (tid == 0) ? expf(c - m) : 0.0f;
    red[tid] = ea + ec;
    __syncthreads();
    for (int off = 128; off; off >>= 1) {
        if (tid < off) red[tid] += red[tid + off];
        __syncthreads();
    }
    float inv = 1.0f / red[0];
    if (tid < kS) p[tid] = ea * inv;
    if (tid == 0) p[256] = ec * inv;
}

__global__ void attnv_kernel(const float* __restrict__ sc,
                             const float* __restrict__ vm,
                             float* __restrict__ om) {
    int bh = blockIdx.z;
    int b = bh / kH, h = bh % kH;
    int q0 = blockIdx.y * 4;
    int r = threadIdx.x >> 6;
    int d = threadIdx.x & 63;
    __shared__ float as_[4][kS];
    for (int idx = threadIdx.x; idx < 4 * kS; idx += 256) {
        int rr = idx / kS, kk = idx % kS;
        int gq = q0 + rr;
        as_[rr][kk] = (gq < kS) ? sc[(((size_t)bh) * kS + gq) * kS + kk] : 0.0f;
    }
    __syncthreads();
    const float* vb = vm + (size_t)b * kS * kD + h * kHD + d;
    float acc = 0.0f;
#pragma unroll 4
    for (int kk = 0; kk < kS; kk++) acc += as_[r][kk] * vb[(size_t)kk * kD];
    int gq = q0 + r;
    if (gq < kS)
        om[((size_t)(b * kS + gq)) * kD + h * kHD + d] = acc;
}

// ---------------------------------------------------------------------------
// Host launcher
// ---------------------------------------------------------------------------
extern "C" void kernel_launch(void* const* d_in, const int* in_sizes, int n_in,
                              void* d_out, int out_size) {
    (void)in_sizes; (void)n_in; (void)out_size;

    const int*   x              = (const int*)  d_in[0];
    const float* attn_bias      = (const float*)d_in[1];
    const int*   spatial_pos    = (const int*)  d_in[2];
    const int*   attn_edge_type = (const int*)  d_in[3];
    const int*   in_degree      = (const int*)  d_in[4];
    const int*   out_degree     = (const int*)  d_in[5];
    const float* atom_emb       = (const float*)d_in[6];
    const float* in_deg_emb     = (const float*)d_in[7];
    const float* out_deg_emb    = (const float*)d_in[8];
    const float* graph_token    = (const float*)d_in[9];
    const float* spatial_emb    = (const float*)d_in[10];
    const float* edge_emb       = (const float*)d_in[11];
    const float* virt_dist      = (const float*)d_in[12];
    const float* Wq             = (const float*)d_in[13];
    const float* Wk             = (const float*)d_in[14];
    const float* Wv             = (const float*)d_in[15];
    const float* Wo             = (const float*)d_in[16];
    const float* bq             = (const float*)d_in[17];
    const float* bk             = (const float*)d_in[18];
    const float* bv             = (const float*)d_in[19];
    const float* bo             = (const float*)d_in[20];
    const float* ln1_g          = (const float*)d_in[21];
    const float* ln1_b          = (const float*)d_in[22];
    const float* ln2_g          = (const float*)d_in[23];
    const float* ln2_b          = (const float*)d_in[24];
    const float* W1             = (const float*)d_in[25];
    const float* b1             = (const float*)d_in[26];
    const float* W2             = (const float*)d_in[27];
    const float* b2             = (const float*)d_in[28];
    const float* fin_g          = (const float*)d_in[29];
    const float* fin_b          = (const float*)d_in[30];
    float* out = (float*)d_out;

    float* base = nullptr;
    cudaGetSymbolAddress((void**)&base, g_scratch);
    float* h  = base + OFF_H;
    float* z  = base + OFF_Z;
    float* q  = base + OFF_Q;
    float* k  = base + OFF_K;
    float* v  = base + OFF_V;
    float* o  = base + OFF_O;
    float* gb = base + OFF_GB;
    float* sc = base + OFF_SC;
    float* f  = base + OFF_F;

    cudaFuncSetAttribute(gemm_tc, cudaFuncAttributeMaxDynamicSharedMemorySize,
                         GT_SMEM);

    embed_kernel<<<kBS, 256>>>(x, in_degree, out_degree, atom_emb, in_deg_emb,
                               out_deg_emb, graph_token, h);
    bias_kernel<<<dim3((kS * kS + 255) / 256, kB), 256>>>(
        attn_bias, spatial_pos, attn_edge_type, x, spatial_emb, edge_emb,
        virt_dist, gb);

    const int mtiles = (kBS + 127) / 128;            // 65
    dim3 gemmD(kD / 128, mtiles);                    // (6, 65)
    dim3 gemmF(kFF / 128, mtiles);                   // (24, 65)
    dim3 scoreG((kS + 15) / 16, (kS + 15) / 16, kB * kH);
    dim3 avG(1, (kS + 3) / 4, kB * kH);

    for (int l = 0; l < kL; l++) {
        const size_t wdd = (size_t)l * kD * kD;
        const size_t wfd = (size_t)l * kFF * kD;

        ln_kernel<<<kBS, 256>>>(h, ln1_g + l * kD, ln1_b + l * kD, z);

        gemm_tc<<<gemmD, 256, GT_SMEM>>>(z, Wq + wdd, bq + l * kD, q,
                                         kBS, kD, kD, EPI_SCALE);
        gemm_tc<<<gemmD, 256, GT_SMEM>>>(z, Wk + wdd, bk + l * kD, k,
                                         kBS, kD, kD, EPI_NONE);
        gemm_tc<<<gemmD, 256, GT_SMEM>>>(z, Wv + wdd, bv + l * kD, v,
                                         kBS, kD, kD, EPI_NONE);

        scores_kernel<<<scoreG, 256>>>(q, k, gb, sc);
        softmax_kernel<<<kB * kH * kS, 256>>>(sc);
        attnv_kernel<<<avG, 256>>>(sc, v, o);

        gemm_tc<<<gemmD, 256, GT_SMEM>>>(o, Wo + wdd, bo + l * kD, h,
                                         kBS, kD, kD, EPI_RES);

        ln_kernel<<<kBS, 256>>>(h, ln2_g + l * kD, ln2_b + l * kD, z);
        gemm_tc<<<gemmF, 256, GT_SMEM>>>(z, W1 + wfd, b1 + l * kFF, f,
                                         kBS, kFF, kD, EPI_GELU);
        gemm_tc<<<gemmD, 256, GT_SMEM>>>(f, W2 + wfd, b2 + l * kD, h,
                                         kBS, kD, kFF, EPI_RES);
    }

    final_ln_kernel<<<kBS, 256>>>(h, fin_g, fin_b, out);
}

// round 13
// speedup vs baseline: 2.4876x; 1.2760x over previous
#include <cuda_runtime.h>
#include <math.h>
#include <stdint.h>

// ---------------------------------------------------------------------------
// Problem constants
// ---------------------------------------------------------------------------
namespace {
constexpr int kB   = 32;
constexpr int kN   = 256;
constexpr int kNF  = 3;
constexpr int kNEF = 3;
constexpr int kD   = 768;
constexpr int kFF  = 3072;
constexpr int kH   = 12;
constexpr int kL   = 6;
constexpr int kNA  = 512;
constexpr int kND  = 512;
constexpr int kNE  = 512;
constexpr int kNS  = 512;
constexpr int kS   = 257;          // N + 1
constexpr int kHD  = 64;           // D / H
constexpr int kBS  = kB * kS;      // 8224 tokens
constexpr float kSCALE = 0.125f;   // HD^-0.5
constexpr float kEPS   = 1e-5f;

constexpr size_t SZ_TOK = (size_t)kBS * kD;            // 6,316,032
constexpr size_t SZ_ATT = (size_t)kB * kH * kS * kS;   // 25,365,504
constexpr size_t SZ_FF  = (size_t)kBS * kFF;           // 25,264,128
constexpr size_t OFF_H  = 0;
constexpr size_t OFF_Z  = OFF_H  + SZ_TOK;
constexpr size_t OFF_Q  = OFF_Z  + SZ_TOK;
constexpr size_t OFF_K  = OFF_Q  + SZ_TOK;
constexpr size_t OFF_V  = OFF_K  + SZ_TOK;
constexpr size_t OFF_O  = OFF_V  + SZ_TOK;
constexpr size_t OFF_GB = OFF_O  + SZ_TOK;
constexpr size_t OFF_F  = OFF_GB + SZ_ATT;
constexpr size_t SCRATCH_ELEMS = OFF_F + SZ_FF + (size_t)128 * kFF;

// bf16 hi/lo conversion buffers (uint16 elements)
constexpr size_t W_DD   = (size_t)kL * kD * kD;        // 3,538,944
constexpr size_t W_FD   = (size_t)kL * kFF * kD;       // 14,155,776
constexpr size_t CV_WQ  = 0;
constexpr size_t CV_WK  = CV_WQ + 2 * W_DD;
constexpr size_t CV_WV  = CV_WK + 2 * W_DD;
constexpr size_t CV_WO  = CV_WV + 2 * W_DD;
constexpr size_t CV_W1  = CV_WO + 2 * W_DD;
constexpr size_t CV_W2  = CV_W1 + 2 * W_FD;
constexpr size_t CV_A   = CV_W2 + 2 * W_FD;
constexpr size_t ACT_PLANE = (size_t)8320 * kFF;       // 25,559,040 (padded rows)
constexpr size_t CV_TOTAL  = CV_A + 2 * ACT_PLANE;     // 136,052,736
}  // namespace

__device__ float    g_scratch[SCRATCH_ELEMS];
__device__ uint16_t g_cv[CV_TOTAL];

__device__ __forceinline__ int iclamp(int v, int lo, int hi) {
    return min(max(v, lo), hi);
}

__device__ __forceinline__ uint32_t smem_u32(const void* p) {
    uint32_t a;
    asm("{ .reg .u64 t; cvta.to.shared.u64 t, %1; cvt.u32.u64 %0, t; }"
        : "=r"(a) : "l"(p));
    return a;
}

// ---------------------------------------------------------------------------
// bf16 split helpers
// ---------------------------------------------------------------------------
__device__ __forceinline__ uint32_t pk_bf2(float lo_f, float hi_f) {
    uint32_t r;
    asm("cvt.rn.bf16x2.f32 %0, %1, %2;" : "=r"(r) : "f"(hi_f), "f"(lo_f));
    return r;
}
// split two floats -> {hi pair, lo pair} (mem order: first arg at low half)
__device__ __forceinline__ uint2 sp2(float a, float b) {
    uint32_t h = pk_bf2(a, b);
    float ha = __uint_as_float(h << 16);
    float hb = __uint_as_float(h & 0xffff0000u);
    uint32_t l = pk_bf2(a - ha, b - hb);
    return make_uint2(h, l);
}

// fp32 [n] -> hi bf16 plane, lo bf16 plane (row-major preserved)
__global__ void cvt_split(const float4* __restrict__ in,
                          uint2* __restrict__ hi, uint2* __restrict__ lo,
                          int n4) {
    for (int i = blockIdx.x * 256 + threadIdx.x; i < n4; i += gridDim.x * 256) {
        float4 v = in[i];
        uint2 s0 = sp2(v.x, v.y);
        uint2 s1 = sp2(v.z, v.w);
        hi[i] = make_uint2(s0.x, s1.x);
        lo[i] = make_uint2(s0.y, s1.y);
    }
}

// ---------------------------------------------------------------------------
// cp.async helpers
// ---------------------------------------------------------------------------
__device__ __forceinline__ void cpa16(uint32_t dst, const void* src) {
    asm volatile("cp.async.cg.shared.global [%0], [%1], 16;"
                 :: "r"(dst), "l"(src) : "memory");
}
__device__ __forceinline__ void cpa_commit() {
    asm volatile("cp.async.commit_group;" ::: "memory");
}

#define LDM4(r0, r1, r2, r3, ad)                                              \
    asm volatile(                                                             \
        "ldmatrix.sync.aligned.m8n8.x4.shared.b16 {%0,%1,%2,%3}, [%4];"       \
        : "=r"(r0), "=r"(r1), "=r"(r2), "=r"(r3) : "r"(ad))

#define MMA_BF16(c, a, b0r, b1r)                                              \
    asm volatile(                                                             \
        "mma.sync.aligned.m16n8k16.row.col.f32.bf16.bf16.f32 "                \
        "{%0,%1,%2,%3}, {%4,%5,%6,%7}, {%8,%9}, {%0,%1,%2,%3};"               \
        : "+f"((c)[0]), "+f"((c)[1]), "+f"((c)[2]), "+f"((c)[3])              \
        : "r"((a)[0]), "r"((a)[1]), "r"((a)[2]), "r"((a)[3]),                 \
          "r"(b0r), "r"(b1r))

// ---------------------------------------------------------------------------
// GEMM (bf16 2-term split, 3 MMA passes, fp32 acc), pre-converted operands.
// C[M,N] = epi(A @ W^T + bias).  BM=BN=128, BK=32, 256 threads.
// 3-stage cp.async pipeline; stage = Ahi[8K] Alo[8K] Bhi[8K] Blo[8K].
// ---------------------------------------------------------------------------
enum { EPI_NONE = 0, EPI_SCALE = 1, EPI_GELU = 2, EPI_RES = 3 };

namespace {
constexpr uint32_t STAGE = 32768;
constexpr uint32_t GT_SMEM = 3 * STAGE;  // 96KB
}

__device__ __forceinline__ void issue_stage(uint32_t st,
                                            const uint16_t* __restrict__ Ahi,
                                            const uint16_t* __restrict__ Alo,
                                            const uint16_t* __restrict__ Whi,
                                            const uint16_t* __restrict__ Wlo,
                                            int K, int bm, int bn, int kc,
                                            int tid) {
#pragma unroll
    for (int it = 0; it < 2; it++) {
        int p = tid + it * 256;
        int row = p >> 2;
        uint32_t u = (uint32_t)(p & 3);
        uint32_t dst = st + (uint32_t)row * 64 +
                       ((u ^ (((uint32_t)row >> 1) & 3)) << 4);
        size_t ao = (size_t)(bm + row) * K + kc + u * 8;
        size_t wo = (size_t)(bn + row) * K + kc + u * 8;
        cpa16(dst,          Ahi + ao);
        cpa16(dst + 8192,   Alo + ao);
        cpa16(dst + 16384,  Whi + wo);
        cpa16(dst + 24576,  Wlo + wo);
    }
    cpa_commit();
}

__global__ __launch_bounds__(256, 1)
void gemm_tc(const uint16_t* __restrict__ Ahi, const uint16_t* __restrict__ Alo,
             const uint16_t* __restrict__ Whi, const uint16_t* __restrict__ Wlo,
             const float* __restrict__ bias, float* __restrict__ C,
             int M, int N, int K, int epi) {
    extern __shared__ char sm[];
    const int tid = threadIdx.x;
    const int lane = tid & 31;
    const int wid = tid >> 5;
    const int bm = blockIdx.y * 128;
    const int bn = blockIdx.x * 128;
    const int wm = (wid & 1) * 64;
    const int wn = (wid >> 1) * 32;
    const uint32_t sbase = smem_u32(sm);
    const int nchunk = K >> 5;

    const int g = lane >> 3;
    const int r8 = lane & 7;
    const int aRow = wm + ((g & 1) << 3) + r8;
    const uint32_t aK1 = (uint32_t)(g >> 1);
    const int bRow = wn + ((g >> 1) << 3) + r8;
    const uint32_t bK1 = (uint32_t)(g & 1);
    const uint32_t swA = ((uint32_t)(aRow >> 1)) & 3;
    const uint32_t swB = ((uint32_t)(bRow >> 1)) & 3;

    float acc[4][4][4];
#pragma unroll
    for (int i = 0; i < 4; i++)
#pragma unroll
        for (int j = 0; j < 4; j++)
#pragma unroll
            for (int t = 0; t < 4; t++) acc[i][j][t] = 0.0f;

    issue_stage(sbase,         Ahi, Alo, Whi, Wlo, K, bm, bn, 0,  tid);
    issue_stage(sbase + STAGE, Ahi, Alo, Whi, Wlo, K, bm, bn, 32, tid);

    for (int c = 0; c < nchunk; c++) {
        if (c + 1 == nchunk)
            asm volatile("cp.async.wait_group 0;" ::: "memory");
        else
            asm volatile("cp.async.wait_group 1;" ::: "memory");
        __syncthreads();
        if (c + 2 < nchunk) {
            int s2 = (c + 2) % 3;
            issue_stage(sbase + (uint32_t)s2 * STAGE, Ahi, Alo, Whi, Wlo,
                        K, bm, bn, (c + 2) << 5, tid);
        }

        const uint32_t st = sbase + (uint32_t)(c % 3) * STAGE;
#pragma unroll
        for (int ks = 0; ks < 2; ks++) {
            const uint32_t kx = ks ? 2u : 0u;
            uint32_t a[4][4], bh[4][2], bl[4][2];
#pragma unroll
            for (int mf = 0; mf < 4; mf++) {
                uint32_t ad = st + (uint32_t)(aRow + mf * 16) * 64 +
                              (((kx | aK1) ^ swA) << 4);
                LDM4(a[mf][0], a[mf][1], a[mf][2], a[mf][3], ad);
            }
#pragma unroll
            for (int p = 0; p < 2; p++) {
                uint32_t ad = st + 16384u + (uint32_t)(bRow + p * 16) * 64 +
                              (((kx | bK1) ^ swB) << 4);
                uint32_t r0, r1, r2, r3;
                LDM4(r0, r1, r2, r3, ad);
                bh[p * 2][0] = r0; bh[p * 2][1] = r1;
                bh[p * 2 + 1][0] = r2; bh[p * 2 + 1][1] = r3;
            }
#pragma unroll
            for (int mf = 0; mf < 4; mf++)
#pragma unroll
                for (int nf = 0; nf < 4; nf++)
                    MMA_BF16(acc[mf][nf], a[mf], bh[nf][0], bh[nf][1]);
#pragma unroll
            for (int p = 0; p < 2; p++) {
                uint32_t ad = st + 24576u + (uint32_t)(bRow + p * 16) * 64 +
                              (((kx | bK1) ^ swB) << 4);
                uint32_t r0, r1, r2, r3;
                LDM4(r0, r1, r2, r3, ad);
                bl[p * 2][0] = r0; bl[p * 2][1] = r1;
                bl[p * 2 + 1][0] = r2; bl[p * 2 + 1][1] = r3;
            }
#pragma unroll
            for (int mf = 0; mf < 4; mf++)
#pragma unroll
                for (int nf = 0; nf < 4; nf++)
                    MMA_BF16(acc[mf][nf], a[mf], bl[nf][0], bl[nf][1]);
#pragma unroll
            for (int mf = 0; mf < 4; mf++) {
                uint32_t ad = st + 8192u + (uint32_t)(aRow + mf * 16) * 64 +
                              (((kx | aK1) ^ swA) << 4);
                LDM4(a[mf][0], a[mf][1], a[mf][2], a[mf][3], ad);
            }
#pragma unroll
            for (int mf = 0; mf < 4; mf++)
#pragma unroll
                for (int nf = 0; nf < 4; nf++)
                    MMA_BF16(acc[mf][nf], a[mf], bh[nf][0], bh[nf][1]);
        }
    }

    // epilogue: register -> GMEM
#pragma unroll
    for (int mf = 0; mf < 4; mf++) {
        const int r0 = bm + wm + mf * 16 + (lane >> 2);
#pragma unroll
        for (int nf = 0; nf < 4; nf++) {
            const int cc = bn + wn + nf * 8 + ((lane & 3) << 1);
            const float b0v = bias[cc];
            const float b1v = bias[cc + 1];
            float v0 = acc[mf][nf][0] + b0v;
            float v1 = acc[mf][nf][1] + b1v;
            float v2 = acc[mf][nf][2] + b0v;
            float v3 = acc[mf][nf][3] + b1v;
            if (epi == EPI_SCALE) {
                v0 *= kSCALE; v1 *= kSCALE; v2 *= kSCALE; v3 *= kSCALE;
            } else if (epi == EPI_GELU) {
                v0 = 0.5f * v0 * (1.0f + erff(v0 * 0.70710678118654752f));
                v1 = 0.5f * v1 * (1.0f + erff(v1 * 0.70710678118654752f));
                v2 = 0.5f * v2 * (1.0f + erff(v2 * 0.70710678118654752f));
                v3 = 0.5f * v3 * (1.0f + erff(v3 * 0.70710678118654752f));
            }
            if (r0 < M) {
                float* cp = C + (size_t)r0 * N + cc;
                if (epi == EPI_RES) {
                    float2 old = *(float2*)cp;
                    v0 += old.x; v1 += old.y;
                }
                *(float2*)cp = make_float2(v0, v1);
            }
            if (r0 + 8 < M) {
                float* cp = C + (size_t)(r0 + 8) * N + cc;
                if (epi == EPI_RES) {
                    float2 old = *(float2*)cp;
                    v2 += old.x; v3 += old.y;
                }
                *(float2*)cp = make_float2(v2, v3);
            }
        }
    }
}

// ---------------------------------------------------------------------------
// Fused attention: per (b,h,q-tile=64) block computes softmax(QK^T+gb)V.
// 256 threads. SMEM: kT[64][72] (alias vs[64][68]) | qs[64][68] | ps[64][264]
// ---------------------------------------------------------------------------
namespace {
constexpr int AT_KT = 0;        // 4608 floats
constexpr int AT_QS = 4608;     // 4352 floats
constexpr int AT_PS = 8960;     // 16896 floats
constexpr uint32_t AT_SMEM = (8960 + 16896) * 4;  // 103,424 B
}

__global__ __launch_bounds__(256)
void attn_fused(const float* __restrict__ qm, const float* __restrict__ km,
                const float* __restrict__ vm, const float* __restrict__ gb,
                float* __restrict__ om) {
    extern __shared__ float s[];
    float* kT = s + AT_KT;   // [64][72]; later vs [64][68]
    float* qs = s + AT_QS;   // [64][68]
    float* ps = s + AT_PS;   // [64][264]
    const int tid = threadIdx.x;
    const int lane = tid & 31;
    const int wid = tid >> 5;
    const int bh = blockIdx.y;
    const int b = bh / kH, hh = bh % kH;
    const int q0 = blockIdx.x * 64;

    // ---- load Q tile (64 rows x 64 d) ----
#pragma unroll
    for (int it = 0; it < 4; it++) {
        int p = tid + it * 256;      // 0..1023
        int r = p >> 4;              // 0..63
        int u = p & 15;              // float4 idx
        int gq = q0 + r;
        float4 v4 = make_float4(0.f, 0.f, 0.f, 0.f);
        if (gq < kS)
            v4 = *(const float4*)(qm + ((size_t)(b * kS + gq)) * kD +
                                  hh * kHD + u * 4);
        *(float4*)&qs[r * 68 + u * 4] = v4;
    }

    const int qg = tid >> 3;         // 0..31 -> q = qg*2, qg*2+1
    const int kg = tid & 7;          // k sub: kg*8..kg*8+7
    const int q1 = qg * 2;

    // ---- phase 1: scores ----
    for (int koff = 0; koff < kS; koff += 64) {
        // load K chunk transposed: kT[d][t]
        {
            int t = tid & 63;
            int db = (tid >> 6) * 16;
            int gk = koff + t;
#pragma unroll
            for (int m = 0; m < 4; m++) {
                float4 v4 = make_float4(0.f, 0.f, 0.f, 0.f);
                if (gk < kS)
                    v4 = *(const float4*)(km + ((size_t)(b * kS + gk)) * kD +
                                          hh * kHD + db + m * 4);
                kT[(db + m * 4 + 0) * 72 + t] = v4.x;
                kT[(db + m * 4 + 1) * 72 + t] = v4.y;
                kT[(db + m * 4 + 2) * 72 + t] = v4.z;
                kT[(db + m * 4 + 3) * 72 + t] = v4.w;
            }
        }
        __syncthreads();

        float a0[8], a1[8];
#pragma unroll
        for (int j = 0; j < 8; j++) { a0[j] = 0.f; a1[j] = 0.f; }
#pragma unroll 16
        for (int d = 0; d < 64; d++) {
            float qv0 = qs[q1 * 68 + d];
            float qv1 = qs[(q1 + 1) * 68 + d];
            float4 ka = *(float4*)&kT[d * 72 + kg * 8];
            float4 kb = *(float4*)&kT[d * 72 + kg * 8 + 4];
            a0[0] += qv0 * ka.x; a0[1] += qv0 * ka.y;
            a0[2] += qv0 * ka.z; a0[3] += qv0 * ka.w;
            a0[4] += qv0 * kb.x; a0[5] += qv0 * kb.y;
            a0[6] += qv0 * kb.z; a0[7] += qv0 * kb.w;
            a1[0] += qv1 * ka.x; a1[1] += qv1 * ka.y;
            a1[2] += qv1 * ka.z; a1[3] += qv1 * ka.w;
            a1[4] += qv1 * kb.x; a1[5] += qv1 * kb.y;
            a1[6] += qv1 * kb.z; a1[7] += qv1 * kb.w;
        }
        // store scores (+gb) for both q rows
        {
            int gq = q0 + q1;
            const size_t gr0 = ((size_t)bh * kS + gq) * kS;
            const size_t gr1 = gr0 + kS;
            bool v0 = (gq < kS), v1 = (gq + 1 < kS);
#pragma unroll
            for (int j = 0; j < 8; j++) {
                int gk = koff + kg * 8 + j;
                if (gk < kS) {
                    ps[q1 * 264 + gk] =
                        v0 ? (a0[j] + gb[gr0 + gk]) : 0.0f;
                    ps[(q1 + 1) * 264 + gk] =
                        v1 ? (a1[j] + gb[gr1 + gk]) : 0.0f;
                }
            }
        }
        __syncthreads();
    }

    // ---- phase 2: softmax (warp per 8 rows) ----
    for (int rr = 0; rr < 8; rr++) {
        int r = wid * 8 + rr;
        float m = -3.4e38f;
        for (int kk = lane; kk < kS; kk += 32)
            m = fmaxf(m, ps[r * 264 + kk]);
#pragma unroll
        for (int o2 = 16; o2; o2 >>= 1)
            m = fmaxf(m, __shfl_xor_sync(0xffffffffu, m, o2));
        float sum = 0.0f;
        for (int kk = lane; kk < kS; kk += 32) {
            float e = expf(ps[r * 264 + kk] - m);
            ps[r * 264 + kk] = e;
            sum += e;
        }
#pragma unroll
        for (int o2 = 16; o2; o2 >>= 1)
            sum += __shfl_xor_sync(0xffffffffu, sum, o2);
        float inv = 1.0f / sum;
        for (int kk = lane; kk < kS; kk += 32)
            ps[r * 264 + kk] *= inv;
    }
    __syncthreads();

    // ---- phase 3: P @ V ----
    float* vs = s + AT_KT;           // [64][68], aliases kT
    const int dg = tid & 7;
    const int d8 = dg * 8;
    float o0[8], o1[8];
#pragma unroll
    for (int j = 0; j < 8; j++) { o0[j] = 0.f; o1[j] = 0.f; }

    for (int koff = 0; koff < kS; koff += 64) {
        {
#pragma unroll
            for (int it = 0; it < 4; it++) {
                int p = tid + it * 256;
                int t = p >> 4;
                int u = p & 15;
                int gk = koff + t;
                float4 v4 = make_float4(0.f, 0.f, 0.f, 0.f);
                if (gk < kS)
                    v4 = *(const float4*)(vm + ((size_t)(b * kS + gk)) * kD +
                                          hh * kHD + u * 4);
                *(float4*)&vs[t * 68 + u * 4] = v4;
            }
        }
        __syncthreads();
        int klim = min(64, kS - koff);
#pragma unroll 8
        for (int kl = 0; kl < klim; kl++) {
            float p0 = ps[q1 * 264 + koff + kl];
            float p1 = ps[(q1 + 1) * 264 + koff + kl];
            float4 va = *(float4*)&vs[kl * 68 + d8];
            float4 vb = *(float4*)&vs[kl * 68 + d8 + 4];
            o0[0] += p0 * va.x; o0[1] += p0 * va.y;
            o0[2] += p0 * va.z; o0[3] += p0 * va.w;
            o0[4] += p0 * vb.x; o0[5] += p0 * vb.y;
            o0[6] += p0 * vb.z; o0[7] += p0 * vb.w;
            o1[0] += p1 * va.x; o1[1] += p1 * va.y;
            o1[2] += p1 * va.z; o1[3] += p1 * va.w;
            o1[4] += p1 * vb.x; o1[5] += p1 * vb.y;
            o1[6] += p1 * vb.z; o1[7] += p1 * vb.w;
        }
        __syncthreads();
    }

    // write o
    {
        int gq = q0 + q1;
        if (gq < kS) {
            float* op = om + ((size_t)(b * kS + gq)) * kD + hh * kHD + d8;
            *(float4*)op       = make_float4(o0[0], o0[1], o0[2], o0[3]);
            *(float4*)(op + 4) = make_float4(o0[4], o0[5], o0[6], o0[7]);
        }
        if (gq + 1 < kS) {
            float* op = om + ((size_t)(b * kS + gq + 1)) * kD + hh * kHD + d8;
            *(float4*)op       = make_float4(o1[0], o1[1], o1[2], o1[3]);
            *(float4*)(op + 4) = make_float4(o1[4], o1[5], o1[6], o1[7]);
        }
    }
}

// ---------------------------------------------------------------------------
// Embedding
// ---------------------------------------------------------------------------
__global__ void embed_kernel(const int* __restrict__ x,
                             const int* __restrict__ in_deg,
                             const int* __restrict__ out_deg,
                             const float* __restrict__ atom_emb,
                             const float* __restrict__ in_deg_emb,
                             const float* __restrict__ out_deg_emb,
                             const float* __restrict__ graph_token,
                             float* __restrict__ h) {
    int tok = blockIdx.x;
    int b = tok / kS, s = tok % kS;
    float* out = h + (size_t)tok * kD;
    if (s == 0) {
        for (int d = threadIdx.x; d < kD; d += 256) out[d] = graph_token[d];
        return;
    }
    int n = s - 1;
    const int* xr = x + (b * kN + n) * kNF;
    int a0 = iclamp(xr[0], 0, kNA);
    int a1 = iclamp(xr[1], 0, kNA);
    int a2 = iclamp(xr[2], 0, kNA);
    int di = iclamp(in_deg[b * kN + n], 0, kND - 1);
    int dq = iclamp(out_deg[b * kN + n], 0, kND - 1);
    const float* e0 = atom_emb + (size_t)a0 * kD;
    const float* e1 = atom_emb + (size_t)a1 * kD;
    const float* e2 = atom_emb + (size_t)a2 * kD;
    const float* ei = in_deg_emb + (size_t)di * kD;
    const float* eo = out_deg_emb + (size_t)dq * kD;
    for (int d = threadIdx.x; d < kD; d += 256)
        out[d] = e0[d] + e1[d] + e2[d] + ei[d] + eo[d];
}

// ---------------------------------------------------------------------------
// Graph bias gb[b,h,q,k] (mask baked in)
// ---------------------------------------------------------------------------
__global__ void bias_kernel(const float* __restrict__ attn_bias,
                            const int* __restrict__ spatial_pos,
                            const int* __restrict__ edge_type,
                            const int* __restrict__ x,
                            const float* __restrict__ spatial_emb,
                            const float* __restrict__ edge_emb,
                            const float* __restrict__ virt_dist,
                            float* __restrict__ gb) {
    int idx = blockIdx.x * 256 + threadIdx.x;
    if (idx >= kS * kS) return;
    int b = blockIdx.y;
    int q = idx / kS, k = idx % kS;

    size_t obase = ((size_t)b * kH) * kS * kS + (size_t)q * kS + k;

    if (k >= 1 && x[(b * kN + (k - 1)) * kNF] == 0) {
#pragma unroll
        for (int hh = 0; hh < kH; hh++)
            gb[obase + (size_t)hh * kS * kS] = -1e30f;
        return;
    }

    float base = attn_bias[(size_t)b * kS * kS + idx];
    float vals[kH];
#pragma unroll
    for (int hh = 0; hh < kH; hh++) vals[hh] = base;

    if (q >= 1 && k >= 1) {
        size_t e = (size_t)b * kN * kN + (size_t)(q - 1) * kN + (k - 1);
        int sp = iclamp(spatial_pos[e], 0, kNS - 1);
        const int* et = edge_type + e * kNEF;
        int t0 = iclamp(et[0], 0, kNE);
        int t1 = iclamp(et[1], 0, kNE);
        int t2 = iclamp(et[2], 0, kNE);
        const float* sr = spatial_emb + (size_t)sp * kH;
        const float* r0 = edge_emb + (size_t)t0 * kH;
        const float* r1 = edge_emb + (size_t)t1 * kH;
        const float* r2 = edge_emb + (size_t)t2 * kH;
#pragma unroll
        for (int hh = 0; hh < kH; hh++)
            vals[hh] += sr[hh] + (r0[hh] + r1[hh] + r2[hh]) * (1.0f / 3.0f);
    }
    if (q == 0 || k == 0) {
#pragma unroll
        for (int hh = 0; hh < kH; hh++) vals[hh] += virt_dist[hh];
    }
#pragma unroll
    for (int hh = 0; hh < kH; hh++)
        gb[obase + (size_t)hh * kS * kS] = vals[hh];
}

// ---------------------------------------------------------------------------
// LayerNorm
// ---------------------------------------------------------------------------
__global__ void ln_kernel(const float* __restrict__ in,
                          const float* __restrict__ g,
                          const float* __restrict__ bt,
                          float* __restrict__ out) {
    int tok = blockIdx.x;
    int tid = threadIdx.x;
    const float* xr = in + (size_t)tok * kD;
    __shared__ float red[256];
    float x0 = xr[tid], x1 = xr[tid + 256], x2 = xr[tid + 512];
    red[tid] = x0 + x1 + x2;
    __syncthreads();
    for (int off = 128; off; off >>= 1) {
        if (tid < off) red[tid] += red[tid + off];
        __syncthreads();
    }
    float mean = red[0] * (1.0f / kD);
    __syncthreads();
    float d0 = x0 - mean, d1 = x1 - mean, d2 = x2 - mean;
    red[tid] = d0 * d0 + d1 * d1 + d2 * d2;
    __syncthreads();
    for (int off = 128; off; off >>= 1) {
        if (tid < off) red[tid] += red[tid + off];
        __syncthreads();
    }
    float inv = rsqrtf(red[0] * (1.0f / kD) + kEPS);
    float* orow = out + (size_t)tok * kD;
    orow[tid]       = d0 * inv * g[tid]       + bt[tid];
    orow[tid + 256] = d1 * inv * g[tid + 256] + bt[tid + 256];
    orow[tid + 512] = d2 * inv * g[tid + 512] + bt[tid + 512];
}

__global__ void final_ln_kernel(const float* __restrict__ in,
                                const float* __restrict__ g,
                                const float* __restrict__ bt,
                                float* __restrict__ out) {
    int tok = blockIdx.x;
    int b = tok / kS, s = tok % kS;
    int tid = threadIdx.x;
    const float* xr = in + (size_t)tok * kD;
    __shared__ float red[256];
    float x0 = xr[tid], x1 = xr[tid + 256], x2 = xr[tid + 512];
    red[tid] = x0 + x1 + x2;
    __syncthreads();
    for (int off = 128; off; off >>= 1) {
        if (tid < off) red[tid] += red[tid + off];
        __syncthreads();
    }
    float mean = red[0] * (1.0f / kD);
    __syncthreads();
    float d0 = x0 - mean, d1 = x1 - mean, d2 = x2 - mean;
    red[tid] = d0 * d0 + d1 * d1 + d2 * d2;
    __syncthreads();
    for (int off = 128; off; off >>= 1) {
        if (tid < off) red[tid] += red[tid + off];
        __syncthreads();
    }
    float inv = rsqrtf(red[0] * (1.0f / kD) + kEPS);
    float* orow = (s == 0)
        ? out + (size_t)kB * kN * kD + (size_t)b * kD
        : out + ((size_t)b * kN + (s - 1)) * kD;
    orow[tid]       = d0 * inv * g[tid]       + bt[tid];
    orow[tid + 256] = d1 * inv * g[tid + 256] + bt[tid + 256];
    orow[tid + 512] = d2 * inv * g[tid + 512] + bt[tid + 512];
}

// ---------------------------------------------------------------------------
// Host launcher
// ---------------------------------------------------------------------------
extern "C" void kernel_launch(void* const* d_in, const int* in_sizes, int n_in,
                              void* d_out, int out_size) {
    (void)in_sizes; (void)n_in; (void)out_size;

    const int*   x              = (const int*)  d_in[0];
    const float* attn_bias      = (const float*)d_in[1];
    const int*   spatial_pos    = (const int*)  d_in[2];
    const int*   attn_edge_type = (const int*)  d_in[3];
    const int*   in_degree      = (const int*)  d_in[4];
    const int*   out_degree     = (const int*)  d_in[5];
    const float* atom_emb       = (const float*)d_in[6];
    const float* in_deg_emb     = (const float*)d_in[7];
    const float* out_deg_emb    = (const float*)d_in[8];
    const float* graph_token    = (const float*)d_in[9];
    const float* spatial_emb    = (const float*)d_in[10];
    const float* edge_emb       = (const float*)d_in[11];
    const float* virt_dist      = (const float*)d_in[12];
    const float* Wq             = (const float*)d_in[13];
    const float* Wk             = (const float*)d_in[14];
    const float* Wv             = (const float*)d_in[15];
    const float* Wo             = (const float*)d_in[16];
    const float* bq             = (const float*)d_in[17];
    const float* bk             = (const float*)d_in[18];
    const float* bv             = (const float*)d_in[19];
    const float* bo             = (const float*)d_in[20];
    const float* ln1_g          = (const float*)d_in[21];
    const float* ln1_b          = (const float*)d_in[22];
    const float* ln2_g          = (const float*)d_in[23];
    const float* ln2_b          = (const float*)d_in[24];
    const float* W1             = (const float*)d_in[25];
    const float* b1             = (const float*)d_in[26];
    const float* W2             = (const float*)d_in[27];
    const float* b2             = (const float*)d_in[28];
    const float* fin_g          = (const float*)d_in[29];
    const float* fin_b          = (const float*)d_in[30];
    float* out = (float*)d_out;

    float* base = nullptr;
    cudaGetSymbolAddress((void**)&base, g_scratch);
    uint16_t* cv = nullptr;
    cudaGetSymbolAddress((void**)&cv, g_cv);

    float* h  = base + OFF_H;
    float* z  = base + OFF_Z;
    float* q  = base + OFF_Q;
    float* k  = base + OFF_K;
    float* v  = base + OFF_V;
    float* o  = base + OFF_O;
    float* gb = base + OFF_GB;
    float* f  = base + OFF_F;

    const uint16_t* aHi = cv + CV_A;
    const uint16_t* aLo = cv + CV_A + ACT_PLANE;

    cudaFuncSetAttribute(gemm_tc, cudaFuncAttributeMaxDynamicSharedMemorySize,
                         GT_SMEM);
    cudaFuncSetAttribute(attn_fused,
                         cudaFuncAttributeMaxDynamicSharedMemorySize, AT_SMEM);

    // weight conversions (once per launch; graph-captured, deterministic)
    cvt_split<<<4096, 256>>>((const float4*)Wq, (uint2*)(cv + CV_WQ),
                             (uint2*)(cv + CV_WQ + W_DD), (int)(W_DD / 4));
    cvt_split<<<4096, 256>>>((const float4*)Wk, (uint2*)(cv + CV_WK),
                             (uint2*)(cv + CV_WK + W_DD), (int)(W_DD / 4));
    cvt_split<<<4096, 256>>>((const float4*)Wv, (uint2*)(cv + CV_WV),
                             (uint2*)(cv + CV_WV + W_DD), (int)(W_DD / 4));
    cvt_split<<<4096, 256>>>((const float4*)Wo, (uint2*)(cv + CV_WO),
                             (uint2*)(cv + CV_WO + W_DD), (int)(W_DD / 4));
    cvt_split<<<4096, 256>>>((const float4*)W1, (uint2*)(cv + CV_W1),
                             (uint2*)(cv + CV_W1 + W_FD), (int)(W_FD / 4));
    cvt_split<<<4096, 256>>>((const float4*)W2, (uint2*)(cv + CV_W2),
                             (uint2*)(cv + CV_W2 + W_FD), (int)(W_FD / 4));

    embed_kernel<<<kBS, 256>>>(x, in_degree, out_degree, atom_emb, in_deg_emb,
                               out_deg_emb, graph_token, h);
    bias_kernel<<<dim3((kS * kS + 255) / 256, kB), 256>>>(
        attn_bias, spatial_pos, attn_edge_type, x, spatial_emb, edge_emb,
        virt_dist, gb);

    const int mtiles = (kBS + 127) / 128;            // 65
    dim3 gemmD(kD / 128, mtiles);                    // (6, 65)
    dim3 gemmF(kFF / 128, mtiles);                   // (24, 65)
    dim3 attnG((kS + 63) / 64, kB * kH);             // (5, 384)

    for (int l = 0; l < kL; l++) {
        const size_t odd = (size_t)l * kD * kD;      // per-layer elem offsets
        const size_t ofd = (size_t)l * kFF * kD;

        ln_kernel<<<kBS, 256>>>(h, ln1_g + l * kD, ln1_b + l * kD, z);
        cvt_split<<<4096, 256>>>((const float4*)z, (uint2*)(cv + CV_A),
                                 (uint2*)(cv + CV_A + ACT_PLANE),
                                 (int)(SZ_TOK / 4));

        gemm_tc<<<gemmD, 256, GT_SMEM>>>(aHi, aLo, cv + CV_WQ + odd,
                                         cv + CV_WQ + W_DD + odd,
                                         bq + l * kD, q, kBS, kD, kD, EPI_SCALE);
        gemm_tc<<<gemmD, 256, GT_SMEM>>>(aHi, aLo, cv + CV_WK + odd,
                                         cv + CV_WK + W_DD + odd,
                                         bk + l * kD, k, kBS, kD, kD, EPI_NONE);
        gemm_tc<<<gemmD, 256, GT_SMEM>>>(aHi, aLo, cv + CV_WV + odd,
                                         cv + CV_WV + W_DD + odd,
                                         bv + l * kD, v, kBS, kD, kD, EPI_NONE);

        attn_fused<<<attnG, 256, AT_SMEM>>>(q, k, v, gb, o);

        cvt_split<<<4096, 256>>>((const float4*)o, (uint2*)(cv + CV_A),
                                 (uint2*)(cv + CV_A + ACT_PLANE),
                                 (int)(SZ_TOK / 4));
        gemm_tc<<<gemmD, 256, GT_SMEM>>>(aHi, aLo, cv + CV_WO + odd,
                                         cv + CV_WO + W_DD + odd,
                                         bo + l * kD, h, kBS, kD, kD, EPI_RES);

        ln_kernel<<<kBS, 256>>>(h, ln2_g + l * kD, ln2_b + l * kD, z);
        cvt_split<<<4096, 256>>>((const float4*)z, (uint2*)(cv + CV_A),
                                 (uint2*)(cv + CV_A + ACT_PLANE),
                                 (int)(SZ_TOK / 4));
        gemm_tc<<<gemmF, 256, GT_SMEM>>>(aHi, aLo, cv + CV_W1 + ofd,
                                         cv + CV_W1 + W_FD + ofd,
                                         b1 + l * kFF, f, kBS, kFF, kD,
                                         EPI_GELU);
        cvt_split<<<4096, 256>>>((const float4*)f, (uint2*)(cv + CV_A),
                                 (uint2*)(cv + CV_A + ACT_PLANE),
                                 (int)(SZ_FF / 4));
        gemm_tc<<<gemmD, 256, GT_SMEM>>>(aHi, aLo, cv + CV_W2 + ofd,
                                         cv + CV_W2 + W_FD + ofd,
                                         b2 + l * kD, h, kBS, kD, kFF, EPI_RES);
    }

    final_ln_kernel<<<kBS, 256>>>(h, fin_g, fin_b, out);
}

// round 15
// speedup vs baseline: 2.7562x; 1.1080x over previous
#include <cuda_runtime.h>
#include <math.h>
#include <stdint.h>

// ---------------------------------------------------------------------------
// Problem constants
// ---------------------------------------------------------------------------
namespace {
constexpr int kB   = 32;
constexpr int kN   = 256;
constexpr int kNF  = 3;
constexpr int kNEF = 3;
constexpr int kD   = 768;
constexpr int kFF  = 3072;
constexpr int kH   = 12;
constexpr int kL   = 6;
constexpr int kNA  = 512;
constexpr int kND  = 512;
constexpr int kNE  = 512;
constexpr int kNS  = 512;
constexpr int kS   = 257;          // N + 1
constexpr int kHD  = 64;           // D / H
constexpr int kBS  = kB * kS;      // 8224 tokens
constexpr float kSCALE = 0.125f;   // HD^-0.5
constexpr float kEPS   = 1e-5f;

constexpr size_t SZ_TOK = (size_t)kBS * kD;            // 6,316,032
constexpr size_t SZ_ATT = (size_t)kB * kH * kS * kS;   // 25,365,504
constexpr size_t OFF_H  = 0;
constexpr size_t OFF_Q  = OFF_H  + SZ_TOK;
constexpr size_t OFF_K  = OFF_Q  + SZ_TOK;
constexpr size_t OFF_V  = OFF_K  + SZ_TOK;
constexpr size_t OFF_GB = OFF_V  + SZ_TOK;
constexpr size_t SCRATCH_ELEMS = OFF_GB + SZ_ATT;

// bf16 hi/lo conversion buffers (uint16 elements)
constexpr size_t W_DD   = (size_t)kL * kD * kD;        // 3,538,944
constexpr size_t W_FD   = (size_t)kL * kFF * kD;       // 14,155,776
constexpr size_t CV_WQ  = 0;
constexpr size_t CV_WK  = CV_WQ + 2 * W_DD;
constexpr size_t CV_WV  = CV_WK + 2 * W_DD;
constexpr size_t CV_WO  = CV_WV + 2 * W_DD;
constexpr size_t CV_W1  = CV_WO + 2 * W_DD;
constexpr size_t CV_W2  = CV_W1 + 2 * W_FD;
constexpr size_t CV_A   = CV_W2 + 2 * W_FD;
// activation plane: 8320 padded rows x kFF (covers both 768- and 3072-stride views)
constexpr size_t ACT_PLANE = (size_t)8320 * kFF;       // 25,559,040
constexpr size_t CV_TOTAL  = CV_A + 2 * ACT_PLANE;
}  // namespace

__device__ float    g_scratch[SCRATCH_ELEMS];
__device__ uint16_t g_cv[CV_TOTAL];          // BSS zero — pad rows stay 0
__device__ uint16_t g_f[2 * ACT_PLANE];      // FFN intermediate planes (disjoint!)

__device__ __forceinline__ int iclamp(int v, int lo, int hi) {
    return min(max(v, lo), hi);
}

__device__ __forceinline__ uint32_t smem_u32(const void* p) {
    uint32_t a;
    asm("{ .reg .u64 t; cvta.to.shared.u64 t, %1; cvt.u32.u64 %0, t; }"
        : "=r"(a) : "l"(p));
    return a;
}

// ---------------------------------------------------------------------------
// bf16 split helpers
// ---------------------------------------------------------------------------
__device__ __forceinline__ uint32_t pk_bf2(float lo_f, float hi_f) {
    uint32_t r;
    asm("cvt.rn.bf16x2.f32 %0, %1, %2;" : "=r"(r) : "f"(hi_f), "f"(lo_f));
    return r;
}
// split two floats -> {hi pair, lo pair} (first arg in low half)
__device__ __forceinline__ uint2 sp2(float a, float b) {
    uint32_t h = pk_bf2(a, b);
    float ha = __uint_as_float(h << 16);
    float hb = __uint_as_float(h & 0xffff0000u);
    uint32_t l = pk_bf2(a - ha, b - hb);
    return make_uint2(h, l);
}

// fp32 [n] -> hi bf16 plane, lo bf16 plane (weights only; once per launch)
__global__ void cvt_split(const float4* __restrict__ in,
                          uint2* __restrict__ hi, uint2* __restrict__ lo,
                          int n4) {
    for (int i = blockIdx.x * 256 + threadIdx.x; i < n4; i += gridDim.x * 256) {
        float4 v = in[i];
        uint2 s0 = sp2(v.x, v.y);
        uint2 s1 = sp2(v.z, v.w);
        hi[i] = make_uint2(s0.x, s1.x);
        lo[i] = make_uint2(s0.y, s1.y);
    }
}

// ---------------------------------------------------------------------------
// cp.async helpers
// ---------------------------------------------------------------------------
__device__ __forceinline__ void cpa16(uint32_t dst, const void* src) {
    asm volatile("cp.async.cg.shared.global [%0], [%1], 16;"
                 :: "r"(dst), "l"(src) : "memory");
}
__device__ __forceinline__ void cpa_commit() {
    asm volatile("cp.async.commit_group;" ::: "memory");
}

#define LDM4(r0, r1, r2, r3, ad)                                              \
    asm volatile(                                                             \
        "ldmatrix.sync.aligned.m8n8.x4.shared.b16 {%0,%1,%2,%3}, [%4];"       \
        : "=r"(r0), "=r"(r1), "=r"(r2), "=r"(r3) : "r"(ad))

#define MMA_BF16(c, a, b0r, b1r)                                              \
    asm volatile(                                                             \
        "mma.sync.aligned.m16n8k16.row.col.f32.bf16.bf16.f32 "                \
        "{%0,%1,%2,%3}, {%4,%5,%6,%7}, {%8,%9}, {%0,%1,%2,%3};"               \
        : "+f"((c)[0]), "+f"((c)[1]), "+f"((c)[2]), "+f"((c)[3])              \
        : "r"((a)[0]), "r"((a)[1]), "r"((a)[2]), "r"((a)[3]),                 \
          "r"(b0r), "r"(b1r))

// ---------------------------------------------------------------------------
// GEMM (bf16 2-term split, 3 MMA passes, fp32 acc), pre-converted operands.
// C[M,N] = epi(A @ W^T + bias).  BM=BN=128, BK=32, 256 threads, 2 CTAs/SM.
// 3-stage cp.async pipeline; stage = Ahi[8K] Alo[8K] Bhi[8K] Blo[8K].
// EPI_GELU writes split bf16 planes (CHi/CLo) instead of fp32 C.
// ---------------------------------------------------------------------------
enum { EPI_NONE = 0, EPI_SCALE = 1, EPI_GELU = 2, EPI_RES = 3 };

namespace {
constexpr uint32_t STAGE = 32768;
constexpr uint32_t GT_SMEM = 3 * STAGE;  // 96KB -> 2 CTAs/SM = 192KB
}

__device__ __forceinline__ void issue_stage(uint32_t st,
                                            const uint16_t* __restrict__ Ahi,
                                            const uint16_t* __restrict__ Alo,
                                            const uint16_t* __restrict__ Whi,
                                            const uint16_t* __restrict__ Wlo,
                                            int K, int bm, int bn, int kc,
                                            int tid) {
#pragma unroll
    for (int it = 0; it < 2; it++) {
        int p = tid + it * 256;
        int row = p >> 2;
        uint32_t u = (uint32_t)(p & 3);
        uint32_t dst = st + (uint32_t)row * 64 +
                       ((u ^ (((uint32_t)row >> 1) & 3)) << 4);
        size_t ao = (size_t)(bm + row) * K + kc + u * 8;
        size_t wo = (size_t)(bn + row) * K + kc + u * 8;
        cpa16(dst,          Ahi + ao);
        cpa16(dst + 8192,   Alo + ao);
        cpa16(dst + 16384,  Whi + wo);
        cpa16(dst + 24576,  Wlo + wo);
    }
    cpa_commit();
}

__global__ __launch_bounds__(256, 2)
void gemm_tc(const uint16_t* __restrict__ Ahi, const uint16_t* __restrict__ Alo,
             const uint16_t* __restrict__ Whi, const uint16_t* __restrict__ Wlo,
             const float* __restrict__ bias, float* __restrict__ C,
             uint16_t* __restrict__ CHi, uint16_t* __restrict__ CLo,
             int M, int N, int K, int epi) {
    extern __shared__ char sm[];
    const int tid = threadIdx.x;
    const int lane = tid & 31;
    const int wid = tid >> 5;
    const int bm = blockIdx.y * 128;
    const int bn = blockIdx.x * 128;
    const int wm = (wid & 1) * 64;
    const int wn = (wid >> 1) * 32;
    const uint32_t sbase = smem_u32(sm);
    const int nchunk = K >> 5;

    const int g = lane >> 3;
    const int r8 = lane & 7;
    const int aRow = wm + ((g & 1) << 3) + r8;
    const uint32_t aK1 = (uint32_t)(g >> 1);
    const int bRow = wn + ((g >> 1) << 3) + r8;
    const uint32_t bK1 = (uint32_t)(g & 1);
    const uint32_t swA = ((uint32_t)(aRow >> 1)) & 3;
    const uint32_t swB = ((uint32_t)(bRow >> 1)) & 3;

    float acc[4][4][4];
#pragma unroll
    for (int i = 0; i < 4; i++)
#pragma unroll
        for (int j = 0; j < 4; j++)
#pragma unroll
            for (int t = 0; t < 4; t++) acc[i][j][t] = 0.0f;

    issue_stage(sbase,         Ahi, Alo, Whi, Wlo, K, bm, bn, 0,  tid);
    issue_stage(sbase + STAGE, Ahi, Alo, Whi, Wlo, K, bm, bn, 32, tid);

    for (int c = 0; c < nchunk; c++) {
        if (c + 1 == nchunk)
            asm volatile("cp.async.wait_group 0;" ::: "memory");
        else
            asm volatile("cp.async.wait_group 1;" ::: "memory");
        __syncthreads();
        if (c + 2 < nchunk) {
            int s2 = (c + 2) % 3;
            issue_stage(sbase + (uint32_t)s2 * STAGE, Ahi, Alo, Whi, Wlo,
                        K, bm, bn, (c + 2) << 5, tid);
        }

        const uint32_t st = sbase + (uint32_t)(c % 3) * STAGE;
#pragma unroll
        for (int ks = 0; ks < 2; ks++) {
            const uint32_t kx = ks ? 2u : 0u;
            uint32_t a[4][4], bh[4][2], bl[4][2];
#pragma unroll
            for (int mf = 0; mf < 4; mf++) {
                uint32_t ad = st + (uint32_t)(aRow + mf * 16) * 64 +
                              (((kx | aK1) ^ swA) << 4);
                LDM4(a[mf][0], a[mf][1], a[mf][2], a[mf][3], ad);
            }
#pragma unroll
            for (int p = 0; p < 2; p++) {
                uint32_t ad = st + 16384u + (uint32_t)(bRow + p * 16) * 64 +
                              (((kx | bK1) ^ swB) << 4);
                uint32_t r0, r1, r2, r3;
                LDM4(r0, r1, r2, r3, ad);
                bh[p * 2][0] = r0; bh[p * 2][1] = r1;
                bh[p * 2 + 1][0] = r2; bh[p * 2 + 1][1] = r3;
            }
#pragma unroll
            for (int mf = 0; mf < 4; mf++)
#pragma unroll
                for (int nf = 0; nf < 4; nf++)
                    MMA_BF16(acc[mf][nf], a[mf], bh[nf][0], bh[nf][1]);
#pragma unroll
            for (int p = 0; p < 2; p++) {
                uint32_t ad = st + 24576u + (uint32_t)(bRow + p * 16) * 64 +
                              (((kx | bK1) ^ swB) << 4);
                uint32_t r0, r1, r2, r3;
                LDM4(r0, r1, r2, r3, ad);
                bl[p * 2][0] = r0; bl[p * 2][1] = r1;
                bl[p * 2 + 1][0] = r2; bl[p * 2 + 1][1] = r3;
            }
#pragma unroll
            for (int mf = 0; mf < 4; mf++)
#pragma unroll
                for (int nf = 0; nf < 4; nf++)
                    MMA_BF16(acc[mf][nf], a[mf], bl[nf][0], bl[nf][1]);
#pragma unroll
            for (int mf = 0; mf < 4; mf++) {
                uint32_t ad = st + 8192u + (uint32_t)(aRow + mf * 16) * 64 +
                              (((kx | aK1) ^ swA) << 4);
                LDM4(a[mf][0], a[mf][1], a[mf][2], a[mf][3], ad);
            }
#pragma unroll
            for (int mf = 0; mf < 4; mf++)
#pragma unroll
                for (int nf = 0; nf < 4; nf++)
                    MMA_BF16(acc[mf][nf], a[mf], bh[nf][0], bh[nf][1]);
        }
    }

    // epilogue
#pragma unroll
    for (int mf = 0; mf < 4; mf++) {
        const int r0 = bm + wm + mf * 16 + (lane >> 2);
#pragma unroll
        for (int nf = 0; nf < 4; nf++) {
            const int cc = bn + wn + nf * 8 + ((lane & 3) << 1);
            const float b0v = bias[cc];
            const float b1v = bias[cc + 1];
            float v0 = acc[mf][nf][0] + b0v;
            float v1 = acc[mf][nf][1] + b1v;
            float v2 = acc[mf][nf][2] + b0v;
            float v3 = acc[mf][nf][3] + b1v;
            if (epi == EPI_GELU) {
                v0 = 0.5f * v0 * (1.0f + erff(v0 * 0.70710678118654752f));
                v1 = 0.5f * v1 * (1.0f + erff(v1 * 0.70710678118654752f));
                v2 = 0.5f * v2 * (1.0f + erff(v2 * 0.70710678118654752f));
                v3 = 0.5f * v3 * (1.0f + erff(v3 * 0.70710678118654752f));
                if (r0 < M) {
                    uint2 s = sp2(v0, v1);
                    size_t o = (size_t)r0 * N + cc;
                    *(uint32_t*)(CHi + o) = s.x;
                    *(uint32_t*)(CLo + o) = s.y;
                }
                if (r0 + 8 < M) {
                    uint2 s = sp2(v2, v3);
                    size_t o = (size_t)(r0 + 8) * N + cc;
                    *(uint32_t*)(CHi + o) = s.x;
                    *(uint32_t*)(CLo + o) = s.y;
                }
                continue;
            }
            if (epi == EPI_SCALE) {
                v0 *= kSCALE; v1 *= kSCALE; v2 *= kSCALE; v3 *= kSCALE;
            }
            if (r0 < M) {
                float* cp = C + (size_t)r0 * N + cc;
                if (epi == EPI_RES) {
                    float2 old = *(float2*)cp;
                    v0 += old.x; v1 += old.y;
                }
                *(float2*)cp = make_float2(v0, v1);
            }
            if (r0 + 8 < M) {
                float* cp = C + (size_t)(r0 + 8) * N + cc;
                if (epi == EPI_RES) {
                    float2 old = *(float2*)cp;
                    v2 += old.x; v3 += old.y;
                }
                *(float2*)cp = make_float2(v2, v3);
            }
        }
    }
}

// ---------------------------------------------------------------------------
// Fused attention (fp32): per (b,h,q-tile=64) block. Writes o as split planes.
// ---------------------------------------------------------------------------
namespace {
constexpr int AT_KT = 0;        // 4608 floats
constexpr int AT_QS = 4608;     // 4352 floats
constexpr int AT_PS = 8960;     // 16896 floats
constexpr uint32_t AT_SMEM = (8960 + 16896) * 4;  // 103,424 B
}

__global__ __launch_bounds__(256)
void attn_fused(const float* __restrict__ qm, const float* __restrict__ km,
                const float* __restrict__ vm, const float* __restrict__ gb,
                uint16_t* __restrict__ oHi, uint16_t* __restrict__ oLo) {
    extern __shared__ float s[];
    float* kT = s + AT_KT;   // [64][72]; later vs [64][68]
    float* qs = s + AT_QS;   // [64][68]
    float* ps = s + AT_PS;   // [64][264]
    const int tid = threadIdx.x;
    const int lane = tid & 31;
    const int wid = tid >> 5;
    const int bh = blockIdx.y;
    const int b = bh / kH, hh = bh % kH;
    const int q0 = blockIdx.x * 64;

    // ---- load Q tile ----
#pragma unroll
    for (int it = 0; it < 4; it++) {
        int p = tid + it * 256;
        int r = p >> 4;
        int u = p & 15;
        int gq = q0 + r;
        float4 v4 = make_float4(0.f, 0.f, 0.f, 0.f);
        if (gq < kS)
            v4 = *(const float4*)(qm + ((size_t)(b * kS + gq)) * kD +
                                  hh * kHD + u * 4);
        *(float4*)&qs[r * 68 + u * 4] = v4;
    }

    const int qg = tid >> 3;
    const int kg = tid & 7;
    const int q1 = qg * 2;

    // ---- phase 1: scores ----
    for (int koff = 0; koff < kS; koff += 64) {
        {
            int t = tid & 63;
            int db = (tid >> 6) * 16;
            int gk = koff + t;
#pragma unroll
            for (int m = 0; m < 4; m++) {
                float4 v4 = make_float4(0.f, 0.f, 0.f, 0.f);
                if (gk < kS)
                    v4 = *(const float4*)(km + ((size_t)(b * kS + gk)) * kD +
                                          hh * kHD + db + m * 4);
                kT[(db + m * 4 + 0) * 72 + t] = v4.x;
                kT[(db + m * 4 + 1) * 72 + t] = v4.y;
                kT[(db + m * 4 + 2) * 72 + t] = v4.z;
                kT[(db + m * 4 + 3) * 72 + t] = v4.w;
            }
        }
        __syncthreads();

        float a0[8], a1[8];
#pragma unroll
        for (int j = 0; j < 8; j++) { a0[j] = 0.f; a1[j] = 0.f; }
#pragma unroll 16
        for (int d = 0; d < 64; d++) {
            float qv0 = qs[q1 * 68 + d];
            float qv1 = qs[(q1 + 1) * 68 + d];
            float4 ka = *(float4*)&kT[d * 72 + kg * 8];
            float4 kb = *(float4*)&kT[d * 72 + kg * 8 + 4];
            a0[0] += qv0 * ka.x; a0[1] += qv0 * ka.y;
            a0[2] += qv0 * ka.z; a0[3] += qv0 * ka.w;
            a0[4] += qv0 * kb.x; a0[5] += qv0 * kb.y;
            a0[6] += qv0 * kb.z; a0[7] += qv0 * kb.w;
            a1[0] += qv1 * ka.x; a1[1] += qv1 * ka.y;
            a1[2] += qv1 * ka.z; a1[3] += qv1 * ka.w;
            a1[4] += qv1 * kb.x; a1[5] += qv1 * kb.y;
            a1[6] += qv1 * kb.z; a1[7] += qv1 * kb.w;
        }
        {
            int gq = q0 + q1;
            const size_t gr0 = ((size_t)bh * kS + gq) * kS;
            const size_t gr1 = gr0 + kS;
            bool v0 = (gq < kS), v1 = (gq + 1 < kS);
#pragma unroll
            for (int j = 0; j < 8; j++) {
                int gk = koff + kg * 8 + j;
                if (gk < kS) {
                    ps[q1 * 264 + gk] = v0 ? (a0[j] + gb[gr0 + gk]) : 0.0f;
                    ps[(q1 + 1) * 264 + gk] = v1 ? (a1[j] + gb[gr1 + gk]) : 0.0f;
                }
            }
        }
        __syncthreads();
    }

    // ---- phase 2: softmax ----
    for (int rr = 0; rr < 8; rr++) {
        int r = wid * 8 + rr;
        float m = -3.4e38f;
        for (int kk = lane; kk < kS; kk += 32)
            m = fmaxf(m, ps[r * 264 + kk]);
#pragma unroll
        for (int o2 = 16; o2; o2 >>= 1)
            m = fmaxf(m, __shfl_xor_sync(0xffffffffu, m, o2));
        float sum = 0.0f;
        for (int kk = lane; kk < kS; kk += 32) {
            float e = expf(ps[r * 264 + kk] - m);
            ps[r * 264 + kk] = e;
            sum += e;
        }
#pragma unroll
        for (int o2 = 16; o2; o2 >>= 1)
            sum += __shfl_xor_sync(0xffffffffu, sum, o2);
        float inv = 1.0f / sum;
        for (int kk = lane; kk < kS; kk += 32)
            ps[r * 264 + kk] *= inv;
    }
    __syncthreads();

    // ---- phase 3: P @ V ----
    float* vs = s + AT_KT;
    const int dg = tid & 7;
    const int d8 = dg * 8;
    float o0[8], o1[8];
#pragma unroll
    for (int j = 0; j < 8; j++) { o0[j] = 0.f; o1[j] = 0.f; }

    for (int koff = 0; koff < kS; koff += 64) {
        {
#pragma unroll
            for (int it = 0; it < 4; it++) {
                int p = tid + it * 256;
                int t = p >> 4;
                int u = p & 15;
                int gk = koff + t;
                float4 v4 = make_float4(0.f, 0.f, 0.f, 0.f);
                if (gk < kS)
                    v4 = *(const float4*)(vm + ((size_t)(b * kS + gk)) * kD +
                                          hh * kHD + u * 4);
                *(float4*)&vs[t * 68 + u * 4] = v4;
            }
        }
        __syncthreads();
        int klim = min(64, kS - koff);
#pragma unroll 8
        for (int kl = 0; kl < klim; kl++) {
            float p0 = ps[q1 * 264 + koff + kl];
            float p1 = ps[(q1 + 1) * 264 + koff + kl];
            float4 va = *(float4*)&vs[kl * 68 + d8];
            float4 vb = *(float4*)&vs[kl * 68 + d8 + 4];
            o0[0] += p0 * va.x; o0[1] += p0 * va.y;
            o0[2] += p0 * va.z; o0[3] += p0 * va.w;
            o0[4] += p0 * vb.x; o0[5] += p0 * vb.y;
            o0[6] += p0 * vb.z; o0[7] += p0 * vb.w;
            o1[0] += p1 * va.x; o1[1] += p1 * va.y;
            o1[2] += p1 * va.z; o1[3] += p1 * va.w;
            o1[4] += p1 * vb.x; o1[5] += p1 * vb.y;
            o1[6] += p1 * vb.z; o1[7] += p1 * vb.w;
        }
        __syncthreads();
    }

    // write o as split bf16 planes
    {
        int gq = q0 + q1;
        if (gq < kS) {
            size_t off = ((size_t)(b * kS + gq)) * kD + hh * kHD + d8;
            uint2 s0 = sp2(o0[0], o0[1]);
            uint2 s1 = sp2(o0[2], o0[3]);
            uint2 s2 = sp2(o0[4], o0[5]);
            uint2 s3 = sp2(o0[6], o0[7]);
            *(uint4*)(oHi + off) = make_uint4(s0.x, s1.x, s2.x, s3.x);
            *(uint4*)(oLo + off) = make_uint4(s0.y, s1.y, s2.y, s3.y);
        }
        if (gq + 1 < kS) {
            size_t off = ((size_t)(b * kS + gq + 1)) * kD + hh * kHD + d8;
            uint2 s0 = sp2(o1[0], o1[1]);
            uint2 s1 = sp2(o1[2], o1[3]);
            uint2 s2 = sp2(o1[4], o1[5]);
            uint2 s3 = sp2(o1[6], o1[7]);
            *(uint4*)(oHi + off) = make_uint4(s0.x, s1.x, s2.x, s3.x);
            *(uint4*)(oLo + off) = make_uint4(s0.y, s1.y, s2.y, s3.y);
        }
    }
}

// ---------------------------------------------------------------------------
// Embedding
// ---------------------------------------------------------------------------
__global__ void embed_kernel(const int* __restrict__ x,
                             const int* __restrict__ in_deg,
                             const int* __restrict__ out_deg,
                             const float* __restrict__ atom_emb,
                             const float* __restrict__ in_deg_emb,
                             const float* __restrict__ out_deg_emb,
                             const float* __restrict__ graph_token,
                             float* __restrict__ h) {
    int tok = blockIdx.x;
    int b = tok / kS, s = tok % kS;
    float* out = h + (size_t)tok * kD;
    if (s == 0) {
        for (int d = threadIdx.x; d < kD; d += 256) out[d] = graph_token[d];
        return;
    }
    int n = s - 1;
    const int* xr = x + (b * kN + n) * kNF;
    int a0 = iclamp(xr[0], 0, kNA);
    int a1 = iclamp(xr[1], 0, kNA);
    int a2 = iclamp(xr[2], 0, kNA);
    int di = iclamp(in_deg[b * kN + n], 0, kND - 1);
    int dq = iclamp(out_deg[b * kN + n], 0, kND - 1);
    const float* e0 = atom_emb + (size_t)a0 * kD;
    const float* e1 = atom_emb + (size_t)a1 * kD;
    const float* e2 = atom_emb + (size_t)a2 * kD;
    const float* ei = in_deg_emb + (size_t)di * kD;
    const float* eo = out_deg_emb + (size_t)dq * kD;
    for (int d = threadIdx.x; d < kD; d += 256)
        out[d] = e0[d] + e1[d] + e2[d] + ei[d] + eo[d];
}

// ---------------------------------------------------------------------------
// Graph bias gb[b,h,q,k] (mask baked in)
// ---------------------------------------------------------------------------
__global__ void bias_kernel(const float* __restrict__ attn_bias,
                            const int* __restrict__ spatial_pos,
                            const int* __restrict__ edge_type,
                            const int* __restrict__ x,
                            const float* __restrict__ spatial_emb,
                            const float* __restrict__ edge_emb,
                            const float* __restrict__ virt_dist,
                            float* __restrict__ gb) {
    int idx = blockIdx.x * 256 + threadIdx.x;
    if (idx >= kS * kS) return;
    int b = blockIdx.y;
    int q = idx / kS, k = idx % kS;

    size_t obase = ((size_t)b * kH) * kS * kS + (size_t)q * kS + k;

    if (k >= 1 && x[(b * kN + (k - 1)) * kNF] == 0) {
#pragma unroll
        for (int hh = 0; hh < kH; hh++)
            gb[obase + (size_t)hh * kS * kS] = -1e30f;
        return;
    }

    float base = attn_bias[(size_t)b * kS * kS + idx];
    float vals[kH];
#pragma unroll
    for (int hh = 0; hh < kH; hh++) vals[hh] = base;

    if (q >= 1 && k >= 1) {
        size_t e = (size_t)b * kN * kN + (size_t)(q - 1) * kN + (k - 1);
        int sp = iclamp(spatial_pos[e], 0, kNS - 1);
        const int* et = edge_type + e * kNEF;
        int t0 = iclamp(et[0], 0, kNE);
        int t1 = iclamp(et[1], 0, kNE);
        int t2 = iclamp(et[2], 0, kNE);
        const float* sr = spatial_emb + (size_t)sp * kH;
        const float* r0 = edge_emb + (size_t)t0 * kH;
        const float* r1 = edge_emb + (size_t)t1 * kH;
        const float* r2 = edge_emb + (size_t)t2 * kH;
#pragma unroll
        for (int hh = 0; hh < kH; hh++)
            vals[hh] += sr[hh] + (r0[hh] + r1[hh] + r2[hh]) * (1.0f / 3.0f);
    }
    if (q == 0 || k == 0) {
#pragma unroll
        for (int hh = 0; hh < kH; hh++) vals[hh] += virt_dist[hh];
    }
#pragma unroll
    for (int hh = 0; hh < kH; hh++)
        gb[obase + (size_t)hh * kS * kS] = vals[hh];
}

// ---------------------------------------------------------------------------
// LayerNorm -> split bf16 planes (GEMM input)
// ---------------------------------------------------------------------------
__global__ void ln_split_kernel(const float* __restrict__ in,
                                const float* __restrict__ g,
                                const float* __restrict__ bt,
                                uint16_t* __restrict__ hiP,
                                uint16_t* __restrict__ loP) {
    int tok = blockIdx.x;
    int tid = threadIdx.x;
    const float* xr = in + (size_t)tok * kD;
    __shared__ float red[256];
    float x0 = xr[tid], x1 = xr[tid + 256], x2 = xr[tid + 512];
    red[tid] = x0 + x1 + x2;
    __syncthreads();
    for (int off = 128; off; off >>= 1) {
        if (tid < off) red[tid] += red[tid + off];
        __syncthreads();
    }
    float mean = red[0] * (1.0f / kD);
    __syncthreads();
    float d0 = x0 - mean, d1 = x1 - mean, d2 = x2 - mean;
    red[tid] = d0 * d0 + d1 * d1 + d2 * d2;
    __syncthreads();
    for (int off = 128; off; off >>= 1) {
        if (tid < off) red[tid] += red[tid + off];
        __syncthreads();
    }
    float inv = rsqrtf(red[0] * (1.0f / kD) + kEPS);
    float z0 = d0 * inv * g[tid]       + bt[tid];
    float z1 = d1 * inv * g[tid + 256] + bt[tid + 256];
    float z2 = d2 * inv * g[tid + 512] + bt[tid + 512];
    size_t base = (size_t)tok * kD;
    uint2 s;
    s = sp2(z0, z0); hiP[base + tid]       = (uint16_t)(s.x & 0xffff);
                     loP[base + tid]       = (uint16_t)(s.y & 0xffff);
    s = sp2(z1, z1); hiP[base + tid + 256] = (uint16_t)(s.x & 0xffff);
                     loP[base + tid + 256] = (uint16_t)(s.y & 0xffff);
    s = sp2(z2, z2); hiP[base + tid + 512] = (uint16_t)(s.x & 0xffff);
                     loP[base + tid + 512] = (uint16_t)(s.y & 0xffff);
}

__global__ void final_ln_kernel(const float* __restrict__ in,
                                const float* __restrict__ g,
                                const float* __restrict__ bt,
                                float* __restrict__ out) {
    int tok = blockIdx.x;
    int b = tok / kS, s = tok % kS;
    int tid = threadIdx.x;
    const float* xr = in + (size_t)tok * kD;
    __shared__ float red[256];
    float x0 = xr[tid], x1 = xr[tid + 256], x2 = xr[tid + 512];
    red[tid] = x0 + x1 + x2;
    __syncthreads();
    for (int off = 128; off; off >>= 1) {
        if (tid < off) red[tid] += red[tid + off];
        __syncthreads();
    }
    float mean = red[0] * (1.0f / kD);
    __syncthreads();
    float d0 = x0 - mean, d1 = x1 - mean, d2 = x2 - mean;
    red[tid] = d0 * d0 + d1 * d1 + d2 * d2;
    __syncthreads();
    for (int off = 128; off; off >>= 1) {
        if (tid < off) red[tid] += red[tid + off];
        __syncthreads();
    }
    float inv = rsqrtf(red[0] * (1.0f / kD) + kEPS);
    float* orow = (s == 0)
        ? out + (size_t)kB * kN * kD + (size_t)b * kD
        : out + ((size_t)b * kN + (s - 1)) * kD;
    orow[tid]       = d0 * inv * g[tid]       + bt[tid];
    orow[tid + 256] = d1 * inv * g[tid + 256] + bt[tid + 256];
    orow[tid + 512] = d2 * inv * g[tid + 512] + bt[tid + 512];
}

// ---------------------------------------------------------------------------
// Host launcher
// ---------------------------------------------------------------------------
extern "C" void kernel_launch(void* const* d_in, const int* in_sizes, int n_in,
                              void* d_out, int out_size) {
    (void)in_sizes; (void)n_in; (void)out_size;

    const int*   x              = (const int*)  d_in[0];
    const float* attn_bias      = (const float*)d_in[1];
    const int*   spatial_pos    = (const int*)  d_in[2];
    const int*   attn_edge_type = (const int*)  d_in[3];
    const int*   in_degree      = (const int*)  d_in[4];
    const int*   out_degree     = (const int*)  d_in[5];
    const float* atom_emb       = (const float*)d_in[6];
    const float* in_deg_emb     = (const float*)d_in[7];
    const float* out_deg_emb    = (const float*)d_in[8];
    const float* graph_token    = (const float*)d_in[9];
    const float* spatial_emb    = (const float*)d_in[10];
    const float* edge_emb       = (const float*)d_in[11];
    const float* virt_dist      = (const float*)d_in[12];
    const float* Wq             = (const float*)d_in[13];
    const float* Wk             = (const float*)d_in[14];
    const float* Wv             = (const float*)d_in[15];
    const float* Wo             = (const float*)d_in[16];
    const float* bq             = (const float*)d_in[17];
    const float* bk             = (const float*)d_in[18];
    const float* bv             = (const float*)d_in[19];
    const float* bo             = (const float*)d_in[20];
    const float* ln1_g          = (const float*)d_in[21];
    const float* ln1_b          = (const float*)d_in[22];
    const float* ln2_g          = (const float*)d_in[23];
    const float* ln2_b          = (const float*)d_in[24];
    const float* W1             = (const float*)d_in[25];
    const float* b1             = (const float*)d_in[26];
    const float* W2             = (const float*)d_in[27];
    const float* b2             = (const float*)d_in[28];
    const float* fin_g          = (const float*)d_in[29];
    const float* fin_b          = (const float*)d_in[30];
    float* out = (float*)d_out;

    float* base = nullptr;
    cudaGetSymbolAddress((void**)&base, g_scratch);
    uint16_t* cv = nullptr;
    cudaGetSymbolAddress((void**)&cv, g_cv);
    uint16_t* fpl = nullptr;
    cudaGetSymbolAddress((void**)&fpl, g_f);

    float* h  = base + OFF_H;
    float* q  = base + OFF_Q;
    float* k  = base + OFF_K;
    float* v  = base + OFF_V;
    float* gb = base + OFF_GB;

    uint16_t* aHi = cv + CV_A;
    uint16_t* aLo = cv + CV_A + ACT_PLANE;
    uint16_t* fHi = fpl;
    uint16_t* fLo = fpl + ACT_PLANE;

    cudaFuncSetAttribute(gemm_tc, cudaFuncAttributeMaxDynamicSharedMemorySize,
                         GT_SMEM);
    cudaFuncSetAttribute(attn_fused,
                         cudaFuncAttributeMaxDynamicSharedMemorySize, AT_SMEM);

    // weight conversions (once per launch; deterministic)
    cvt_split<<<4096, 256>>>((const float4*)Wq, (uint2*)(cv + CV_WQ),
                             (uint2*)(cv + CV_WQ + W_DD), (int)(W_DD / 4));
    cvt_split<<<4096, 256>>>((const float4*)Wk, (uint2*)(cv + CV_WK),
                             (uint2*)(cv + CV_WK + W_DD), (int)(W_DD / 4));
    cvt_split<<<4096, 256>>>((const float4*)Wv, (uint2*)(cv + CV_WV),
                             (uint2*)(cv + CV_WV + W_DD), (int)(W_DD / 4));
    cvt_split<<<4096, 256>>>((const float4*)Wo, (uint2*)(cv + CV_WO),
                             (uint2*)(cv + CV_WO + W_DD), (int)(W_DD / 4));
    cvt_split<<<4096, 256>>>((const float4*)W1, (uint2*)(cv + CV_W1),
                             (uint2*)(cv + CV_W1 + W_FD), (int)(W_FD / 4));
    cvt_split<<<4096, 256>>>((const float4*)W2, (uint2*)(cv + CV_W2),
                             (uint2*)(cv + CV_W2 + W_FD), (int)(W_FD / 4));

    embed_kernel<<<kBS, 256>>>(x, in_degree, out_degree, atom_emb, in_deg_emb,
                               out_deg_emb, graph_token, h);
    bias_kernel<<<dim3((kS * kS + 255) / 256, kB), 256>>>(
        attn_bias, spatial_pos, attn_edge_type, x, spatial_emb, edge_emb,
        virt_dist, gb);

    const int mtiles = (kBS + 127) / 128;            // 65
    dim3 gemmD(kD / 128, mtiles);                    // (6, 65)
    dim3 gemmF(kFF / 128, mtiles);                   // (24, 65)
    dim3 attnG((kS + 63) / 64, kB * kH);             // (5, 384)

    for (int l = 0; l < kL; l++) {
        const size_t odd = (size_t)l * kD * kD;
        const size_t ofd = (size_t)l * kFF * kD;

        ln_split_kernel<<<kBS, 256>>>(h, ln1_g + l * kD, ln1_b + l * kD,
                                      aHi, aLo);

        gemm_tc<<<gemmD, 256, GT_SMEM>>>(aHi, aLo, cv + CV_WQ + odd,
                                         cv + CV_WQ + W_DD + odd,
                                         bq + l * kD, q, nullptr, nullptr,
                                         kBS, kD, kD, EPI_SCALE);
        gemm_tc<<<gemmD, 256, GT_SMEM>>>(aHi, aLo, cv + CV_WK + odd,
                                         cv + CV_WK + W_DD + odd,
                                         bk + l * kD, k, nullptr, nullptr,
                                         kBS, kD, kD, EPI_NONE);
        gemm_tc<<<gemmD, 256, GT_SMEM>>>(aHi, aLo, cv + CV_WV + odd,
                                         cv + CV_WV + W_DD + odd,
                                         bv + l * kD, v, nullptr, nullptr,
                                         kBS, kD, kD, EPI_NONE);

        // attention writes the next GEMM's A operand (z planes are dead now)
        attn_fused<<<attnG, 256, AT_SMEM>>>(q, k, v, gb, aHi, aLo);

        gemm_tc<<<gemmD, 256, GT_SMEM>>>(aHi, aLo, cv + CV_WO + odd,
                                         cv + CV_WO + W_DD + odd,
                                         bo + l * kD, h, nullptr, nullptr,
                                         kBS, kD, kD, EPI_RES);

        ln_split_kernel<<<kBS, 256>>>(h, ln2_g + l * kD, ln2_b + l * kD,
                                      aHi, aLo);
        // GELU output -> DEDICATED f planes (no overlap with A input)
        gemm_tc<<<gemmF, 256, GT_SMEM>>>(aHi, aLo, cv + CV_W1 + ofd,
                                         cv + CV_W1 + W_FD + ofd,
                                         b1 + l * kFF, nullptr, fHi, fLo,
                                         kBS, kFF, kD, EPI_GELU);
        gemm_tc<<<gemmD, 256, GT_SMEM>>>(fHi, fLo, cv + CV_W2 + ofd,
                                         cv + CV_W2 + W_FD + ofd,
                                         b2 + l * kD, h, nullptr, nullptr,
                                         kBS, kD, kFF, EPI_RES);
    }

    final_ln_kernel<<<kBS, 256>>>(h, fin_g, fin_b, out);
}

// round 16
// speedup vs baseline: 2.8088x; 1.0191x over previous
#include <cuda_runtime.h>
#include <math.h>
#include <stdint.h>

// ---------------------------------------------------------------------------
// Problem constants
// ---------------------------------------------------------------------------
namespace {
constexpr int kB   = 32;
constexpr int kN   = 256;
constexpr int kNF  = 3;
constexpr int kNEF = 3;
constexpr int kD   = 768;
constexpr int kFF  = 3072;
constexpr int kH   = 12;
constexpr int kL   = 6;
constexpr int kNA  = 512;
constexpr int kND  = 512;
constexpr int kNE  = 512;
constexpr int kNS  = 512;
constexpr int kS   = 257;          // N + 1
constexpr int kHD  = 64;           // D / H
constexpr int kBS  = kB * kS;      // 8224 tokens
constexpr int kQKV = 3 * kD;       // 2304
constexpr float kSCALE = 0.125f;   // HD^-0.5
constexpr float kEPS   = 1e-5f;

constexpr size_t SZ_TOK = (size_t)kBS * kD;            // 6,316,032
constexpr size_t SZ_ATT = (size_t)kB * kH * kS * kS;   // 25,365,504
constexpr size_t OFF_H   = 0;
constexpr size_t OFF_QKV = OFF_H + SZ_TOK;             // [kBS][2304] = 3*SZ_TOK
constexpr size_t OFF_GB  = OFF_QKV + 3 * SZ_TOK;
constexpr size_t SCRATCH_ELEMS = OFF_GB + SZ_ATT;

// bf16 hi/lo conversion buffers (uint16 elements)
constexpr size_t W_DD   = (size_t)kL * kD * kD;        // 3,538,944
constexpr size_t W_FD   = (size_t)kL * kFF * kD;       // 14,155,776
constexpr size_t W_QKV  = 3 * W_DD;                    // combined [l][2304][768]
constexpr size_t CV_WQKV = 0;                          // hi then lo, each W_QKV
constexpr size_t CV_WO  = CV_WQKV + 2 * W_QKV;
constexpr size_t CV_W1  = CV_WO + 2 * W_DD;
constexpr size_t CV_W2  = CV_W1 + 2 * W_FD;
constexpr size_t CV_A   = CV_W2 + 2 * W_FD;
// activation plane: 8320 padded rows x kFF (covers 768- and 3072-stride views)
constexpr size_t ACT_PLANE = (size_t)8320 * kFF;       // 25,559,040
constexpr size_t CV_TOTAL  = CV_A + 2 * ACT_PLANE;
}  // namespace

__device__ float    g_scratch[SCRATCH_ELEMS];
__device__ uint16_t g_cv[CV_TOTAL];          // BSS zero — pad rows stay 0
__device__ uint16_t g_f[2 * ACT_PLANE];      // FFN intermediate planes
__device__ float    g_bqkv[(size_t)kL * kQKV];  // concatenated qkv bias

__device__ __forceinline__ int iclamp(int v, int lo, int hi) {
    return min(max(v, lo), hi);
}

__device__ __forceinline__ uint32_t smem_u32(const void* p) {
    uint32_t a;
    asm("{ .reg .u64 t; cvta.to.shared.u64 t, %1; cvt.u32.u64 %0, t; }"
        : "=r"(a) : "l"(p));
    return a;
}

// ---------------------------------------------------------------------------
// bf16 split helpers
// ---------------------------------------------------------------------------
__device__ __forceinline__ uint32_t pk_bf2(float lo_f, float hi_f) {
    uint32_t r;
    asm("cvt.rn.bf16x2.f32 %0, %1, %2;" : "=r"(r) : "f"(hi_f), "f"(lo_f));
    return r;
}
// split two floats -> {hi pair, lo pair} (first arg in low half)
__device__ __forceinline__ uint2 sp2(float a, float b) {
    uint32_t h = pk_bf2(a, b);
    float ha = __uint_as_float(h << 16);
    float hb = __uint_as_float(h & 0xffff0000u);
    uint32_t l = pk_bf2(a - ha, b - hb);
    return make_uint2(h, l);
}

// fp32 [n] -> hi/lo planes (linear layout; used for Wo/W1/W2)
__global__ void cvt_split(const float4* __restrict__ in,
                          uint2* __restrict__ hi, uint2* __restrict__ lo,
                          int n4) {
    for (int i = blockIdx.x * 256 + threadIdx.x; i < n4; i += gridDim.x * 256) {
        float4 v = in[i];
        uint2 s0 = sp2(v.x, v.y);
        uint2 s1 = sp2(v.z, v.w);
        hi[i] = make_uint2(s0.x, s1.x);
        lo[i] = make_uint2(s0.y, s1.y);
    }
}

// Wq/Wk/Wv [l][768][768] -> combined plane [l][2304][768] at row block `part`
__global__ void cvt_split_qkv(const float4* __restrict__ in,
                              uint2* __restrict__ hi, uint2* __restrict__ lo,
                              int part, int n4) {
    constexpr int L4 = kD * kD / 4;       // float4s per layer
    for (int i = blockIdx.x * 256 + threadIdx.x; i < n4; i += gridDim.x * 256) {
        int l = i / L4;
        int r = i - l * L4;
        size_t d4 = (size_t)l * (3 * L4) + (size_t)part * L4 + r;
        float4 v = in[i];
        uint2 s0 = sp2(v.x, v.y);
        uint2 s1 = sp2(v.z, v.w);
        hi[d4] = make_uint2(s0.x, s1.x);
        lo[d4] = make_uint2(s0.y, s1.y);
    }
}

// concat bq/bk/bv -> g_bqkv[l][2304]
__global__ void bias_cat(const float* __restrict__ bq,
                         const float* __restrict__ bk,
                         const float* __restrict__ bv,
                         float* __restrict__ o) {
    int idx = blockIdx.x * 256 + threadIdx.x;
    if (idx >= kL * kQKV) return;
    int l = idx / kQKV, c = idx % kQKV;
    float v;
    if (c < kD)            v = bq[l * kD + c];
    else if (c < 2 * kD)   v = bk[l * kD + (c - kD)];
    else                   v = bv[l * kD + (c - 2 * kD)];
    o[idx] = v;
}

// ---------------------------------------------------------------------------
// cp.async helpers
// ---------------------------------------------------------------------------
__device__ __forceinline__ void cpa16(uint32_t dst, const void* src) {
    asm volatile("cp.async.cg.shared.global [%0], [%1], 16;"
                 :: "r"(dst), "l"(src) : "memory");
}
__device__ __forceinline__ void cpa_commit() {
    asm volatile("cp.async.commit_group;" ::: "memory");
}

#define LDM4(r0, r1, r2, r3, ad)                                              \
    asm volatile(                                                             \
        "ldmatrix.sync.aligned.m8n8.x4.shared.b16 {%0,%1,%2,%3}, [%4];"       \
        : "=r"(r0), "=r"(r1), "=r"(r2), "=r"(r3) : "r"(ad))

#define MMA_BF16(c, a, b0r, b1r)                                              \
    asm volatile(                                                             \
        "mma.sync.aligned.m16n8k16.row.col.f32.bf16.bf16.f32 "                \
        "{%0,%1,%2,%3}, {%4,%5,%6,%7}, {%8,%9}, {%0,%1,%2,%3};"               \
        : "+f"((c)[0]), "+f"((c)[1]), "+f"((c)[2]), "+f"((c)[3])              \
        : "r"((a)[0]), "r"((a)[1]), "r"((a)[2]), "r"((a)[3]),                 \
          "r"(b0r), "r"(b1r))

// ---------------------------------------------------------------------------
// GEMM (bf16 2-term split, 3 MMA passes, fp32 acc), pre-converted operands.
// C[M,N] = epi(A @ W^T + bias).  BM=BN=128, BK=32, 256 threads, 2 CTAs/SM.
// EPI_QKV: scale columns < 768 by kSCALE (fused QKV projection).
// EPI_GELU writes split bf16 planes (CHi/CLo).
// ---------------------------------------------------------------------------
enum { EPI_NONE = 0, EPI_QKV = 1, EPI_GELU = 2, EPI_RES = 3 };

namespace {
constexpr uint32_t STAGE = 32768;
constexpr uint32_t GT_SMEM = 3 * STAGE;  // 96KB -> 2 CTAs/SM
}

__device__ __forceinline__ void issue_stage(uint32_t st,
                                            const uint16_t* __restrict__ Ahi,
                                            const uint16_t* __restrict__ Alo,
                                            const uint16_t* __restrict__ Whi,
                                            const uint16_t* __restrict__ Wlo,
                                            int K, int bm, int bn, int kc,
                                            int tid) {
#pragma unroll
    for (int it = 0; it < 2; it++) {
        int p = tid + it * 256;
        int row = p >> 2;
        uint32_t u = (uint32_t)(p & 3);
        uint32_t dst = st + (uint32_t)row * 64 +
                       ((u ^ (((uint32_t)row >> 1) & 3)) << 4);
        size_t ao = (size_t)(bm + row) * K + kc + u * 8;
        size_t wo = (size_t)(bn + row) * K + kc + u * 8;
        cpa16(dst,          Ahi + ao);
        cpa16(dst + 8192,   Alo + ao);
        cpa16(dst + 16384,  Whi + wo);
        cpa16(dst + 24576,  Wlo + wo);
    }
    cpa_commit();
}

__global__ __launch_bounds__(256, 2)
void gemm_tc(const uint16_t* __restrict__ Ahi, const uint16_t* __restrict__ Alo,
             const uint16_t* __restrict__ Whi, const uint16_t* __restrict__ Wlo,
             const float* __restrict__ bias, float* __restrict__ C,
             uint16_t* __restrict__ CHi, uint16_t* __restrict__ CLo,
             int M, int N, int K, int epi) {
    extern __shared__ char sm[];
    const int tid = threadIdx.x;
    const int lane = tid & 31;
    const int wid = tid >> 5;
    const int bm = blockIdx.y * 128;
    const int bn = blockIdx.x * 128;
    const int wm = (wid & 1) * 64;
    const int wn = (wid >> 1) * 32;
    const uint32_t sbase = smem_u32(sm);
    const int nchunk = K >> 5;

    const int g = lane >> 3;
    const int r8 = lane & 7;
    const int aRow = wm + ((g & 1) << 3) + r8;
    const uint32_t aK1 = (uint32_t)(g >> 1);
    const int bRow = wn + ((g >> 1) << 3) + r8;
    const uint32_t bK1 = (uint32_t)(g & 1);
    const uint32_t swA = ((uint32_t)(aRow >> 1)) & 3;
    const uint32_t swB = ((uint32_t)(bRow >> 1)) & 3;

    float acc[4][4][4];
#pragma unroll
    for (int i = 0; i < 4; i++)
#pragma unroll
        for (int j = 0; j < 4; j++)
#pragma unroll
            for (int t = 0; t < 4; t++) acc[i][j][t] = 0.0f;

    issue_stage(sbase,         Ahi, Alo, Whi, Wlo, K, bm, bn, 0,  tid);
    issue_stage(sbase + STAGE, Ahi, Alo, Whi, Wlo, K, bm, bn, 32, tid);

    for (int c = 0; c < nchunk; c++) {
        if (c + 1 == nchunk)
            asm volatile("cp.async.wait_group 0;" ::: "memory");
        else
            asm volatile("cp.async.wait_group 1;" ::: "memory");
        __syncthreads();
        if (c + 2 < nchunk) {
            int s2 = (c + 2) % 3;
            issue_stage(sbase + (uint32_t)s2 * STAGE, Ahi, Alo, Whi, Wlo,
                        K, bm, bn, (c + 2) << 5, tid);
        }

        const uint32_t st = sbase + (uint32_t)(c % 3) * STAGE;
#pragma unroll
        for (int ks = 0; ks < 2; ks++) {
            const uint32_t kx = ks ? 2u : 0u;
            uint32_t a[4][4], bh[4][2], bl[4][2];
#pragma unroll
            for (int mf = 0; mf < 4; mf++) {
                uint32_t ad = st + (uint32_t)(aRow + mf * 16) * 64 +
                              (((kx | aK1) ^ swA) << 4);
                LDM4(a[mf][0], a[mf][1], a[mf][2], a[mf][3], ad);
            }
#pragma unroll
            for (int p = 0; p < 2; p++) {
                uint32_t ad = st + 16384u + (uint32_t)(bRow + p * 16) * 64 +
                              (((kx | bK1) ^ swB) << 4);
                uint32_t r0, r1, r2, r3;
                LDM4(r0, r1, r2, r3, ad);
                bh[p * 2][0] = r0; bh[p * 2][1] = r1;
                bh[p * 2 + 1][0] = r2; bh[p * 2 + 1][1] = r3;
            }
#pragma unroll
            for (int mf = 0; mf < 4; mf++)
#pragma unroll
                for (int nf = 0; nf < 4; nf++)
                    MMA_BF16(acc[mf][nf], a[mf], bh[nf][0], bh[nf][1]);
#pragma unroll
            for (int p = 0; p < 2; p++) {
                uint32_t ad = st + 24576u + (uint32_t)(bRow + p * 16) * 64 +
                              (((kx | bK1) ^ swB) << 4);
                uint32_t r0, r1, r2, r3;
                LDM4(r0, r1, r2, r3, ad);
                bl[p * 2][0] = r0; bl[p * 2][1] = r1;
                bl[p * 2 + 1][0] = r2; bl[p * 2 + 1][1] = r3;
            }
#pragma unroll
            for (int mf = 0; mf < 4; mf++)
#pragma unroll
                for (int nf = 0; nf < 4; nf++)
                    MMA_BF16(acc[mf][nf], a[mf], bl[nf][0], bl[nf][1]);
#pragma unroll
            for (int mf = 0; mf < 4; mf++) {
                uint32_t ad = st + 8192u + (uint32_t)(aRow + mf * 16) * 64 +
                              (((kx | aK1) ^ swA) << 4);
                LDM4(a[mf][0], a[mf][1], a[mf][2], a[mf][3], ad);
            }
#pragma unroll
            for (int mf = 0; mf < 4; mf++)
#pragma unroll
                for (int nf = 0; nf < 4; nf++)
                    MMA_BF16(acc[mf][nf], a[mf], bh[nf][0], bh[nf][1]);
        }
    }

    // epilogue
#pragma unroll
    for (int mf = 0; mf < 4; mf++) {
        const int r0 = bm + wm + mf * 16 + (lane >> 2);
#pragma unroll
        for (int nf = 0; nf < 4; nf++) {
            const int cc = bn + wn + nf * 8 + ((lane & 3) << 1);
            const float b0v = bias[cc];
            const float b1v = bias[cc + 1];
            float v0 = acc[mf][nf][0] + b0v;
            float v1 = acc[mf][nf][1] + b1v;
            float v2 = acc[mf][nf][2] + b0v;
            float v3 = acc[mf][nf][3] + b1v;
            if (epi == EPI_GELU) {
                v0 = 0.5f * v0 * (1.0f + erff(v0 * 0.70710678118654752f));
                v1 = 0.5f * v1 * (1.0f + erff(v1 * 0.70710678118654752f));
                v2 = 0.5f * v2 * (1.0f + erff(v2 * 0.70710678118654752f));
                v3 = 0.5f * v3 * (1.0f + erff(v3 * 0.70710678118654752f));
                if (r0 < M) {
                    uint2 s = sp2(v0, v1);
                    size_t o = (size_t)r0 * N + cc;
                    *(uint32_t*)(CHi + o) = s.x;
                    *(uint32_t*)(CLo + o) = s.y;
                }
                if (r0 + 8 < M) {
                    uint2 s = sp2(v2, v3);
                    size_t o = (size_t)(r0 + 8) * N + cc;
                    *(uint32_t*)(CHi + o) = s.x;
                    *(uint32_t*)(CLo + o) = s.y;
                }
                continue;
            }
            if (epi == EPI_QKV && cc < kD) {
                v0 *= kSCALE; v1 *= kSCALE; v2 *= kSCALE; v3 *= kSCALE;
            }
            if (r0 < M) {
                float* cp = C + (size_t)r0 * N + cc;
                if (epi == EPI_RES) {
                    float2 old = *(float2*)cp;
                    v0 += old.x; v1 += old.y;
                }
                *(float2*)cp = make_float2(v0, v1);
            }
            if (r0 + 8 < M) {
                float* cp = C + (size_t)(r0 + 8) * N + cc;
                if (epi == EPI_RES) {
                    float2 old = *(float2*)cp;
                    v2 += old.x; v3 += old.y;
                }
                *(float2*)cp = make_float2(v2, v3);
            }
        }
    }
}

// ---------------------------------------------------------------------------
// Fused attention (fp32): per (b,h,q-tile=64) block; reads combined qkv
// buffer [tok][2304] (q at +0, k at +768, v at +1536). Writes o split planes.
// ---------------------------------------------------------------------------
namespace {
constexpr int AT_KT = 0;        // 4608 floats
constexpr int AT_QS = 4608;     // 4352 floats
constexpr int AT_PS = 8960;     // 16896 floats
constexpr uint32_t AT_SMEM = (8960 + 16896) * 4;  // 103,424 B
}

__global__ __launch_bounds__(256)
void attn_fused(const float* __restrict__ qkv, const float* __restrict__ gb,
                uint16_t* __restrict__ oHi, uint16_t* __restrict__ oLo) {
    extern __shared__ float s[];
    float* kT = s + AT_KT;   // [64][72]; later vs [64][68]
    float* qs = s + AT_QS;   // [64][68]
    float* ps = s + AT_PS;   // [64][264]
    const int tid = threadIdx.x;
    const int lane = tid & 31;
    const int wid = tid >> 5;
    const int bh = blockIdx.y;
    const int b = bh / kH, hh = bh % kH;
    const int q0 = blockIdx.x * 64;

    // ---- load Q tile ----
#pragma unroll
    for (int it = 0; it < 4; it++) {
        int p = tid + it * 256;
        int r = p >> 4;
        int u = p & 15;
        int gq = q0 + r;
        float4 v4 = make_float4(0.f, 0.f, 0.f, 0.f);
        if (gq < kS)
            v4 = *(const float4*)(qkv + ((size_t)(b * kS + gq)) * kQKV +
                                  hh * kHD + u * 4);
        *(float4*)&qs[r * 68 + u * 4] = v4;
    }

    const int qg = tid >> 3;
    const int kg = tid & 7;
    const int q1 = qg * 2;

    // ---- phase 1: scores ----
    for (int koff = 0; koff < kS; koff += 64) {
        {
            int t = tid & 63;
            int db = (tid >> 6) * 16;
            int gk = koff + t;
#pragma unroll
            for (int m = 0; m < 4; m++) {
                float4 v4 = make_float4(0.f, 0.f, 0.f, 0.f);
                if (gk < kS)
                    v4 = *(const float4*)(qkv + ((size_t)(b * kS + gk)) * kQKV +
                                          kD + hh * kHD + db + m * 4);
                kT[(db + m * 4 + 0) * 72 + t] = v4.x;
                kT[(db + m * 4 + 1) * 72 + t] = v4.y;
                kT[(db + m * 4 + 2) * 72 + t] = v4.z;
                kT[(db + m * 4 + 3) * 72 + t] = v4.w;
            }
        }
        __syncthreads();

        float a0[8], a1[8];
#pragma unroll
        for (int j = 0; j < 8; j++) { a0[j] = 0.f; a1[j] = 0.f; }
#pragma unroll 16
        for (int d = 0; d < 64; d++) {
            float qv0 = qs[q1 * 68 + d];
            float qv1 = qs[(q1 + 1) * 68 + d];
            float4 ka = *(float4*)&kT[d * 72 + kg * 8];
            float4 kb = *(float4*)&kT[d * 72 + kg * 8 + 4];
            a0[0] += qv0 * ka.x; a0[1] += qv0 * ka.y;
            a0[2] += qv0 * ka.z; a0[3] += qv0 * ka.w;
            a0[4] += qv0 * kb.x; a0[5] += qv0 * kb.y;
            a0[6] += qv0 * kb.z; a0[7] += qv0 * kb.w;
            a1[0] += qv1 * ka.x; a1[1] += qv1 * ka.y;
            a1[2] += qv1 * ka.z; a1[3] += qv1 * ka.w;
            a1[4] += qv1 * kb.x; a1[5] += qv1 * kb.y;
            a1[6] += qv1 * kb.z; a1[7] += qv1 * kb.w;
        }
        {
            int gq = q0 + q1;
            const size_t gr0 = ((size_t)bh * kS + gq) * kS;
            const size_t gr1 = gr0 + kS;
            bool v0 = (gq < kS), v1 = (gq + 1 < kS);
#pragma unroll
            for (int j = 0; j < 8; j++) {
                int gk = koff + kg * 8 + j;
                if (gk < kS) {
                    ps[q1 * 264 + gk] = v0 ? (a0[j] + gb[gr0 + gk]) : 0.0f;
                    ps[(q1 + 1) * 264 + gk] = v1 ? (a1[j] + gb[gr1 + gk]) : 0.0f;
                }
            }
        }
        __syncthreads();
    }

    // ---- phase 2: softmax (fast exp) ----
    for (int rr = 0; rr < 8; rr++) {
        int r = wid * 8 + rr;
        float m = -3.4e38f;
        for (int kk = lane; kk < kS; kk += 32)
            m = fmaxf(m, ps[r * 264 + kk]);
#pragma unroll
        for (int o2 = 16; o2; o2 >>= 1)
            m = fmaxf(m, __shfl_xor_sync(0xffffffffu, m, o2));
        float sum = 0.0f;
        for (int kk = lane; kk < kS; kk += 32) {
            float e = __expf(ps[r * 264 + kk] - m);
            ps[r * 264 + kk] = e;
            sum += e;
        }
#pragma unroll
        for (int o2 = 16; o2; o2 >>= 1)
            sum += __shfl_xor_sync(0xffffffffu, sum, o2);
        float inv = 1.0f / sum;
        for (int kk = lane; kk < kS; kk += 32)
            ps[r * 264 + kk] *= inv;
    }
    __syncthreads();

    // ---- phase 3: P @ V ----
    float* vs = s + AT_KT;
    const int dg = tid & 7;
    const int d8 = dg * 8;
    float o0[8], o1[8];
#pragma unroll
    for (int j = 0; j < 8; j++) { o0[j] = 0.f; o1[j] = 0.f; }

    for (int koff = 0; koff < kS; koff += 64) {
        {
#pragma unroll
            for (int it = 0; it < 4; it++) {
                int p = tid + it * 256;
                int t = p >> 4;
                int u = p & 15;
                int gk = koff + t;
                float4 v4 = make_float4(0.f, 0.f, 0.f, 0.f);
                if (gk < kS)
                    v4 = *(const float4*)(qkv + ((size_t)(b * kS + gk)) * kQKV +
                                          2 * kD + hh * kHD + u * 4);
                *(float4*)&vs[t * 68 + u * 4] = v4;
            }
        }
        __syncthreads();
        int klim = min(64, kS - koff);
#pragma unroll 8
        for (int kl = 0; kl < klim; kl++) {
            float p0 = ps[q1 * 264 + koff + kl];
            float p1 = ps[(q1 + 1) * 264 + koff + kl];
            float4 va = *(float4*)&vs[kl * 68 + d8];
            float4 vb = *(float4*)&vs[kl * 68 + d8 + 4];
            o0[0] += p0 * va.x; o0[1] += p0 * va.y;
            o0[2] += p0 * va.z; o0[3] += p0 * va.w;
            o0[4] += p0 * vb.x; o0[5] += p0 * vb.y;
            o0[6] += p0 * vb.z; o0[7] += p0 * vb.w;
            o1[0] += p1 * va.x; o1[1] += p1 * va.y;
            o1[2] += p1 * va.z; o1[3] += p1 * va.w;
            o1[4] += p1 * vb.x; o1[5] += p1 * vb.y;
            o1[6] += p1 * vb.z; o1[7] += p1 * vb.w;
        }
        __syncthreads();
    }

    // write o as split bf16 planes (row-major [tok][768])
    {
        int gq = q0 + q1;
        if (gq < kS) {
            size_t off = ((size_t)(b * kS + gq)) * kD + hh * kHD + d8;
            uint2 s0 = sp2(o0[0], o0[1]);
            uint2 s1 = sp2(o0[2], o0[3]);
            uint2 s2 = sp2(o0[4], o0[5]);
            uint2 s3 = sp2(o0[6], o0[7]);
            *(uint4*)(oHi + off) = make_uint4(s0.x, s1.x, s2.x, s3.x);
            *(uint4*)(oLo + off) = make_uint4(s0.y, s1.y, s2.y, s3.y);
        }
        if (gq + 1 < kS) {
            size_t off = ((size_t)(b * kS + gq + 1)) * kD + hh * kHD + d8;
            uint2 s0 = sp2(o1[0], o1[1]);
            uint2 s1 = sp2(o1[2], o1[3]);
            uint2 s2 = sp2(o1[4], o1[5]);
            uint2 s3 = sp2(o1[6], o1[7]);
            *(uint4*)(oHi + off) = make_uint4(s0.x, s1.x, s2.x, s3.x);
            *(uint4*)(oLo + off) = make_uint4(s0.y, s1.y, s2.y, s3.y);
        }
    }
}

// ---------------------------------------------------------------------------
// Embedding
// ---------------------------------------------------------------------------
__global__ void embed_kernel(const int* __restrict__ x,
                             const int* __restrict__ in_deg,
                             const int* __restrict__ out_deg,
                             const float* __restrict__ atom_emb,
                             const float* __restrict__ in_deg_emb,
                             const float* __restrict__ out_deg_emb,
                             const float* __restrict__ graph_token,
                             float* __restrict__ h) {
    int tok = blockIdx.x;
    int b = tok / kS, s = tok % kS;
    float* out = h + (size_t)tok * kD;
    if (s == 0) {
        for (int d = threadIdx.x; d < kD; d += 256) out[d] = graph_token[d];
        return;
    }
    int n = s - 1;
    const int* xr = x + (b * kN + n) * kNF;
    int a0 = iclamp(xr[0], 0, kNA);
    int a1 = iclamp(xr[1], 0, kNA);
    int a2 = iclamp(xr[2], 0, kNA);
    int di = iclamp(in_deg[b * kN + n], 0, kND - 1);
    int dq = iclamp(out_deg[b * kN + n], 0, kND - 1);
    const float* e0 = atom_emb + (size_t)a0 * kD;
    const float* e1 = atom_emb + (size_t)a1 * kD;
    const float* e2 = atom_emb + (size_t)a2 * kD;
    const float* ei = in_deg_emb + (size_t)di * kD;
    const float* eo = out_deg_emb + (size_t)dq * kD;
    for (int d = threadIdx.x; d < kD; d += 256)
        out[d] = e0[d] + e1[d] + e2[d] + ei[d] + eo[d];
}

// ---------------------------------------------------------------------------
// Graph bias gb[b,h,q,k] (mask baked in)
// ---------------------------------------------------------------------------
__global__ void bias_kernel(const float* __restrict__ attn_bias,
                            const int* __restrict__ spatial_pos,
                            const int* __restrict__ edge_type,
                            const int* __restrict__ x,
                            const float* __restrict__ spatial_emb,
                            const float* __restrict__ edge_emb,
                            const float* __restrict__ virt_dist,
                            float* __restrict__ gb) {
    int idx = blockIdx.x * 256 + threadIdx.x;
    if (idx >= kS * kS) return;
    int b = blockIdx.y;
    int q = idx / kS, k = idx % kS;

    size_t obase = ((size_t)b * kH) * kS * kS + (size_t)q * kS + k;

    if (k >= 1 && x[(b * kN + (k - 1)) * kNF] == 0) {
#pragma unroll
        for (int hh = 0; hh < kH; hh++)
            gb[obase + (size_t)hh * kS * kS] = -1e30f;
        return;
    }

    float base = attn_bias[(size_t)b * kS * kS + idx];
    float vals[kH];
#pragma unroll
    for (int hh = 0; hh < kH; hh++) vals[hh] = base;

    if (q >= 1 && k >= 1) {
        size_t e = (size_t)b * kN * kN + (size_t)(q - 1) * kN + (k - 1);
        int sp = iclamp(spatial_pos[e], 0, kNS - 1);
        const int* et = edge_type + e * kNEF;
        int t0 = iclamp(et[0], 0, kNE);
        int t1 = iclamp(et[1], 0, kNE);
        int t2 = iclamp(et[2], 0, kNE);
        const float* sr = spatial_emb + (size_t)sp * kH;
        const float* r0 = edge_emb + (size_t)t0 * kH;
        const float* r1 = edge_emb + (size_t)t1 * kH;
        const float* r2 = edge_emb + (size_t)t2 * kH;
#pragma unroll
        for (int hh = 0; hh < kH; hh++)
            vals[hh] += sr[hh] + (r0[hh] + r1[hh] + r2[hh]) * (1.0f / 3.0f);
    }
    if (q == 0 || k == 0) {
#pragma unroll
        for (int hh = 0; hh < kH; hh++) vals[hh] += virt_dist[hh];
    }
#pragma unroll
    for (int hh = 0; hh < kH; hh++)
        gb[obase + (size_t)hh * kS * kS] = vals[hh];
}

// ---------------------------------------------------------------------------
// LayerNorm -> split bf16 planes (GEMM input)
// ---------------------------------------------------------------------------
__global__ void ln_split_kernel(const float* __restrict__ in,
                                const float* __restrict__ g,
                                const float* __restrict__ bt,
                                uint16_t* __restrict__ hiP,
                                uint16_t* __restrict__ loP) {
    int tok = blockIdx.x;
    int tid = threadIdx.x;
    const float* xr = in + (size_t)tok * kD;
    __shared__ float red[256];
    float x0 = xr[tid], x1 = xr[tid + 256], x2 = xr[tid + 512];
    red[tid] = x0 + x1 + x2;
    __syncthreads();
    for (int off = 128; off; off >>= 1) {
        if (tid < off) red[tid] += red[tid + off];
        __syncthreads();
    }
    float mean = red[0] * (1.0f / kD);
    __syncthreads();
    float d0 = x0 - mean, d1 = x1 - mean, d2 = x2 - mean;
    red[tid] = d0 * d0 + d1 * d1 + d2 * d2;
    __syncthreads();
    for (int off = 128; off; off >>= 1) {
        if (tid < off) red[tid] += red[tid + off];
        __syncthreads();
    }
    float inv = rsqrtf(red[0] * (1.0f / kD) + kEPS);
    float z0 = d0 * inv * g[tid]       + bt[tid];
    float z1 = d1 * inv * g[tid + 256] + bt[tid + 256];
    float z2 = d2 * inv * g[tid + 512] + bt[tid + 512];
    size_t base = (size_t)tok * kD;
    uint2 s;
    s = sp2(z0, z0); hiP[base + tid]       = (uint16_t)(s.x & 0xffff);
                     loP[base + tid]       = (uint16_t)(s.y & 0xffff);
    s = sp2(z1, z1); hiP[base + tid + 256] = (uint16_t)(s.x & 0xffff);
                     loP[base + tid + 256] = (uint16_t)(s.y & 0xffff);
    s = sp2(z2, z2); hiP[base + tid + 512] = (uint16_t)(s.x & 0xffff);
                     loP[base + tid + 512] = (uint16_t)(s.y & 0xffff);
}

__global__ void final_ln_kernel(const float* __restrict__ in,
                                const float* __restrict__ g,
                                const float* __restrict__ bt,
                                float* __restrict__ out) {
    int tok = blockIdx.x;
    int b = tok / kS, s = tok % kS;
    int tid = threadIdx.x;
    const float* xr = in + (size_t)tok * kD;
    __shared__ float red[256];
    float x0 = xr[tid], x1 = xr[tid + 256], x2 = xr[tid + 512];
    red[tid] = x0 + x1 + x2;
    __syncthreads();
    for (int off = 128; off; off >>= 1) {
        if (tid < off) red[tid] += red[tid + off];
        __syncthreads();
    }
    float mean = red[0] * (1.0f / kD);
    __syncthreads();
    float d0 = x0 - mean, d1 = x1 - mean, d2 = x2 - mean;
    red[tid] = d0 * d0 + d1 * d1 + d2 * d2;
    __syncthreads();
    for (int off = 128; off; off >>= 1) {
        if (tid < off) red[tid] += red[tid + off];
        __syncthreads();
    }
    float inv = rsqrtf(red[0] * (1.0f / kD) + kEPS);
    float* orow = (s == 0)
        ? out + (size_t)kB * kN * kD + (size_t)b * kD
        : out + ((size_t)b * kN + (s - 1)) * kD;
    orow[tid]       = d0 * inv * g[tid]       + bt[tid];
    orow[tid + 256] = d1 * inv * g[tid + 256] + bt[tid + 256];
    orow[tid + 512] = d2 * inv * g[tid + 512] + bt[tid + 512];
}

// ---------------------------------------------------------------------------
// Host launcher
// ---------------------------------------------------------------------------
extern "C" void kernel_launch(void* const* d_in, const int* in_sizes, int n_in,
                              void* d_out, int out_size) {
    (void)in_sizes; (void)n_in; (void)out_size;

    const int*   x              = (const int*)  d_in[0];
    const float* attn_bias      = (const float*)d_in[1];
    const int*   spatial_pos    = (const int*)  d_in[2];
    const int*   attn_edge_type = (const int*)  d_in[3];
    const int*   in_degree      = (const int*)  d_in[4];
    const int*   out_degree     = (const int*)  d_in[5];
    const float* atom_emb       = (const float*)d_in[6];
    const float* in_deg_emb     = (const float*)d_in[7];
    const float* out_deg_emb    = (const float*)d_in[8];
    const float* graph_token    = (const float*)d_in[9];
    const float* spatial_emb    = (const float*)d_in[10];
    const float* edge_emb       = (const float*)d_in[11];
    const float* virt_dist      = (const float*)d_in[12];
    const float* Wq             = (const float*)d_in[13];
    const float* Wk             = (const float*)d_in[14];
    const float* Wv             = (const float*)d_in[15];
    const float* Wo             = (const float*)d_in[16];
    const float* bq             = (const float*)d_in[17];
    const float* bk             = (const float*)d_in[18];
    const float* bv             = (const float*)d_in[19];
    const float* bo             = (const float*)d_in[20];
    const float* ln1_g          = (const float*)d_in[21];
    const float* ln1_b          = (const float*)d_in[22];
    const float* ln2_g          = (const float*)d_in[23];
    const float* ln2_b          = (const float*)d_in[24];
    const float* W1             = (const float*)d_in[25];
    const float* b1             = (const float*)d_in[26];
    const float* W2             = (const float*)d_in[27];
    const float* b2             = (const float*)d_in[28];
    const float* fin_g          = (const float*)d_in[29];
    const float* fin_b          = (const float*)d_in[30];
    float* out = (float*)d_out;

    float* base = nullptr;
    cudaGetSymbolAddress((void**)&base, g_scratch);
    uint16_t* cv = nullptr;
    cudaGetSymbolAddress((void**)&cv, g_cv);
    uint16_t* fpl = nullptr;
    cudaGetSymbolAddress((void**)&fpl, g_f);
    float* bqkv = nullptr;
    cudaGetSymbolAddress((void**)&bqkv, g_bqkv);

    float* h   = base + OFF_H;
    float* qkv = base + OFF_QKV;
    float* gb  = base + OFF_GB;

    uint16_t* aHi = cv + CV_A;
    uint16_t* aLo = cv + CV_A + ACT_PLANE;
    uint16_t* fHi = fpl;
    uint16_t* fLo = fpl + ACT_PLANE;

    cudaFuncSetAttribute(gemm_tc, cudaFuncAttributeMaxDynamicSharedMemorySize,
                         GT_SMEM);
    cudaFuncSetAttribute(attn_fused,
                         cudaFuncAttributeMaxDynamicSharedMemorySize, AT_SMEM);

    // weight conversions (once per launch; deterministic)
    cvt_split_qkv<<<4096, 256>>>((const float4*)Wq, (uint2*)(cv + CV_WQKV),
                                 (uint2*)(cv + CV_WQKV + W_QKV), 0,
                                 (int)(W_DD / 4));
    cvt_split_qkv<<<4096, 256>>>((const float4*)Wk, (uint2*)(cv + CV_WQKV),
                                 (uint2*)(cv + CV_WQKV + W_QKV), 1,
                                 (int)(W_DD / 4));
    cvt_split_qkv<<<4096, 256>>>((const float4*)Wv, (uint2*)(cv + CV_WQKV),
                                 (uint2*)(cv + CV_WQKV + W_QKV), 2,
                                 (int)(W_DD / 4));
    cvt_split<<<4096, 256>>>((const float4*)Wo, (uint2*)(cv + CV_WO),
                             (uint2*)(cv + CV_WO + W_DD), (int)(W_DD / 4));
    cvt_split<<<4096, 256>>>((const float4*)W1, (uint2*)(cv + CV_W1),
                             (uint2*)(cv + CV_W1 + W_FD), (int)(W_FD / 4));
    cvt_split<<<4096, 256>>>((const float4*)W2, (uint2*)(cv + CV_W2),
                             (uint2*)(cv + CV_W2 + W_FD), (int)(W_FD / 4));
    bias_cat<<<(kL * kQKV + 255) / 256, 256>>>(bq, bk, bv, bqkv);

    embed_kernel<<<kBS, 256>>>(x, in_degree, out_degree, atom_emb, in_deg_emb,
                               out_deg_emb, graph_token, h);
    bias_kernel<<<dim3((kS * kS + 255) / 256, kB), 256>>>(
        attn_bias, spatial_pos, attn_edge_type, x, spatial_emb, edge_emb,
        virt_dist, gb);

    const int mtiles = (kBS + 127) / 128;            // 65
    dim3 gemmD(kD / 128, mtiles);                    // (6, 65)
    dim3 gemmQ(kQKV / 128, mtiles);                  // (18, 65)
    dim3 gemmF(kFF / 128, mtiles);                   // (24, 65)
    dim3 attnG((kS + 63) / 64, kB * kH);             // (5, 384)

    for (int l = 0; l < kL; l++) {
        const size_t odd  = (size_t)l * kD * kD;
        const size_t oqkv = (size_t)l * kQKV * kD;
        const size_t ofd  = (size_t)l * kFF * kD;

        ln_split_kernel<<<kBS, 256>>>(h, ln1_g + l * kD, ln1_b + l * kD,
                                      aHi, aLo);

        gemm_tc<<<gemmQ, 256, GT_SMEM>>>(aHi, aLo, cv + CV_WQKV + oqkv,
                                         cv + CV_WQKV + W_QKV + oqkv,
                                         bqkv + (size_t)l * kQKV, qkv,
                                         nullptr, nullptr,
                                         kBS, kQKV, kD, EPI_QKV);

        // attention writes the next GEMM's A operand (z planes are dead now)
        attn_fused<<<attnG, 256, AT_SMEM>>>(qkv, gb, aHi, aLo);

        gemm_tc<<<gemmD, 256, GT_SMEM>>>(aHi, aLo, cv + CV_WO + odd,
                                         cv + CV_WO + W_DD + odd,
                                         bo + l * kD, h, nullptr, nullptr,
                                         kBS, kD, kD, EPI_RES);

        ln_split_kernel<<<kBS, 256>>>(h, ln2_g + l * kD, ln2_b + l * kD,
                                      aHi, aLo);
        gemm_tc<<<gemmF, 256, GT_SMEM>>>(aHi, aLo, cv + CV_W1 + ofd,
                                         cv + CV_W1 + W_FD + ofd,
                                         b1 + l * kFF, nullptr, fHi, fLo,
                                         kBS, kFF, kD, EPI_GELU);
        gemm_tc<<<gemmD, 256, GT_SMEM>>>(fHi, fLo, cv + CV_W2 + ofd,
                                         cv + CV_W2 + W_FD + ofd,
                                         b2 + l * kD, h, nullptr, nullptr,
                                         kBS, kD, kFF, EPI_RES);
    }

    final_ln_kernel<<<kBS, 256>>>(h, fin_g, fin_b, out);
}

// round 17
// speedup vs baseline: 3.2697x; 1.1641x over previous
#include <cuda_runtime.h>
#include <math.h>
#include <stdint.h>

// ---------------------------------------------------------------------------
// Problem constants
// ---------------------------------------------------------------------------
namespace {
constexpr int kB   = 32;
constexpr int kN   = 256;
constexpr int kNF  = 3;
constexpr int kNEF = 3;
constexpr int kD   = 768;
constexpr int kFF  = 3072;
constexpr int kH   = 12;
constexpr int kL   = 6;
constexpr int kNA  = 512;
constexpr int kND  = 512;
constexpr int kNE  = 512;
constexpr int kNS  = 512;
constexpr int kS   = 257;          // N + 1
constexpr int kHD  = 64;           // D / H
constexpr int kBS  = kB * kS;      // 8224 tokens
constexpr int kQKV = 3 * kD;       // 2304
constexpr float kSCALE = 0.125f;   // HD^-0.5
constexpr float kEPS   = 1e-5f;

constexpr size_t SZ_TOK = (size_t)kBS * kD;            // 6,316,032
constexpr size_t SZ_ATT = (size_t)kB * kH * kS * kS;   // 25,365,504
constexpr size_t OFF_H   = 0;
constexpr size_t OFF_QKV = OFF_H + SZ_TOK;             // [kBS][2304]
constexpr size_t OFF_GB  = OFF_QKV + 3 * SZ_TOK;
constexpr size_t SCRATCH_ELEMS = OFF_GB + SZ_ATT;

// bf16 hi/lo conversion buffers (uint16 elements)
constexpr size_t W_DD   = (size_t)kL * kD * kD;        // 3,538,944
constexpr size_t W_FD   = (size_t)kL * kFF * kD;       // 14,155,776
constexpr size_t W_QKV  = 3 * W_DD;                    // combined [l][2304][768]
constexpr size_t CV_WQKV = 0;                          // hi then lo
constexpr size_t CV_WO  = CV_WQKV + 2 * W_QKV;
constexpr size_t CV_W1  = CV_WO + 2 * W_DD;
constexpr size_t CV_W2  = CV_W1 + 2 * W_FD;
constexpr size_t CV_A   = CV_W2 + 2 * W_FD;
constexpr size_t ACT_PLANE = (size_t)8320 * kFF;       // 25,559,040
constexpr size_t CV_TOTAL  = CV_A + 2 * ACT_PLANE;
}  // namespace

__device__ float    g_scratch[SCRATCH_ELEMS];
__device__ uint16_t g_cv[CV_TOTAL];          // BSS zero — pad rows stay 0
__device__ uint16_t g_f[2 * ACT_PLANE];      // FFN intermediate planes
__device__ float    g_bqkv[(size_t)kL * kQKV];

__device__ __forceinline__ int iclamp(int v, int lo, int hi) {
    return min(max(v, lo), hi);
}

__device__ __forceinline__ uint32_t smem_u32(const void* p) {
    uint32_t a;
    asm("{ .reg .u64 t; cvta.to.shared.u64 t, %1; cvt.u32.u64 %0, t; }"
        : "=r"(a) : "l"(p));
    return a;
}

// ---------------------------------------------------------------------------
// bf16 split helpers
// ---------------------------------------------------------------------------
__device__ __forceinline__ uint32_t pk_bf2(float lo_f, float hi_f) {
    uint32_t r;
    asm("cvt.rn.bf16x2.f32 %0, %1, %2;" : "=r"(r) : "f"(hi_f), "f"(lo_f));
    return r;
}
__device__ __forceinline__ uint2 sp2(float a, float b) {
    uint32_t h = pk_bf2(a, b);
    float ha = __uint_as_float(h << 16);
    float hb = __uint_as_float(h & 0xffff0000u);
    uint32_t l = pk_bf2(a - ha, b - hb);
    return make_uint2(h, l);
}
__device__ __forceinline__ void split8(float4 f0, float4 f1, uint4& hi, uint4& lo) {
    uint2 s;
    s = sp2(f0.x, f0.y); hi.x = s.x; lo.x = s.y;
    s = sp2(f0.z, f0.w); hi.y = s.x; lo.y = s.y;
    s = sp2(f1.x, f1.y); hi.z = s.x; lo.z = s.y;
    s = sp2(f1.z, f1.w); hi.w = s.x; lo.w = s.y;
}

// All weight conversions in ONE kernel (also aligns ncu -s 5 capture to gemm_tc)
__global__ void cvt_all(const float4* __restrict__ Wq,
                        const float4* __restrict__ Wk,
                        const float4* __restrict__ Wv,
                        const float4* __restrict__ Wo,
                        const float4* __restrict__ W1,
                        const float4* __restrict__ W2,
                        uint16_t* __restrict__ cv) {
    constexpr int n1 = (int)(W_DD / 4);
    constexpr int nf = (int)(W_FD / 4);
    constexpr int L4 = kD * kD / 4;
    const int total = 4 * n1 + 2 * nf;
    for (int i = blockIdx.x * 256 + threadIdx.x; i < total;
         i += gridDim.x * 256) {
        const float4* src;
        uint2 *hiP, *loP;
        size_t d4;
        if (i < 3 * n1) {
            int part = i / n1;
            int r = i - part * n1;
            src = (part == 0 ? Wq : part == 1 ? Wk : Wv) + r;
            int l = r / L4;
            int rr = r - l * L4;
            d4 = (size_t)l * (3 * L4) + (size_t)part * L4 + rr;
            hiP = (uint2*)(cv + CV_WQKV);
            loP = (uint2*)(cv + CV_WQKV + W_QKV);
        } else if (i < 4 * n1) {
            int r = i - 3 * n1;
            src = Wo + r; d4 = r;
            hiP = (uint2*)(cv + CV_WO);
            loP = (uint2*)(cv + CV_WO + W_DD);
        } else if (i < 4 * n1 + nf) {
            int r = i - 4 * n1;
            src = W1 + r; d4 = r;
            hiP = (uint2*)(cv + CV_W1);
            loP = (uint2*)(cv + CV_W1 + W_FD);
        } else {
            int r = i - 4 * n1 - nf;
            src = W2 + r; d4 = r;
            hiP = (uint2*)(cv + CV_W2);
            loP = (uint2*)(cv + CV_W2 + W_FD);
        }
        float4 v = *src;
        uint2 s0 = sp2(v.x, v.y);
        uint2 s1 = sp2(v.z, v.w);
        hiP[d4] = make_uint2(s0.x, s1.x);
        loP[d4] = make_uint2(s0.y, s1.y);
    }
}

__global__ void bias_cat(const float* __restrict__ bq,
                         const float* __restrict__ bk,
                         const float* __restrict__ bv,
                         float* __restrict__ o) {
    int idx = blockIdx.x * 256 + threadIdx.x;
    if (idx >= kL * kQKV) return;
    int l = idx / kQKV, c = idx % kQKV;
    float v;
    if (c < kD)          v = bq[l * kD + c];
    else if (c < 2 * kD) v = bk[l * kD + (c - kD)];
    else                 v = bv[l * kD + (c - 2 * kD)];
    o[idx] = v;
}

// ---------------------------------------------------------------------------
// cp.async / ldmatrix / mma helpers
// ---------------------------------------------------------------------------
__device__ __forceinline__ void cpa16(uint32_t dst, const void* src) {
    asm volatile("cp.async.cg.shared.global [%0], [%1], 16;"
                 :: "r"(dst), "l"(src) : "memory");
}
__device__ __forceinline__ void cpa_commit() {
    asm volatile("cp.async.commit_group;" ::: "memory");
}

#define LDM4(r0, r1, r2, r3, ad)                                              \
    asm volatile(                                                             \
        "ldmatrix.sync.aligned.m8n8.x4.shared.b16 {%0,%1,%2,%3}, [%4];"       \
        : "=r"(r0), "=r"(r1), "=r"(r2), "=r"(r3) : "r"(ad))

#define LDM4T(r0, r1, r2, r3, ad)                                             \
    asm volatile(                                                             \
        "ldmatrix.sync.aligned.m8n8.x4.trans.shared.b16 {%0,%1,%2,%3}, [%4];" \
        : "=r"(r0), "=r"(r1), "=r"(r2), "=r"(r3) : "r"(ad))

#define MMA_BF16(c, a, b0r, b1r)                                              \
    asm volatile(                                                             \
        "mma.sync.aligned.m16n8k16.row.col.f32.bf16.bf16.f32 "                \
        "{%0,%1,%2,%3}, {%4,%5,%6,%7}, {%8,%9}, {%0,%1,%2,%3};"               \
        : "+f"((c)[0]), "+f"((c)[1]), "+f"((c)[2]), "+f"((c)[3])              \
        : "r"((a)[0]), "r"((a)[1]), "r"((a)[2]), "r"((a)[3]),                 \
          "r"(b0r), "r"(b1r))

// ---------------------------------------------------------------------------
// GEMM (unchanged from R15/R16 — passing)
// ---------------------------------------------------------------------------
enum { EPI_NONE = 0, EPI_QKV = 1, EPI_GELU = 2, EPI_RES = 3 };

namespace {
constexpr uint32_t STAGE = 32768;
constexpr uint32_t GT_SMEM = 3 * STAGE;  // 96KB -> 2 CTAs/SM
}

__device__ __forceinline__ void issue_stage(uint32_t st,
                                            const uint16_t* __restrict__ Ahi,
                                            const uint16_t* __restrict__ Alo,
                                            const uint16_t* __restrict__ Whi,
                                            const uint16_t* __restrict__ Wlo,
                                            int K, int bm, int bn, int kc,
                                            int tid) {
#pragma unroll
    for (int it = 0; it < 2; it++) {
        int p = tid + it * 256;
        int row = p >> 2;
        uint32_t u = (uint32_t)(p & 3);
        uint32_t dst = st + (uint32_t)row * 64 +
                       ((u ^ (((uint32_t)row >> 1) & 3)) << 4);
        size_t ao = (size_t)(bm + row) * K + kc + u * 8;
        size_t wo = (size_t)(bn + row) * K + kc + u * 8;
        cpa16(dst,          Ahi + ao);
        cpa16(dst + 8192,   Alo + ao);
        cpa16(dst + 16384,  Whi + wo);
        cpa16(dst + 24576,  Wlo + wo);
    }
    cpa_commit();
}

__global__ __launch_bounds__(256, 2)
void gemm_tc(const uint16_t* __restrict__ Ahi, const uint16_t* __restrict__ Alo,
             const uint16_t* __restrict__ Whi, const uint16_t* __restrict__ Wlo,
             const float* __restrict__ bias, float* __restrict__ C,
             uint16_t* __restrict__ CHi, uint16_t* __restrict__ CLo,
             int M, int N, int K, int epi) {
    extern __shared__ char sm[];
    const int tid = threadIdx.x;
    const int lane = tid & 31;
    const int wid = tid >> 5;
    const int bm = blockIdx.y * 128;
    const int bn = blockIdx.x * 128;
    const int wm = (wid & 1) * 64;
    const int wn = (wid >> 1) * 32;
    const uint32_t sbase = smem_u32(sm);
    const int nchunk = K >> 5;

    const int g = lane >> 3;
    const int r8 = lane & 7;
    const int aRow = wm + ((g & 1) << 3) + r8;
    const uint32_t aK1 = (uint32_t)(g >> 1);
    const int bRow = wn + ((g >> 1) << 3) + r8;
    const uint32_t bK1 = (uint32_t)(g & 1);
    const uint32_t swA = ((uint32_t)(aRow >> 1)) & 3;
    const uint32_t swB = ((uint32_t)(bRow >> 1)) & 3;

    float acc[4][4][4];
#pragma unroll
    for (int i = 0; i < 4; i++)
#pragma unroll
        for (int j = 0; j < 4; j++)
#pragma unroll
            for (int t = 0; t < 4; t++) acc[i][j][t] = 0.0f;

    issue_stage(sbase,         Ahi, Alo, Whi, Wlo, K, bm, bn, 0,  tid);
    issue_stage(sbase + STAGE, Ahi, Alo, Whi, Wlo, K, bm, bn, 32, tid);

    for (int c = 0; c < nchunk; c++) {
        if (c + 1 == nchunk)
            asm volatile("cp.async.wait_group 0;" ::: "memory");
        else
            asm volatile("cp.async.wait_group 1;" ::: "memory");
        __syncthreads();
        if (c + 2 < nchunk) {
            int s2 = (c + 2) % 3;
            issue_stage(sbase + (uint32_t)s2 * STAGE, Ahi, Alo, Whi, Wlo,
                        K, bm, bn, (c + 2) << 5, tid);
        }

        const uint32_t st = sbase + (uint32_t)(c % 3) * STAGE;
#pragma unroll
        for (int ks = 0; ks < 2; ks++) {
            const uint32_t kx = ks ? 2u : 0u;
            uint32_t a[4][4], bh[4][2], bl[4][2];
#pragma unroll
            for (int mf = 0; mf < 4; mf++) {
                uint32_t ad = st + (uint32_t)(aRow + mf * 16) * 64 +
                              (((kx | aK1) ^ swA) << 4);
                LDM4(a[mf][0], a[mf][1], a[mf][2], a[mf][3], ad);
            }
#pragma unroll
            for (int p = 0; p < 2; p++) {
                uint32_t ad = st + 16384u + (uint32_t)(bRow + p * 16) * 64 +
                              (((kx | bK1) ^ swB) << 4);
                uint32_t r0, r1, r2, r3;
                LDM4(r0, r1, r2, r3, ad);
                bh[p * 2][0] = r0; bh[p * 2][1] = r1;
                bh[p * 2 + 1][0] = r2; bh[p * 2 + 1][1] = r3;
            }
#pragma unroll
            for (int mf = 0; mf < 4; mf++)
#pragma unroll
                for (int nf = 0; nf < 4; nf++)
                    MMA_BF16(acc[mf][nf], a[mf], bh[nf][0], bh[nf][1]);
#pragma unroll
            for (int p = 0; p < 2; p++) {
                uint32_t ad = st + 24576u + (uint32_t)(bRow + p * 16) * 64 +
                              (((kx | bK1) ^ swB) << 4);
                uint32_t r0, r1, r2, r3;
                LDM4(r0, r1, r2, r3, ad);
                bl[p * 2][0] = r0; bl[p * 2][1] = r1;
                bl[p * 2 + 1][0] = r2; bl[p * 2 + 1][1] = r3;
            }
#pragma unroll
            for (int mf = 0; mf < 4; mf++)
#pragma unroll
                for (int nf = 0; nf < 4; nf++)
                    MMA_BF16(acc[mf][nf], a[mf], bl[nf][0], bl[nf][1]);
#pragma unroll
            for (int mf = 0; mf < 4; mf++) {
                uint32_t ad = st + 8192u + (uint32_t)(aRow + mf * 16) * 64 +
                              (((kx | aK1) ^ swA) << 4);
                LDM4(a[mf][0], a[mf][1], a[mf][2], a[mf][3], ad);
            }
#pragma unroll
            for (int mf = 0; mf < 4; mf++)
#pragma unroll
                for (int nf = 0; nf < 4; nf++)
                    MMA_BF16(acc[mf][nf], a[mf], bh[nf][0], bh[nf][1]);
        }
    }

#pragma unroll
    for (int mf = 0; mf < 4; mf++) {
        const int r0 = bm + wm + mf * 16 + (lane >> 2);
#pragma unroll
        for (int nf = 0; nf < 4; nf++) {
            const int cc = bn + wn + nf * 8 + ((lane & 3) << 1);
            const float b0v = bias[cc];
            const float b1v = bias[cc + 1];
            float v0 = acc[mf][nf][0] + b0v;
            float v1 = acc[mf][nf][1] + b1v;
            float v2 = acc[mf][nf][2] + b0v;
            float v3 = acc[mf][nf][3] + b1v;
            if (epi == EPI_GELU) {
                v0 = 0.5f * v0 * (1.0f + erff(v0 * 0.70710678118654752f));
                v1 = 0.5f * v1 * (1.0f + erff(v1 * 0.70710678118654752f));
                v2 = 0.5f * v2 * (1.0f + erff(v2 * 0.70710678118654752f));
                v3 = 0.5f * v3 * (1.0f + erff(v3 * 0.70710678118654752f));
                if (r0 < M) {
                    uint2 s = sp2(v0, v1);
                    size_t o = (size_t)r0 * N + cc;
                    *(uint32_t*)(CHi + o) = s.x;
                    *(uint32_t*)(CLo + o) = s.y;
                }
                if (r0 + 8 < M) {
                    uint2 s = sp2(v2, v3);
                    size_t o = (size_t)(r0 + 8) * N + cc;
                    *(uint32_t*)(CHi + o) = s.x;
                    *(uint32_t*)(CLo + o) = s.y;
                }
                continue;
            }
            if (epi == EPI_QKV && cc < kD) {
                v0 *= kSCALE; v1 *= kSCALE; v2 *= kSCALE; v3 *= kSCALE;
            }
            if (r0 < M) {
                float* cp = C + (size_t)r0 * N + cc;
                if (epi == EPI_RES) {
                    float2 old = *(float2*)cp;
                    v0 += old.x; v1 += old.y;
                }
                *(float2*)cp = make_float2(v0, v1);
            }
            if (r0 + 8 < M) {
                float* cp = C + (size_t)(r0 + 8) * N + cc;
                if (epi == EPI_RES) {
                    float2 old = *(float2*)cp;
                    v2 += old.x; v3 += old.y;
                }
                *(float2*)cp = make_float2(v2, v3);
            }
        }
    }
}

// ---------------------------------------------------------------------------
// Tensor-core fused attention. Per block: (b,h, q-tile of 64).
// scores = split-bf16 MMA (Q,K hi/lo, 3 passes); softmax fp32; PV = split-bf16
// MMA (P,V hi/lo, 3 passes). 256 threads (8 warps): warp = (wq 0-3, wn 0-1),
// output tile 16x32 per warp in both phases.
// SMEM: ps f32[64][264] | Phi/Plo bf16[64][272] | Q hi/lo [2][64][32] (V reuse)
//       | K hi/lo [2][64][32]
// ---------------------------------------------------------------------------
namespace {
constexpr uint32_t AP_PS  = 0;        // 67,584 B
constexpr uint32_t AP_PHI = 67584;    // 34,816 B
constexpr uint32_t AP_PLO = 102400;   // 34,816 B
constexpr uint32_t AP_QH  = 137216;   // 8,192 B  (V hi reuse)
constexpr uint32_t AP_QL  = 145408;   // 8,192 B  (V lo reuse)
constexpr uint32_t AP_KH  = 153600;   // 8,192 B
constexpr uint32_t AP_KL  = 161792;   // 8,192 B
constexpr uint32_t AT2_SMEM = 169984;
}

// load one 64x64 fp32 tile from qkv (+off per element group) into split planes
__device__ __forceinline__ void load_split_tile(char* sm, uint32_t hiOff,
                                                uint32_t loOff,
                                                const float* __restrict__ qkv,
                                                int b, int hh, int row0,
                                                int srcOff, int tid) {
    int row = tid >> 2, u2 = tid & 3;
    int gk = row0 + row;
    float4 f0, f1, f2, f3;
    if (gk < kS) {
        const float4* src = (const float4*)(qkv + ((size_t)(b * kS + gk)) * kQKV +
                                            srcOff + (u2 << 4));
        f0 = src[0]; f1 = src[1]; f2 = src[2]; f3 = src[3];
    } else {
        f0 = f1 = f2 = f3 = make_float4(0.f, 0.f, 0.f, 0.f);
    }
    uint4 h0, l0, h1, l1;
    split8(f0, f1, h0, l0);
    split8(f2, f3, h1, l1);
    int c = u2 >> 1;
    uint32_t uu = (uint32_t)((u2 & 1) << 1);
    uint32_t sw = ((uint32_t)row >> 1) & 3;
    uint32_t o0 = (uint32_t)c * 4096 + (uint32_t)row * 64 + ((uu ^ sw) << 4);
    uint32_t o1 = (uint32_t)c * 4096 + (uint32_t)row * 64 + (((uu + 1) ^ sw) << 4);
    *(uint4*)(sm + hiOff + o0) = h0;
    *(uint4*)(sm + hiOff + o1) = h1;
    *(uint4*)(sm + loOff + o0) = l0;
    *(uint4*)(sm + loOff + o1) = l1;
}

__global__ __launch_bounds__(256)
void attn_mma(const float* __restrict__ qkv, const float* __restrict__ gb,
              uint16_t* __restrict__ oHi, uint16_t* __restrict__ oLo) {
    extern __shared__ char sm[];
    const uint32_t sb = smem_u32(sm);
    float* ps = (float*)sm;                       // [64][264]
    uint16_t* Phi = (uint16_t*)(sm + AP_PHI);     // [64][272]
    uint16_t* Plo = (uint16_t*)(sm + AP_PLO);
    const int tid = threadIdx.x;
    const int lane = tid & 31;
    const int wid = tid >> 5;
    const int bh = blockIdx.y;
    const int b = bh / kH, hh = bh % kH;
    const int q0 = blockIdx.x * 64;

    const int g = lane >> 3, r8 = lane & 7;
    const int wq = wid & 3;        // 16-row band
    const int wn = wid >> 2;       // 32-col half

    // Q tile -> split planes
    load_split_tile(sm, AP_QH, AP_QL, qkv, b, hh, q0, hh * kHD, tid);

    const int aRow = wq * 16 + ((g & 1) << 3) + r8;
    const uint32_t aK1 = (uint32_t)(g >> 1);
    const uint32_t swA = ((uint32_t)aRow >> 1) & 3;
    const int bRow = wn * 32 + ((g >> 1) << 3) + r8;
    const uint32_t bK1 = (uint32_t)(g & 1);
    const uint32_t swB = ((uint32_t)bRow >> 1) & 3;

    // ---- phase 1: scores via split MMA ----
    for (int koff = 0; koff < kS; koff += 64) {
        load_split_tile(sm, AP_KH, AP_KL, qkv, b, hh, koff, kD + hh * kHD, tid);
        __syncthreads();

        float acc[4][4];
#pragma unroll
        for (int i = 0; i < 4; i++)
#pragma unroll
            for (int t = 0; t < 4; t++) acc[i][t] = 0.0f;

#pragma unroll
        for (int dc = 0; dc < 2; dc++) {
#pragma unroll
            for (int ks = 0; ks < 2; ks++) {
                const uint32_t kx = ks ? 2u : 0u;
                uint32_t a[4], bhf[4][2], blf[4][2];
                uint32_t ad = sb + AP_QH + (uint32_t)dc * 4096 +
                              (uint32_t)aRow * 64 + (((kx | aK1) ^ swA) << 4);
                LDM4(a[0], a[1], a[2], a[3], ad);
#pragma unroll
                for (int p = 0; p < 2; p++) {
                    uint32_t adb = sb + AP_KH + (uint32_t)dc * 4096 +
                                   (uint32_t)(bRow + p * 16) * 64 +
                                   (((kx | bK1) ^ swB) << 4);
                    uint32_t r0, r1, r2, r3;
                    LDM4(r0, r1, r2, r3, adb);
                    bhf[p * 2][0] = r0; bhf[p * 2][1] = r1;
                    bhf[p * 2 + 1][0] = r2; bhf[p * 2 + 1][1] = r3;
                }
#pragma unroll
                for (int nf = 0; nf < 4; nf++)
                    MMA_BF16(acc[nf], a, bhf[nf][0], bhf[nf][1]);
#pragma unroll
                for (int p = 0; p < 2; p++) {
                    uint32_t adb = sb + AP_KL + (uint32_t)dc * 4096 +
                                   (uint32_t)(bRow + p * 16) * 64 +
                                   (((kx | bK1) ^ swB) << 4);
                    uint32_t r0, r1, r2, r3;
                    LDM4(r0, r1, r2, r3, adb);
                    blf[p * 2][0] = r0; blf[p * 2][1] = r1;
                    blf[p * 2 + 1][0] = r2; blf[p * 2 + 1][1] = r3;
                }
#pragma unroll
                for (int nf = 0; nf < 4; nf++)
                    MMA_BF16(acc[nf], a, blf[nf][0], blf[nf][1]);
                ad = sb + AP_QL + (uint32_t)dc * 4096 +
                     (uint32_t)aRow * 64 + (((kx | aK1) ^ swA) << 4);
                LDM4(a[0], a[1], a[2], a[3], ad);
#pragma unroll
                for (int nf = 0; nf < 4; nf++)
                    MMA_BF16(acc[nf], a, bhf[nf][0], bhf[nf][1]);
            }
        }

        // epilogue: ps = acc + gb
        {
            const int r = lane >> 2;
            const int c2 = (lane & 3) << 1;
            const int lq = wq * 16 + r;
            const int gq = q0 + lq;
            const int gq8 = gq + 8;
#pragma unroll
            for (int nf = 0; nf < 4; nf++) {
                int col = koff + wn * 32 + nf * 8 + c2;
#pragma unroll
                for (int half = 0; half < 2; half++) {
                    int cc = col + half;
                    if (cc < kS) {
                        float g0 = (gq < kS)
                            ? gb[((size_t)bh * kS + gq) * kS + cc] : 0.f;
                        ps[lq * 264 + cc] = acc[nf][half] + g0;
                        float g2 = (gq8 < kS)
                            ? gb[((size_t)bh * kS + gq8) * kS + cc] : 0.f;
                        ps[(lq + 8) * 264 + cc] = acc[nf][2 + half] + g2;
                    }
                }
            }
        }
        __syncthreads();
    }

    // ---- phase 2: softmax + convert P to split bf16 planes ----
    for (int rr = 0; rr < 8; rr++) {
        int r = wid * 8 + rr;
        float m = -3.4e38f;
        for (int kk = lane; kk < kS; kk += 32)
            m = fmaxf(m, ps[r * 264 + kk]);
#pragma unroll
        for (int o2 = 16; o2; o2 >>= 1)
            m = fmaxf(m, __shfl_xor_sync(0xffffffffu, m, o2));
        float sum = 0.0f;
        for (int kk = lane; kk < kS; kk += 32) {
            float e = __expf(ps[r * 264 + kk] - m);
            ps[r * 264 + kk] = e;
            sum += e;
        }
#pragma unroll
        for (int o2 = 16; o2; o2 >>= 1)
            sum += __shfl_xor_sync(0xffffffffu, sum, o2);
        float inv = 1.0f / sum;
        for (int kk = lane; kk < kS; kk += 32) {
            float p = ps[r * 264 + kk] * inv;
            uint32_t w = pk_bf2(p, p);
            uint16_t hb = (uint16_t)(w & 0xffffu);
            float hf = __uint_as_float((uint32_t)hb << 16);
            uint32_t w2 = pk_bf2(p - hf, 0.f);
            Phi[r * 272 + kk] = hb;
            Plo[r * 272 + kk] = (uint16_t)(w2 & 0xffffu);
        }
        for (int kk = kS + lane; kk < 272; kk += 32) {
            Phi[r * 272 + kk] = 0;
            Plo[r * 272 + kk] = 0;
        }
    }
    __syncthreads();

    // ---- phase 3: O = P @ V via split MMA (V^T frags via ldmatrix.trans) ----
    float oacc[4][4];
#pragma unroll
    for (int i = 0; i < 4; i++)
#pragma unroll
        for (int t = 0; t < 4; t++) oacc[i][t] = 0.0f;

    const int pRow = wq * 16 + ((g & 1) << 3) + r8;   // P A-frag row
    const int vRowBase = ((g & 1) << 3) + r8;          // V key row within kstep
    const uint32_t vdsel = (uint32_t)(g >> 1);         // d 8-half selector

    for (int kc = 0; kc < 5; kc++) {
        load_split_tile(sm, AP_QH, AP_QL, qkv, b, hh, kc * 64,
                        2 * kD + hh * kHD, tid);       // V chunk (reuses Q)
        __syncthreads();
        const int nks = (kc < 4) ? 4 : 1;
        for (int t = 0; t < nks; t++) {
            uint32_t a[4], vh[4][2], vl[4][2];
            const int pk = kc * 64 + t * 16 + ((g >> 1) << 3);
            uint32_t ad = sb + AP_PHI + (uint32_t)pRow * 544 + (uint32_t)pk * 2;
            LDM4(a[0], a[1], a[2], a[3], ad);
            const int vrow = t * 16 + vRowBase;
            const uint32_t swv = ((uint32_t)vrow >> 1) & 3;
#pragma unroll
            for (int p = 0; p < 2; p++) {
                uint32_t uu = (uint32_t)(p << 1) | vdsel;
                uint32_t adv = sb + AP_QH + (uint32_t)wn * 4096 +
                               (uint32_t)vrow * 64 + ((uu ^ swv) << 4);
                uint32_t r0, r1, r2, r3;
                LDM4T(r0, r1, r2, r3, adv);
                vh[p * 2][0] = r0; vh[p * 2][1] = r1;
                vh[p * 2 + 1][0] = r2; vh[p * 2 + 1][1] = r3;
            }
#pragma unroll
            for (int nf = 0; nf < 4; nf++)
                MMA_BF16(oacc[nf], a, vh[nf][0], vh[nf][1]);
#pragma unroll
            for (int p = 0; p < 2; p++) {
                uint32_t uu = (uint32_t)(p << 1) | vdsel;
                uint32_t adv = sb + AP_QL + (uint32_t)wn * 4096 +
                               (uint32_t)vrow * 64 + ((uu ^ swv) << 4);
                uint32_t r0, r1, r2, r3;
                LDM4T(r0, r1, r2, r3, adv);
                vl[p * 2][0] = r0; vl[p * 2][1] = r1;
                vl[p * 2 + 1][0] = r2; vl[p * 2 + 1][1] = r3;
            }
#pragma unroll
            for (int nf = 0; nf < 4; nf++)
                MMA_BF16(oacc[nf], a, vl[nf][0], vl[nf][1]);
            ad = sb + AP_PLO + (uint32_t)pRow * 544 + (uint32_t)pk * 2;
            LDM4(a[0], a[1], a[2], a[3], ad);
#pragma unroll
            for (int nf = 0; nf < 4; nf++)
                MMA_BF16(oacc[nf], a, vh[nf][0], vh[nf][1]);
        }
        __syncthreads();
    }

    // write O as split bf16 planes
    {
        const int r = lane >> 2;
        const int c2 = (lane & 3) << 1;
        const int gq = q0 + wq * 16 + r;
#pragma unroll
        for (int nf = 0; nf < 4; nf++) {
            const int dcol = wn * 32 + nf * 8 + c2;
            if (gq < kS) {
                size_t off = ((size_t)(b * kS + gq)) * kD + hh * kHD + dcol;
                uint2 s = sp2(oacc[nf][0], oacc[nf][1]);
                *(uint32_t*)(oHi + off) = s.x;
                *(uint32_t*)(oLo + off) = s.y;
            }
            if (gq + 8 < kS) {
                size_t off = ((size_t)(b * kS + gq + 8)) * kD + hh * kHD + dcol;
                uint2 s = sp2(oacc[nf][2], oacc[nf][3]);
                *(uint32_t*)(oHi + off) = s.x;
                *(uint32_t*)(oLo + off) = s.y;
            }
        }
    }
}

// ---------------------------------------------------------------------------
// Embedding / bias / LN kernels (unchanged)
// ---------------------------------------------------------------------------
__global__ void embed_kernel(const int* __restrict__ x,
                             const int* __restrict__ in_deg,
                             const int* __restrict__ out_deg,
                             const float* __restrict__ atom_emb,
                             const float* __restrict__ in_deg_emb,
                             const float* __restrict__ out_deg_emb,
                             const float* __restrict__ graph_token,
                             float* __restrict__ h) {
    int tok = blockIdx.x;
    int b = tok / kS, s = tok % kS;
    float* out = h + (size_t)tok * kD;
    if (s == 0) {
        for (int d = threadIdx.x; d < kD; d += 256) out[d] = graph_token[d];
        return;
    }
    int n = s - 1;
    const int* xr = x + (b * kN + n) * kNF;
    int a0 = iclamp(xr[0], 0, kNA);
    int a1 = iclamp(xr[1], 0, kNA);
    int a2 = iclamp(xr[2], 0, kNA);
    int di = iclamp(in_deg[b * kN + n], 0, kND - 1);
    int dq = iclamp(out_deg[b * kN + n], 0, kND - 1);
    const float* e0 = atom_emb + (size_t)a0 * kD;
    const float* e1 = atom_emb + (size_t)a1 * kD;
    const float* e2 = atom_emb + (size_t)a2 * kD;
    const float* ei = in_deg_emb + (size_t)di * kD;
    const float* eo = out_deg_emb + (size_t)dq * kD;
    for (int d = threadIdx.x; d < kD; d += 256)
        out[d] = e0[d] + e1[d] + e2[d] + ei[d] + eo[d];
}

__global__ void bias_kernel(const float* __restrict__ attn_bias,
                            const int* __restrict__ spatial_pos,
                            const int* __restrict__ edge_type,
                            const int* __restrict__ x,
                            const float* __restrict__ spatial_emb,
                            const float* __restrict__ edge_emb,
                            const float* __restrict__ virt_dist,
                            float* __restrict__ gb) {
    int idx = blockIdx.x * 256 + threadIdx.x;
    if (idx >= kS * kS) return;
    int b = blockIdx.y;
    int q = idx / kS, k = idx % kS;

    size_t obase = ((size_t)b * kH) * kS * kS + (size_t)q * kS + k;

    if (k >= 1 && x[(b * kN + (k - 1)) * kNF] == 0) {
#pragma unroll
        for (int hh = 0; hh < kH; hh++)
            gb[obase + (size_t)hh * kS * kS] = -1e30f;
        return;
    }

    float base = attn_bias[(size_t)b * kS * kS + idx];
    float vals[kH];
#pragma unroll
    for (int hh = 0; hh < kH; hh++) vals[hh] = base;

    if (q >= 1 && k >= 1) {
        size_t e = (size_t)b * kN * kN + (size_t)(q - 1) * kN + (k - 1);
        int sp = iclamp(spatial_pos[e], 0, kNS - 1);
        const int* et = edge_type + e * kNEF;
        int t0 = iclamp(et[0], 0, kNE);
        int t1 = iclamp(et[1], 0, kNE);
        int t2 = iclamp(et[2], 0, kNE);
        const float* sr = spatial_emb + (size_t)sp * kH;
        const float* r0 = edge_emb + (size_t)t0 * kH;
        const float* r1 = edge_emb + (size_t)t1 * kH;
        const float* r2 = edge_emb + (size_t)t2 * kH;
#pragma unroll
        for (int hh = 0; hh < kH; hh++)
            vals[hh] += sr[hh] + (r0[hh] + r1[hh] + r2[hh]) * (1.0f / 3.0f);
    }
    if (q == 0 || k == 0) {
#pragma unroll
        for (int hh = 0; hh < kH; hh++) vals[hh] += virt_dist[hh];
    }
#pragma unroll
    for (int hh = 0; hh < kH; hh++)
        gb[obase + (size_t)hh * kS * kS] = vals[hh];
}

__global__ void ln_split_kernel(const float* __restrict__ in,
                                const float* __restrict__ g,
                                const float* __restrict__ bt,
                                uint16_t* __restrict__ hiP,
                                uint16_t* __restrict__ loP) {
    int tok = blockIdx.x;
    int tid = threadIdx.x;
    const float* xr = in + (size_t)tok * kD;
    __shared__ float red[256];
    float x0 = xr[tid], x1 = xr[tid + 256], x2 = xr[tid + 512];
    red[tid] = x0 + x1 + x2;
    __syncthreads();
    for (int off = 128; off; off >>= 1) {
        if (tid < off) red[tid] += red[tid + off];
        __syncthreads();
    }
    float mean = red[0] * (1.0f / kD);
    __syncthreads();
    float d0 = x0 - mean, d1 = x1 - mean, d2 = x2 - mean;
    red[tid] = d0 * d0 + d1 * d1 + d2 * d2;
    __syncthreads();
    for (int off = 128; off; off >>= 1) {
        if (tid < off) red[tid] += red[tid + off];
        __syncthreads();
    }
    float inv = rsqrtf(red[0] * (1.0f / kD) + kEPS);
    float z0 = d0 * inv * g[tid]       + bt[tid];
    float z1 = d1 * inv * g[tid + 256] + bt[tid + 256];
    float z2 = d2 * inv * g[tid + 512] + bt[tid + 512];
    size_t base = (size_t)tok * kD;
    uint2 s;
    s = sp2(z0, z0); hiP[base + tid]       = (uint16_t)(s.x & 0xffff);
                     loP[base + tid]       = (uint16_t)(s.y & 0xffff);
    s = sp2(z1, z1); hiP[base + tid + 256] = (uint16_t)(s.x & 0xffff);
                     loP[base + tid + 256] = (uint16_t)(s.y & 0xffff);
    s = sp2(z2, z2); hiP[base + tid + 512] = (uint16_t)(s.x & 0xffff);
                     loP[base + tid + 512] = (uint16_t)(s.y & 0xffff);
}

__global__ void final_ln_kernel(const float* __restrict__ in,
                                const float* __restrict__ g,
                                const float* __restrict__ bt,
                                float* __restrict__ out) {
    int tok = blockIdx.x;
    int b = tok / kS, s = tok % kS;
    int tid = threadIdx.x;
    const float* xr = in + (size_t)tok * kD;
    __shared__ float red[256];
    float x0 = xr[tid], x1 = xr[tid + 256], x2 = xr[tid + 512];
    red[tid] = x0 + x1 + x2;
    __syncthreads();
    for (int off = 128; off; off >>= 1) {
        if (tid < off) red[tid] += red[tid + off];
        __syncthreads();
    }
    float mean = red[0] * (1.0f / kD);
    __syncthreads();
    float d0 = x0 - mean, d1 = x1 - mean, d2 = x2 - mean;
    red[tid] = d0 * d0 + d1 * d1 + d2 * d2;
    __syncthreads();
    for (int off = 128; off; off >>= 1) {
        if (tid < off) red[tid] += red[tid + off];
        __syncthreads();
    }
    float inv = rsqrtf(red[0] * (1.0f / kD) + kEPS);
    float* orow = (s == 0)
        ? out + (size_t)kB * kN * kD + (size_t)b * kD
        : out + ((size_t)b * kN + (s - 1)) * kD;
    orow[tid]       = d0 * inv * g[tid]       + bt[tid];
    orow[tid + 256] = d1 * inv * g[tid + 256] + bt[tid + 256];
    orow[tid + 512] = d2 * inv * g[tid + 512] + bt[tid + 512];
}

// ---------------------------------------------------------------------------
// Host launcher
// ---------------------------------------------------------------------------
extern "C" void kernel_launch(void* const* d_in, const int* in_sizes, int n_in,
                              void* d_out, int out_size) {
    (void)in_sizes; (void)n_in; (void)out_size;

    const int*   x              = (const int*)  d_in[0];
    const float* attn_bias      = (const float*)d_in[1];
    const int*   spatial_pos    = (const int*)  d_in[2];
    const int*   attn_edge_type = (const int*)  d_in[3];
    const int*   in_degree      = (const int*)  d_in[4];
    const int*   out_degree     = (const int*)  d_in[5];
    const float* atom_emb       = (const float*)d_in[6];
    const float* in_deg_emb     = (const float*)d_in[7];
    const float* out_deg_emb    = (const float*)d_in[8];
    const float* graph_token    = (const float*)d_in[9];
    const float* spatial_emb    = (const float*)d_in[10];
    const float* edge_emb       = (const float*)d_in[11];
    const float* virt_dist      = (const float*)d_in[12];
    const float* Wq             = (const float*)d_in[13];
    const float* Wk             = (const float*)d_in[14];
    const float* Wv             = (const float*)d_in[15];
    const float* Wo             = (const float*)d_in[16];
    const float* bq             = (const float*)d_in[17];
    const float* bk             = (const float*)d_in[18];
    const float* bv             = (const float*)d_in[19];
    const float* bo             = (const float*)d_in[20];
    const float* ln1_g          = (const float*)d_in[21];
    const float* ln1_b          = (const float*)d_in[22];
    const float* ln2_g          = (const float*)d_in[23];
    const float* ln2_b          = (const float*)d_in[24];
    const float* W1             = (const float*)d_in[25];
    const float* b1             = (const float*)d_in[26];
    const float* W2             = (const float*)d_in[27];
    const float* b2             = (const float*)d_in[28];
    const float* fin_g          = (const float*)d_in[29];
    const float* fin_b          = (const float*)d_in[30];
    float* out = (float*)d_out;

    float* base = nullptr;
    cudaGetSymbolAddress((void**)&base, g_scratch);
    uint16_t* cv = nullptr;
    cudaGetSymbolAddress((void**)&cv, g_cv);
    uint16_t* fpl = nullptr;
    cudaGetSymbolAddress((void**)&fpl, g_f);
    float* bqkv = nullptr;
    cudaGetSymbolAddress((void**)&bqkv, g_bqkv);

    float* h   = base + OFF_H;
    float* qkv = base + OFF_QKV;
    float* gb  = base + OFF_GB;

    uint16_t* aHi = cv + CV_A;
    uint16_t* aLo = cv + CV_A + ACT_PLANE;
    uint16_t* fHi = fpl;
    uint16_t* fLo = fpl + ACT_PLANE;

    cudaFuncSetAttribute(gemm_tc, cudaFuncAttributeMaxDynamicSharedMemorySize,
                         GT_SMEM);
    cudaFuncSetAttribute(attn_mma,
                         cudaFuncAttributeMaxDynamicSharedMemorySize, AT2_SMEM);

    // 1: all weight conversions in one launch
    cvt_all<<<4096, 256>>>((const float4*)Wq, (const float4*)Wk,
                           (const float4*)Wv, (const float4*)Wo,
                           (const float4*)W1, (const float4*)W2, cv);
    // 2
    bias_cat<<<(kL * kQKV + 255) / 256, 256>>>(bq, bk, bv, bqkv);
    // 3
    embed_kernel<<<kBS, 256>>>(x, in_degree, out_degree, atom_emb, in_deg_emb,
                               out_deg_emb, graph_token, h);
    // 4
    bias_kernel<<<dim3((kS * kS + 255) / 256, kB), 256>>>(
        attn_bias, spatial_pos, attn_edge_type, x, spatial_emb, edge_emb,
        virt_dist, gb);

    const int mtiles = (kBS + 127) / 128;            // 65
    dim3 gemmD(kD / 128, mtiles);                    // (6, 65)
    dim3 gemmQ(kQKV / 128, mtiles);                  // (18, 65)
    dim3 gemmF(kFF / 128, mtiles);                   // (24, 65)
    dim3 attnG((kS + 63) / 64, kB * kH);             // (5, 384)

    for (int l = 0; l < kL; l++) {
        const size_t odd  = (size_t)l * kD * kD;
        const size_t oqkv = (size_t)l * kQKV * kD;
        const size_t ofd  = (size_t)l * kFF * kD;

        // 5 (first iter): ln_split -> launch 6 = gemm_tc (ncu capture target)
        ln_split_kernel<<<kBS, 256>>>(h, ln1_g + l * kD, ln1_b + l * kD,
                                      aHi, aLo);

        gemm_tc<<<gemmQ, 256, GT_SMEM>>>(aHi, aLo, cv + CV_WQKV + oqkv,
                                         cv + CV_WQKV + W_QKV + oqkv,
                                         bqkv + (size_t)l * kQKV, qkv,
                                         nullptr, nullptr,
                                         kBS, kQKV, kD, EPI_QKV);

        attn_mma<<<attnG, 256, AT2_SMEM>>>(qkv, gb, aHi, aLo);

        gemm_tc<<<gemmD, 256, GT_SMEM>>>(aHi, aLo, cv + CV_WO + odd,
                                         cv + CV_WO + W_DD + odd,
                                         bo + l * kD, h, nullptr, nullptr,
                                         kBS, kD, kD, EPI_RES);

        ln_split_kernel<<<kBS, 256>>>(h, ln2_g + l * kD, ln2_b + l * kD,
                                      aHi, aLo);
        gemm_tc<<<gemmF, 256, GT_SMEM>>>(aHi, aLo, cv + CV_W1 + ofd,
                                         cv + CV_W1 + W_FD + ofd,
                                         b1 + l * kFF, nullptr, fHi, fLo,
                                         kBS, kFF, kD, EPI_GELU);
        gemm_tc<<<gemmD, 256, GT_SMEM>>>(fHi, fLo, cv + CV_W2 + ofd,
                                         cv + CV_W2 + W_FD + ofd,
                                         b2 + l * kD, h, nullptr, nullptr,
                                         kBS, kD, kFF, EPI_RES);
    }

    final_ln_kernel<<<kBS, 256>>>(h, fin_g, fin_b, out);
}